// round 9
// baseline (speedup 1.0000x reference)
#include <cuda_runtime.h>
#include <cuda_fp16.h>
#include <math.h>
#include <stdint.h>

#define BSZ   2
#define SEQ   2048
#define EMB   4096
#define NH    32
#define NKVH  8
#define HD    128
#define GROUPS (NH / NKVH)
#define MROWS (BSZ * SEQ)          // 4096
#define QDIM  (NH * HD)            // 4096
#define KVDIM (NKVH * HD)          // 1024

// log2(e)/sqrt(128), folded into Q so softmax uses bare exp2
#define QSCALE 0.12751744f

// Scratch (device globals)
__device__ __half g_Qa [(size_t)MROWS * EMB];    // half activations
__device__ __half g_Ka [(size_t)MROWS * EMB];
__device__ __half g_Va [(size_t)MROWS * EMB];
__device__ __half g_Qh [(size_t)MROWS * QDIM];   // post-rope half
__device__ __half g_Kh [(size_t)MROWS * KVDIM];
__device__ __half g_Vh [(size_t)MROWS * KVDIM];
__device__ __half g_AOh[(size_t)MROWS * QDIM];
__device__ __half g_Wqh[(size_t)EMB * QDIM];     // [K][N] half (no transpose)
__device__ __half g_Wkh[(size_t)EMB * KVDIM];
__device__ __half g_Wvh[(size_t)EMB * KVDIM];
__device__ __half g_Woh[(size_t)QDIM * EMB];

// ---------------------------------------------------------------------------
// Helpers
// ---------------------------------------------------------------------------
__device__ __forceinline__ uint32_t smem_u32(const void* p) {
    uint32_t a;
    asm("{ .reg .u64 t; cvta.to.shared.u64 t, %1; cvt.u32.u64 %0, t; }" : "=r"(a) : "l"(p));
    return a;
}
__device__ __forceinline__ void cpasync16(uint32_t dst, const void* src) {
    asm volatile("cp.async.cg.shared.global [%0], [%1], 16;" :: "r"(dst), "l"(src) : "memory");
}
#define CP_COMMIT() asm volatile("cp.async.commit_group;" ::: "memory")
#define CP_WAIT(n)  asm volatile("cp.async.wait_group %0;" :: "n"(n) : "memory")

__device__ __forceinline__ void mma_f16(float* d, const uint32_t* a, uint32_t b0, uint32_t b1) {
    asm volatile("mma.sync.aligned.m16n8k16.row.col.f32.f16.f16.f32 "
        "{%0,%1,%2,%3}, {%4,%5,%6,%7}, {%8,%9}, {%0,%1,%2,%3};"
        : "+f"(d[0]), "+f"(d[1]), "+f"(d[2]), "+f"(d[3])
        : "r"(a[0]), "r"(a[1]), "r"(a[2]), "r"(a[3]), "r"(b0), "r"(b1));
}
__device__ __forceinline__ void ldsm4(uint32_t& r0, uint32_t& r1, uint32_t& r2, uint32_t& r3,
                                      uint32_t addr) {
    asm volatile("ldmatrix.sync.aligned.m8n8.x4.shared.b16 {%0,%1,%2,%3}, [%4];"
        : "=r"(r0), "=r"(r1), "=r"(r2), "=r"(r3) : "r"(addr));
}
__device__ __forceinline__ void ldsm4t(uint32_t& r0, uint32_t& r1, uint32_t& r2, uint32_t& r3,
                                       uint32_t addr) {
    asm volatile("ldmatrix.sync.aligned.m8n8.x4.trans.shared.b16 {%0,%1,%2,%3}, [%4];"
        : "=r"(r0), "=r"(r1), "=r"(r2), "=r"(r3) : "r"(addr));
}

// ---------------------------------------------------------------------------
// One-shot fp32->half conversion of all 7 tensors. 1024 elems per block.
// ---------------------------------------------------------------------------
struct ConvDesc {
    const float* src[7];
    __half*      dst[7];
    int          nblk[7];
};

__global__ void conv_all(ConvDesc cd)
{
    int b = blockIdx.x;
    int seg = 0;
#pragma unroll
    for (int i = 0; i < 7; i++) {
        if (b >= cd.nblk[i]) { b -= cd.nblk[i]; seg = i + 1; }
        else break;
    }
    const float* src = cd.src[seg];
    __half* dst = cd.dst[seg];
    size_t i = ((size_t)b * 256 + threadIdx.x) * 4;
    float4 v = *(const float4*)(src + i);
    *(__half2*)(dst + i)     = __floats2half2_rn(v.x, v.y);
    *(__half2*)(dst + i + 2) = __floats2half2_rn(v.z, v.w);
}

// ---------------------------------------------------------------------------
// Grouped fp16 tensor-core GEMM: per segment C[M,N] = A[M,K] @ B[K,N]
// CTA tile 128x128, BK=64, 8 warps (64x32 warp tile), cp.async 3-stage,
// 2 CTAs/SM, single barrier per k-iter, ks+1 fragment double buffering.
// mode: 0 = fp32 out, 1 = half out, 2 = rope(+scale) half out.
// ---------------------------------------------------------------------------
#define HP  72                    // A row pitch (halves)
#define BPN 136                   // B row pitch (halves)
#define SPN 132                   // fp32 staging pitch (floats), mode 2
#define A_ST (128 * HP)           // halves
#define B_ST (64 * BPN)           // halves
#define STG_B ((A_ST + B_ST) * 2)            // 35840 bytes
#define GN_SMEM (3 * STG_B)                  // 107520 bytes

struct GroupArgs {
    const __half* A[3];
    const __half* B[3];
    void*         C[3];
    int           N[3];
    int           mode[3];
    float         rsc[3];
    int           xend[3];   // exclusive prefix ends in blockIdx.x
    int           nseg;
};

__global__ __launch_bounds__(256, 2) void gemm_grp(GroupArgs ga, int K)
{
    extern __shared__ __half smh[];
    const uint32_t sb = smem_u32(smh);

    // segment select (uniform per CTA)
    int bx = blockIdx.x;
    int seg = 0;
#pragma unroll
    for (int i = 0; i < 2; i++)
        if (i + 1 < ga.nseg && bx >= ga.xend[i]) seg = i + 1;
    const int xbase = (seg == 0) ? 0 : ga.xend[seg - 1];
    const __half* A = ga.A[seg];
    const __half* B = ga.B[seg];
    void* Cv        = ga.C[seg];
    const int N     = ga.N[seg];
    const int mode  = ga.mode[seg];
    const float rsc = ga.rsc[seg];

    const int tid  = threadIdx.x;
    const int wid  = tid >> 5, lane = tid & 31;
    const int g    = lane >> 2, tig = lane & 3;
    const int wm   = (wid >> 2) * 64;        // 0,64
    const int wn   = (wid & 3) * 32;         // 0..96
    const int bm   = blockIdx.y * 128, bn = (bx - xbase) * 128;

    auto load_tile = [&](int c, int s) {
        const __half* Ab = A + (size_t)bm * K + c * 64;
        const __half* Bb = B + (size_t)(c * 64) * N + bn;
        uint32_t sa  = sb + (uint32_t)s * STG_B;
        uint32_t sbb = sa + A_ST * 2;
#pragma unroll
        for (int l = 0; l < 4; l++) {
            int id = l * 256 + tid;
            int ra = id >> 3, ca = (id & 7) * 8;         // A: 128 x 64
            cpasync16(sa + (uint32_t)(ra * HP + ca) * 2, Ab + (size_t)ra * K + ca);
            int rb = id >> 4, cb = (id & 15) * 8;        // B: 64 x 128
            cpasync16(sbb + (uint32_t)(rb * BPN + cb) * 2, Bb + (size_t)rb * N + cb);
        }
        CP_COMMIT();
    };

    const int l7  = lane & 7;
    const int lb3 = (lane >> 3) & 1;
    const int lb4 = lane >> 4;

    float acc[4][4][4];
#pragma unroll
    for (int mi = 0; mi < 4; mi++)
#pragma unroll
        for (int ni = 0; ni < 4; ni++)
#pragma unroll
            for (int r = 0; r < 4; r++) acc[mi][ni][r] = 0.0f;

    const int iters = K / 64;
    load_tile(0, 0);
    load_tile(1, 1);

    uint32_t sA = 0, sBb = 0;
    uint32_t af[2][4][4], bf[2][2][4];

    auto load_frag = [&](int ks, int pb) {
        const int kb = ks * 16;
#pragma unroll
        for (int mi = 0; mi < 4; mi++) {
            uint32_t addr = sA + (uint32_t)((wm + mi * 16 + l7 + lb3 * 8) * HP
                                            + kb + lb4 * 8) * 2;
            ldsm4(af[pb][mi][0], af[pb][mi][1], af[pb][mi][2], af[pb][mi][3], addr);
        }
#pragma unroll
        for (int nj = 0; nj < 2; nj++) {
            uint32_t addr = sBb + (uint32_t)((kb + l7 + lb3 * 8) * BPN
                                             + wn + nj * 16 + lb4 * 8) * 2;
            ldsm4t(bf[pb][nj][0], bf[pb][nj][1], bf[pb][nj][2], bf[pb][nj][3], addr);
        }
    };

    for (int c = 0; c < iters; c++) {
        const int s = c % 3;
        if (c + 1 < iters) { CP_WAIT(1); } else { CP_WAIT(0); }
        __syncthreads();
        if (c + 2 < iters) load_tile(c + 2, (c + 2) % 3);

        sA  = sb + (uint32_t)s * STG_B;
        sBb = sA + A_ST * 2;

        load_frag(0, 0);
#pragma unroll
        for (int ks = 0; ks < 4; ks++) {
            const int cur = ks & 1;
            if (ks < 3) load_frag(ks + 1, cur ^ 1);
#pragma unroll
            for (int mi = 0; mi < 4; mi++)
#pragma unroll
                for (int nj = 0; nj < 2; nj++) {
                    mma_f16(acc[mi][nj * 2],     af[cur][mi], bf[cur][nj][0], bf[cur][nj][1]);
                    mma_f16(acc[mi][nj * 2 + 1], af[cur][mi], bf[cur][nj][2], bf[cur][nj][3]);
                }
        }
    }

    if (mode == 2) {
        // stage fp32 tile in smem, apply RoPE (+scale), write half
        __syncthreads();
        float* S = (float*)smh;
#pragma unroll
        for (int mi = 0; mi < 4; mi++) {
            int r0 = wm + mi * 16 + g;
#pragma unroll
            for (int ni = 0; ni < 4; ni++) {
                int cc = wn + ni * 8 + tig * 2;
                *(float2*)(S + (size_t)r0 * SPN + cc)       = make_float2(acc[mi][ni][0], acc[mi][ni][1]);
                *(float2*)(S + (size_t)(r0 + 8) * SPN + cc) = make_float2(acc[mi][ni][2], acc[mi][ni][3]);
            }
        }
        __syncthreads();
        // tile is 128 wide = exactly one head (bn head-aligned)
        __half* C = (__half*)Cv;
        const float LG = 0.2076205059304640f;   // 2*log2(10000)/128
#pragma unroll 4
        for (int l = 0; l < 32; l++) {
            int idx = l * 256 + tid;             // 8192 rotation pairs
            int r  = idx >> 6;
            int d  = idx & 63;
            float x1 = S[(size_t)r * SPN + d];
            float x2 = S[(size_t)r * SPN + d + 64];
            int grow = bm + r;
            float pos = (float)(grow & (SEQ - 1));
            float invf = exp2f(-LG * (float)d);
            float ang = pos * invf;
            float sn, cs;
            sincosf(ang, &sn, &cs);
            size_t o = (size_t)grow * N + bn + d;
            C[o]      = __float2half((x1 * cs - x2 * sn) * rsc);
            C[o + 64] = __float2half((x2 * cs + x1 * sn) * rsc);
        }
    } else if (mode == 1) {
        __half* C = (__half*)Cv;
#pragma unroll
        for (int mi = 0; mi < 4; mi++) {
            int row0 = bm + wm + mi * 16 + g;
#pragma unroll
            for (int ni = 0; ni < 4; ni++) {
                int col = bn + wn + ni * 8 + tig * 2;
                *(__half2*)(C + (size_t)row0 * N + col) =
                    __floats2half2_rn(acc[mi][ni][0], acc[mi][ni][1]);
                *(__half2*)(C + (size_t)(row0 + 8) * N + col) =
                    __floats2half2_rn(acc[mi][ni][2], acc[mi][ni][3]);
            }
        }
    } else {
        float* C = (float*)Cv;
#pragma unroll
        for (int mi = 0; mi < 4; mi++) {
            int row0 = bm + wm + mi * 16 + g;
#pragma unroll
            for (int ni = 0; ni < 4; ni++) {
                int col = bn + wn + ni * 8 + tig * 2;
                *(float2*)(C + (size_t)row0 * N + col)       = make_float2(acc[mi][ni][0], acc[mi][ni][1]);
                *(float2*)(C + (size_t)(row0 + 8) * N + col) = make_float2(acc[mi][ni][2], acc[mi][ni][3]);
            }
        }
    }
}

// ---------------------------------------------------------------------------
// Flash attention v4: fp16 MMA, ldmatrix, 3-stage K/V pipeline,
// one barrier per kv-iteration. Q tile 128, K tile 64, 8 warps.
// ---------------------------------------------------------------------------
#define QP 136
#define VP 72
#define KVST (2 * 64 * QP)
#define FL4_SMEM ((128*QP + 3*KVST + 128*VP) * 2)   // 157696 bytes

__global__ __launch_bounds__(256, 1) void flash4(const __half* __restrict__ Q,
                                                 const __half* __restrict__ K,
                                                 const __half* __restrict__ V,
                                                 __half* __restrict__ O)
{
    extern __shared__ __half hs[];
    __half* Qs  = hs;
    __half* KV0 = Qs + 128 * QP;
    __half* Ps  = KV0 + 3 * KVST;

    const uint32_t sbQ  = smem_u32(Qs);
    const uint32_t sbKV = smem_u32(KV0);
    const uint32_t sbP  = smem_u32(Ps);
    __half2* P2 = (__half2*)Ps;

    const int qi  = (int)gridDim.x - 1 - (int)blockIdx.x;
    const int h   = blockIdx.y;
    const int b   = blockIdx.z;
    const int kvh = h / GROUPS;
    const int tid = threadIdx.x;
    const int wid = tid >> 5, lane = tid & 31;
    const int g   = lane >> 2, tig = lane & 3;
    const int wq  = wid * 16;
    const int l7  = lane & 7;
    const int lb3 = (lane >> 3) & 1;
    const int lb4 = lane >> 4;

    const __half* Qg = Q + (size_t)(b * SEQ + qi * 128) * QDIM + h * HD;
    const __half* Kg = K + (size_t)(b * SEQ) * KVDIM + kvh * HD;
    const __half* Vg = V + (size_t)(b * SEQ) * KVDIM + kvh * HD;

    auto load_kv = [&](int kb, int s) {
        const __half* Kt = Kg + (size_t)(kb * 64) * KVDIM;
        const __half* Vt = Vg + (size_t)(kb * 64) * KVDIM;
        uint32_t ks_ = sbKV + (uint32_t)s * (KVST * 2);
        uint32_t vs_ = ks_ + 64 * QP * 2;
#pragma unroll
        for (int l = 0; l < 4; l++) {
            int id = l * 256 + tid;
            int r = id >> 4, c8 = (id & 15) * 8;
            cpasync16(ks_ + (uint32_t)(r * QP + c8) * 2, Kt + (size_t)r * KVDIM + c8);
            cpasync16(vs_ + (uint32_t)(r * QP + c8) * 2, Vt + (size_t)r * KVDIM + c8);
        }
        CP_COMMIT();
    };

#pragma unroll
    for (int l = 0; l < 8; l++) {
        int id = l * 256 + tid;
        int r = id >> 4, c8 = (id & 15) * 8;
        *(uint4*)(Qs + r * QP + c8) = *(const uint4*)(Qg + (size_t)r * QDIM + c8);
    }

    float m0 = -INFINITY, m1 = -INFINITY, l0 = 0.f, l1 = 0.f;
    float oa[16][4];
#pragma unroll
    for (int ni = 0; ni < 16; ni++)
#pragma unroll
        for (int r = 0; r < 4; r++) oa[ni][r] = 0.f;

    const int kmax = 2 * qi + 2;
    load_kv(0, 0);
    load_kv(1, 1);

    for (int kb = 0; kb < kmax; kb++) {
        const int s = kb % 3;
        if (kb + 1 < kmax) { CP_WAIT(1); } else { CP_WAIT(0); }
        __syncthreads();
        if (kb + 2 < kmax) load_kv(kb + 2, (kb + 2) % 3);

        const uint32_t sK = sbKV + (uint32_t)s * (KVST * 2);
        const uint32_t sV = sK + 64 * QP * 2;

        float sa[8][4];
#pragma unroll
        for (int ni = 0; ni < 8; ni++)
#pragma unroll
            for (int r = 0; r < 4; r++) sa[ni][r] = 0.f;

#pragma unroll
        for (int ks = 0; ks < 8; ks++) {
            const int kc = ks * 16;
            uint32_t a[4], bfr[8][2];
            {
                uint32_t addr = sbQ + (uint32_t)((wq + l7 + lb3 * 8) * QP + kc + lb4 * 8) * 2;
                ldsm4(a[0], a[1], a[2], a[3], addr);
            }
#pragma unroll
            for (int nip = 0; nip < 4; nip++) {
                uint32_t addr = sK + (uint32_t)((nip * 16 + l7 + lb4 * 8) * QP + kc + lb3 * 8) * 2;
                ldsm4(bfr[nip*2][0], bfr[nip*2][1], bfr[nip*2+1][0], bfr[nip*2+1][1], addr);
            }
#pragma unroll
            for (int ni = 0; ni < 8; ni++)
                mma_f16(sa[ni], a, bfr[ni][0], bfr[ni][1]);
        }

        if (kb >= 2 * qi) {
            int r0 = qi * 128 + wq + g;
#pragma unroll
            for (int ni = 0; ni < 8; ni++) {
                int c0 = kb * 64 + ni * 8 + 2 * tig;
                if (c0 > r0)         sa[ni][0] = -INFINITY;
                if (c0 + 1 > r0)     sa[ni][1] = -INFINITY;
                if (c0 > r0 + 8)     sa[ni][2] = -INFINITY;
                if (c0 + 1 > r0 + 8) sa[ni][3] = -INFINITY;
            }
        }

        float mx0 = -INFINITY, mx1 = -INFINITY;
#pragma unroll
        for (int ni = 0; ni < 8; ni++) {
            mx0 = fmaxf(mx0, fmaxf(sa[ni][0], sa[ni][1]));
            mx1 = fmaxf(mx1, fmaxf(sa[ni][2], sa[ni][3]));
        }
        mx0 = fmaxf(mx0, __shfl_xor_sync(0xffffffffu, mx0, 1));
        mx0 = fmaxf(mx0, __shfl_xor_sync(0xffffffffu, mx0, 2));
        mx1 = fmaxf(mx1, __shfl_xor_sync(0xffffffffu, mx1, 1));
        mx1 = fmaxf(mx1, __shfl_xor_sync(0xffffffffu, mx1, 2));

        float mm0 = fmaxf(m0, mx0), mm1 = fmaxf(m1, mx1);
        float sub0 = (mm0 == -INFINITY) ? 0.f : mm0;
        float sub1 = (mm1 == -INFINITY) ? 0.f : mm1;
        float al0 = exp2f(m0 - sub0);
        float al1 = exp2f(m1 - sub1);
        m0 = mm0; m1 = mm1;

        float ls0 = 0.f, ls1 = 0.f;
#pragma unroll
        for (int ni = 0; ni < 8; ni++) {
            float p0 = exp2f(sa[ni][0] - sub0);
            float p1 = exp2f(sa[ni][1] - sub0);
            float p2 = exp2f(sa[ni][2] - sub1);
            float p3 = exp2f(sa[ni][3] - sub1);
            ls0 += p0 + p1; ls1 += p2 + p3;
            P2[(wq + g) * (VP/2) + ni * 4 + tig]     = __floats2half2_rn(p0, p1);
            P2[(wq + g + 8) * (VP/2) + ni * 4 + tig] = __floats2half2_rn(p2, p3);
        }
        ls0 += __shfl_xor_sync(0xffffffffu, ls0, 1);
        ls0 += __shfl_xor_sync(0xffffffffu, ls0, 2);
        ls1 += __shfl_xor_sync(0xffffffffu, ls1, 1);
        ls1 += __shfl_xor_sync(0xffffffffu, ls1, 2);
        l0 = l0 * al0 + ls0;
        l1 = l1 * al1 + ls1;

#pragma unroll
        for (int ni = 0; ni < 16; ni++) {
            oa[ni][0] *= al0; oa[ni][1] *= al0;
            oa[ni][2] *= al1; oa[ni][3] *= al1;
        }
        __syncwarp();

#pragma unroll
        for (int ks = 0; ks < 4; ks++) {
            const int kc = ks * 16;
            uint32_t a[4];
            {
                uint32_t addr = sbP + (uint32_t)((wq + l7 + lb3 * 8) * VP + kc + lb4 * 8) * 2;
                ldsm4(a[0], a[1], a[2], a[3], addr);
            }
#pragma unroll
            for (int nip = 0; nip < 8; nip++) {
                uint32_t bf0, bf1, bf2, bf3;
                uint32_t addr = sV + (uint32_t)((kc + l7 + lb3 * 8) * QP + nip * 16 + lb4 * 8) * 2;
                ldsm4t(bf0, bf1, bf2, bf3, addr);
                mma_f16(oa[nip*2],     a, bf0, bf1);
                mma_f16(oa[nip*2 + 1], a, bf2, bf3);
            }
        }
    }

    float inv0 = 1.0f / l0, inv1 = 1.0f / l1;
    __half* Og = O + (size_t)(b * SEQ + qi * 128 + wq) * QDIM + h * HD;
#pragma unroll
    for (int ni = 0; ni < 16; ni++) {
        int col = ni * 8 + 2 * tig;
        *(__half2*)(Og + (size_t)g * QDIM + col) =
            __floats2half2_rn(oa[ni][0] * inv0, oa[ni][1] * inv0);
        *(__half2*)(Og + (size_t)(g + 8) * QDIM + col) =
            __floats2half2_rn(oa[ni][2] * inv1, oa[ni][3] * inv1);
    }
}

// ---------------------------------------------------------------------------
// Launch: conv_all -> grouped QKV gemm -> flash -> O gemm
// ---------------------------------------------------------------------------
extern "C" void kernel_launch(void* const* d_in, const int* in_sizes, int n_in,
                              void* d_out, int out_size)
{
    const float* query = (const float*)d_in[0];
    const float* key   = (const float*)d_in[1];
    const float* value = (const float*)d_in[2];
    const float* Wq = (const float*)d_in[5];
    const float* Wk = (const float*)d_in[6];
    const float* Wv = (const float*)d_in[7];
    const float* Wo = (const float*)d_in[8];
    float* out = (float*)d_out;

    __half *pQa, *pKa, *pVa, *pQh, *pKh, *pVh, *pAOh, *pWqh, *pWkh, *pWvh, *pWoh;
    cudaGetSymbolAddress((void**)&pQa,  g_Qa);
    cudaGetSymbolAddress((void**)&pKa,  g_Ka);
    cudaGetSymbolAddress((void**)&pVa,  g_Va);
    cudaGetSymbolAddress((void**)&pQh,  g_Qh);
    cudaGetSymbolAddress((void**)&pKh,  g_Kh);
    cudaGetSymbolAddress((void**)&pVh,  g_Vh);
    cudaGetSymbolAddress((void**)&pAOh, g_AOh);
    cudaGetSymbolAddress((void**)&pWqh, g_Wqh);
    cudaGetSymbolAddress((void**)&pWkh, g_Wkh);
    cudaGetSymbolAddress((void**)&pWvh, g_Wvh);
    cudaGetSymbolAddress((void**)&pWoh, g_Woh);

    cudaFuncSetAttribute(gemm_grp, cudaFuncAttributeMaxDynamicSharedMemorySize, GN_SMEM);
    cudaFuncSetAttribute(flash4,   cudaFuncAttributeMaxDynamicSharedMemorySize, FL4_SMEM);

    // one-shot conversion of everything to half
    ConvDesc cd;
    cd.src[0] = query; cd.dst[0] = pQa;  cd.nblk[0] = (MROWS * EMB) / 1024;
    cd.src[1] = key;   cd.dst[1] = pKa;  cd.nblk[1] = (MROWS * EMB) / 1024;
    cd.src[2] = value; cd.dst[2] = pVa;  cd.nblk[2] = (MROWS * EMB) / 1024;
    cd.src[3] = Wq;    cd.dst[3] = pWqh; cd.nblk[3] = (EMB * QDIM) / 1024;
    cd.src[4] = Wk;    cd.dst[4] = pWkh; cd.nblk[4] = (EMB * KVDIM) / 1024;
    cd.src[5] = Wv;    cd.dst[5] = pWvh; cd.nblk[5] = (EMB * KVDIM) / 1024;
    cd.src[6] = Wo;    cd.dst[6] = pWoh; cd.nblk[6] = (QDIM * EMB) / 1024;
    int total_blk = cd.nblk[0] + cd.nblk[1] + cd.nblk[2] + cd.nblk[3]
                  + cd.nblk[4] + cd.nblk[5] + cd.nblk[6];
    conv_all<<<total_blk, 256>>>(cd);

    // grouped Q+K+V projections (one launch; rope fused for Q,K)
    GroupArgs gq;
    gq.A[0] = pQa; gq.B[0] = pWqh; gq.C[0] = pQh; gq.N[0] = QDIM;  gq.mode[0] = 2; gq.rsc[0] = QSCALE; gq.xend[0] = 32;
    gq.A[1] = pKa; gq.B[1] = pWkh; gq.C[1] = pKh; gq.N[1] = KVDIM; gq.mode[1] = 2; gq.rsc[1] = 1.0f;   gq.xend[1] = 40;
    gq.A[2] = pVa; gq.B[2] = pWvh; gq.C[2] = pVh; gq.N[2] = KVDIM; gq.mode[2] = 1; gq.rsc[2] = 0.0f;   gq.xend[2] = 48;
    gq.nseg = 3;
    gemm_grp<<<dim3(48, MROWS / 128), 256, GN_SMEM>>>(gq, EMB);

    // attention
    flash4<<<dim3(SEQ / 128, NH, BSZ), 256, FL4_SMEM>>>(pQh, pKh, pVh, pAOh);

    // output projection
    GroupArgs go;
    go.A[0] = pAOh; go.B[0] = pWoh; go.C[0] = out; go.N[0] = EMB; go.mode[0] = 0; go.rsc[0] = 0.0f; go.xend[0] = 32;
    go.nseg = 1;
    gemm_grp<<<dim3(32, MROWS / 128), 256, GN_SMEM>>>(go, QDIM);
}

// round 10
// speedup vs baseline: 1.0258x; 1.0258x over previous
#include <cuda_runtime.h>
#include <cuda_fp16.h>
#include <math.h>
#include <stdint.h>

#define BSZ   2
#define SEQ   2048
#define EMB   4096
#define NH    32
#define NKVH  8
#define HD    128
#define GROUPS (NH / NKVH)
#define MROWS (BSZ * SEQ)          // 4096
#define QDIM  (NH * HD)            // 4096
#define KVDIM (NKVH * HD)          // 1024

// log2(e)/sqrt(128), folded into Q so softmax uses bare exp2
#define QSCALE 0.12751744f

// Scratch (device globals)
__device__ __half g_Qa [(size_t)MROWS * EMB];    // half activations
__device__ __half g_Ka [(size_t)MROWS * EMB];
__device__ __half g_Va [(size_t)MROWS * EMB];
__device__ __half g_Qh [(size_t)MROWS * QDIM];   // post-rope half
__device__ __half g_Kh [(size_t)MROWS * KVDIM];
__device__ __half g_Vh [(size_t)MROWS * KVDIM];
__device__ __half g_AOh[(size_t)MROWS * QDIM];
__device__ __half g_Wqh[(size_t)EMB * QDIM];     // [K][N] half (no transpose)
__device__ __half g_Wkh[(size_t)EMB * KVDIM];
__device__ __half g_Wvh[(size_t)EMB * KVDIM];
__device__ __half g_Woh[(size_t)QDIM * EMB];

// ---------------------------------------------------------------------------
// Helpers
// ---------------------------------------------------------------------------
__device__ __forceinline__ uint32_t smem_u32(const void* p) {
    uint32_t a;
    asm("{ .reg .u64 t; cvta.to.shared.u64 t, %1; cvt.u32.u64 %0, t; }" : "=r"(a) : "l"(p));
    return a;
}
__device__ __forceinline__ void cpasync16(uint32_t dst, const void* src) {
    asm volatile("cp.async.cg.shared.global [%0], [%1], 16;" :: "r"(dst), "l"(src) : "memory");
}
#define CP_COMMIT() asm volatile("cp.async.commit_group;" ::: "memory")
#define CP_WAIT(n)  asm volatile("cp.async.wait_group %0;" :: "n"(n) : "memory")

__device__ __forceinline__ void mma_f16(float* d, const uint32_t* a, uint32_t b0, uint32_t b1) {
    asm volatile("mma.sync.aligned.m16n8k16.row.col.f32.f16.f16.f32 "
        "{%0,%1,%2,%3}, {%4,%5,%6,%7}, {%8,%9}, {%0,%1,%2,%3};"
        : "+f"(d[0]), "+f"(d[1]), "+f"(d[2]), "+f"(d[3])
        : "r"(a[0]), "r"(a[1]), "r"(a[2]), "r"(a[3]), "r"(b0), "r"(b1));
}
__device__ __forceinline__ void ldsm4(uint32_t& r0, uint32_t& r1, uint32_t& r2, uint32_t& r3,
                                      uint32_t addr) {
    asm volatile("ldmatrix.sync.aligned.m8n8.x4.shared.b16 {%0,%1,%2,%3}, [%4];"
        : "=r"(r0), "=r"(r1), "=r"(r2), "=r"(r3) : "r"(addr));
}
__device__ __forceinline__ void ldsm4t(uint32_t& r0, uint32_t& r1, uint32_t& r2, uint32_t& r3,
                                       uint32_t addr) {
    asm volatile("ldmatrix.sync.aligned.m8n8.x4.trans.shared.b16 {%0,%1,%2,%3}, [%4];"
        : "=r"(r0), "=r"(r1), "=r"(r2), "=r"(r3) : "r"(addr));
}

// ---------------------------------------------------------------------------
// One-shot fp32->half conversion of all 7 tensors. 1024 elems per block.
// ---------------------------------------------------------------------------
struct ConvDesc {
    const float* src[7];
    __half*      dst[7];
    int          nblk[7];
};

__global__ void conv_all(ConvDesc cd)
{
    int b = blockIdx.x;
    int seg = 0;
#pragma unroll
    for (int i = 0; i < 7; i++) {
        if (b >= cd.nblk[i]) { b -= cd.nblk[i]; seg = i + 1; }
        else break;
    }
    const float* src = cd.src[seg];
    __half* dst = cd.dst[seg];
    size_t i = ((size_t)b * 256 + threadIdx.x) * 4;
    float4 v = *(const float4*)(src + i);
    *(__half2*)(dst + i)     = __floats2half2_rn(v.x, v.y);
    *(__half2*)(dst + i + 2) = __floats2half2_rn(v.z, v.w);
}

// ---------------------------------------------------------------------------
// Grouped fp16 tensor-core GEMM: per segment C[M,N] = A[M,K] @ B[K,N]
// CTA tile 128x128, BK=64, 8 warps (64x32 warp tile), cp.async 3-stage,
// 2 CTAs/SM, single barrier per k-iter, ks+1 fragment double buffering.
// mode: 0 = fp32 out, 1 = half out, 2 = rope(+scale) half out.
// ---------------------------------------------------------------------------
#define HP  72                    // A row pitch (halves)
#define BPN 136                   // B row pitch (halves)
#define SPN 132                   // fp32 staging pitch (floats), mode 2
#define A_ST (128 * HP)           // halves
#define B_ST (64 * BPN)           // halves
#define STG_B ((A_ST + B_ST) * 2)            // 35840 bytes
#define GN_SMEM (3 * STG_B)                  // 107520 bytes

struct GroupArgs {
    const __half* A[3];
    const __half* B[3];
    void*         C[3];
    int           N[3];
    int           mode[3];
    float         rsc[3];
    int           xend[3];   // exclusive prefix ends in blockIdx.x
    int           nseg;
};

__global__ __launch_bounds__(256, 2) void gemm_grp(GroupArgs ga, int K)
{
    extern __shared__ __half smh[];
    const uint32_t sb = smem_u32(smh);

    // segment select (uniform per CTA)
    int bx = blockIdx.x;
    int seg = 0;
#pragma unroll
    for (int i = 0; i < 2; i++)
        if (i + 1 < ga.nseg && bx >= ga.xend[i]) seg = i + 1;
    const int xbase = (seg == 0) ? 0 : ga.xend[seg - 1];
    const __half* A = ga.A[seg];
    const __half* B = ga.B[seg];
    void* Cv        = ga.C[seg];
    const int N     = ga.N[seg];
    const int mode  = ga.mode[seg];
    const float rsc = ga.rsc[seg];

    const int tid  = threadIdx.x;
    const int wid  = tid >> 5, lane = tid & 31;
    const int g    = lane >> 2, tig = lane & 3;
    const int wm   = (wid >> 2) * 64;        // 0,64
    const int wn   = (wid & 3) * 32;         // 0..96
    const int bm   = blockIdx.y * 128, bn = (bx - xbase) * 128;

    auto load_tile = [&](int c, int s) {
        const __half* Ab = A + (size_t)bm * K + c * 64;
        const __half* Bb = B + (size_t)(c * 64) * N + bn;
        uint32_t sa  = sb + (uint32_t)s * STG_B;
        uint32_t sbb = sa + A_ST * 2;
#pragma unroll
        for (int l = 0; l < 4; l++) {
            int id = l * 256 + tid;
            int ra = id >> 3, ca = (id & 7) * 8;         // A: 128 x 64
            cpasync16(sa + (uint32_t)(ra * HP + ca) * 2, Ab + (size_t)ra * K + ca);
            int rb = id >> 4, cb = (id & 15) * 8;        // B: 64 x 128
            cpasync16(sbb + (uint32_t)(rb * BPN + cb) * 2, Bb + (size_t)rb * N + cb);
        }
        CP_COMMIT();
    };

    const int l7  = lane & 7;
    const int lb3 = (lane >> 3) & 1;
    const int lb4 = lane >> 4;

    float acc[4][4][4];
#pragma unroll
    for (int mi = 0; mi < 4; mi++)
#pragma unroll
        for (int ni = 0; ni < 4; ni++)
#pragma unroll
            for (int r = 0; r < 4; r++) acc[mi][ni][r] = 0.0f;

    const int iters = K / 64;
    load_tile(0, 0);
    load_tile(1, 1);

    uint32_t sA = 0, sBb = 0;
    uint32_t af[2][4][4], bf[2][2][4];

    auto load_frag = [&](int ks, int pb) {
        const int kb = ks * 16;
#pragma unroll
        for (int mi = 0; mi < 4; mi++) {
            uint32_t addr = sA + (uint32_t)((wm + mi * 16 + l7 + lb3 * 8) * HP
                                            + kb + lb4 * 8) * 2;
            ldsm4(af[pb][mi][0], af[pb][mi][1], af[pb][mi][2], af[pb][mi][3], addr);
        }
#pragma unroll
        for (int nj = 0; nj < 2; nj++) {
            uint32_t addr = sBb + (uint32_t)((kb + l7 + lb3 * 8) * BPN
                                             + wn + nj * 16 + lb4 * 8) * 2;
            ldsm4t(bf[pb][nj][0], bf[pb][nj][1], bf[pb][nj][2], bf[pb][nj][3], addr);
        }
    };

    for (int c = 0; c < iters; c++) {
        const int s = c % 3;
        if (c + 1 < iters) { CP_WAIT(1); } else { CP_WAIT(0); }
        __syncthreads();
        if (c + 2 < iters) load_tile(c + 2, (c + 2) % 3);

        sA  = sb + (uint32_t)s * STG_B;
        sBb = sA + A_ST * 2;

        load_frag(0, 0);
#pragma unroll
        for (int ks = 0; ks < 4; ks++) {
            const int cur = ks & 1;
            if (ks < 3) load_frag(ks + 1, cur ^ 1);
#pragma unroll
            for (int mi = 0; mi < 4; mi++)
#pragma unroll
                for (int nj = 0; nj < 2; nj++) {
                    mma_f16(acc[mi][nj * 2],     af[cur][mi], bf[cur][nj][0], bf[cur][nj][1]);
                    mma_f16(acc[mi][nj * 2 + 1], af[cur][mi], bf[cur][nj][2], bf[cur][nj][3]);
                }
        }
    }

    if (mode == 2) {
        // stage fp32 tile in smem, apply RoPE (+scale), write half
        __syncthreads();
        float* S = (float*)smh;
#pragma unroll
        for (int mi = 0; mi < 4; mi++) {
            int r0 = wm + mi * 16 + g;
#pragma unroll
            for (int ni = 0; ni < 4; ni++) {
                int cc = wn + ni * 8 + tig * 2;
                *(float2*)(S + (size_t)r0 * SPN + cc)       = make_float2(acc[mi][ni][0], acc[mi][ni][1]);
                *(float2*)(S + (size_t)(r0 + 8) * SPN + cc) = make_float2(acc[mi][ni][2], acc[mi][ni][3]);
            }
        }
        __syncthreads();
        // tile is 128 wide = exactly one head (bn head-aligned)
        __half* C = (__half*)Cv;
        const float LG = 0.2076205059304640f;   // 2*log2(10000)/128
#pragma unroll 4
        for (int l = 0; l < 32; l++) {
            int idx = l * 256 + tid;             // 8192 rotation pairs
            int r  = idx >> 6;
            int d  = idx & 63;
            float x1 = S[(size_t)r * SPN + d];
            float x2 = S[(size_t)r * SPN + d + 64];
            int grow = bm + r;
            float pos = (float)(grow & (SEQ - 1));
            float invf = exp2f(-LG * (float)d);
            float ang = pos * invf;
            float sn, cs;
            sincosf(ang, &sn, &cs);
            size_t o = (size_t)grow * N + bn + d;
            C[o]      = __float2half((x1 * cs - x2 * sn) * rsc);
            C[o + 64] = __float2half((x2 * cs + x1 * sn) * rsc);
        }
    } else if (mode == 1) {
        __half* C = (__half*)Cv;
#pragma unroll
        for (int mi = 0; mi < 4; mi++) {
            int row0 = bm + wm + mi * 16 + g;
#pragma unroll
            for (int ni = 0; ni < 4; ni++) {
                int col = bn + wn + ni * 8 + tig * 2;
                *(__half2*)(C + (size_t)row0 * N + col) =
                    __floats2half2_rn(acc[mi][ni][0], acc[mi][ni][1]);
                *(__half2*)(C + (size_t)(row0 + 8) * N + col) =
                    __floats2half2_rn(acc[mi][ni][2], acc[mi][ni][3]);
            }
        }
    } else {
        float* C = (float*)Cv;
#pragma unroll
        for (int mi = 0; mi < 4; mi++) {
            int row0 = bm + wm + mi * 16 + g;
#pragma unroll
            for (int ni = 0; ni < 4; ni++) {
                int col = bn + wn + ni * 8 + tig * 2;
                *(float2*)(C + (size_t)row0 * N + col)       = make_float2(acc[mi][ni][0], acc[mi][ni][1]);
                *(float2*)(C + (size_t)(row0 + 8) * N + col) = make_float2(acc[mi][ni][2], acc[mi][ni][3]);
            }
        }
    }
}

// ---------------------------------------------------------------------------
// Flash attention v5: 128 threads (4 warps), Q tile 64, K tile 64,
// 2-stage cp.async K/V, 2 CTAs/SM so independent CTAs interleave phases.
// smem: Qs[64][136], KV 2x([64][136]+[64][136]), Ps[64][72]  = 96256 B
// ---------------------------------------------------------------------------
#define QP 136
#define VP 72
#define KVST (2 * 64 * QP)                      // halves per stage (K+V)
#define FL5_SMEM ((64*QP + 2*KVST + 64*VP) * 2) // 96256 bytes

__global__ __launch_bounds__(128, 2) void flash5(const __half* __restrict__ Q,
                                                 const __half* __restrict__ K,
                                                 const __half* __restrict__ V,
                                                 __half* __restrict__ O)
{
    extern __shared__ __half hs[];
    __half* Qs  = hs;                        // [64][136]
    __half* KV0 = Qs + 64 * QP;              // 2 stages: K[64][136] then V[64][136]
    __half* Ps  = KV0 + 2 * KVST;            // [64][72]

    const uint32_t sbQ  = smem_u32(Qs);
    const uint32_t sbKV = smem_u32(KV0);
    const uint32_t sbP  = smem_u32(Ps);
    __half2* P2 = (__half2*)Ps;

    const int qi  = (int)gridDim.x - 1 - (int)blockIdx.x;   // big tiles first
    const int h   = blockIdx.y;
    const int b   = blockIdx.z;
    const int kvh = h / GROUPS;
    const int tid = threadIdx.x;
    const int wid = tid >> 5, lane = tid & 31;
    const int g   = lane >> 2, tig = lane & 3;
    const int wq  = wid * 16;                 // 0..48
    const int l7  = lane & 7;
    const int lb3 = (lane >> 3) & 1;
    const int lb4 = lane >> 4;

    const __half* Qg = Q + (size_t)(b * SEQ + qi * 64) * QDIM + h * HD;
    const __half* Kg = K + (size_t)(b * SEQ) * KVDIM + kvh * HD;
    const __half* Vg = V + (size_t)(b * SEQ) * KVDIM + kvh * HD;

    auto load_kv = [&](int kb, int s) {
        const __half* Kt = Kg + (size_t)(kb * 64) * KVDIM;
        const __half* Vt = Vg + (size_t)(kb * 64) * KVDIM;
        uint32_t ks_ = sbKV + (uint32_t)s * (KVST * 2);
        uint32_t vs_ = ks_ + 64 * QP * 2;
#pragma unroll
        for (int l = 0; l < 8; l++) {
            int id = l * 128 + tid;
            int r = id >> 4, c8 = (id & 15) * 8;
            cpasync16(ks_ + (uint32_t)(r * QP + c8) * 2, Kt + (size_t)r * KVDIM + c8);
            cpasync16(vs_ + (uint32_t)(r * QP + c8) * 2, Vt + (size_t)r * KVDIM + c8);
        }
        CP_COMMIT();
    };

    // load Q tile (64 x 128 halves)
#pragma unroll
    for (int l = 0; l < 8; l++) {
        int id = l * 128 + tid;
        int r = id >> 4, c8 = (id & 15) * 8;
        *(uint4*)(Qs + r * QP + c8) = *(const uint4*)(Qg + (size_t)r * QDIM + c8);
    }

    float m0 = -INFINITY, m1 = -INFINITY, l0 = 0.f, l1 = 0.f;
    float oa[16][4];
#pragma unroll
    for (int ni = 0; ni < 16; ni++)
#pragma unroll
        for (int r = 0; r < 4; r++) oa[ni][r] = 0.f;

    const int kmax = qi + 1;
    load_kv(0, 0);

    for (int kb = 0; kb < kmax; kb++) {
        const int s = kb & 1;
        CP_WAIT(0);
        __syncthreads();
        if (kb + 1 < kmax) load_kv(kb + 1, s ^ 1);

        const uint32_t sK = sbKV + (uint32_t)s * (KVST * 2);
        const uint32_t sV = sK + 64 * QP * 2;

        // ---- S = Q K^T (warp: 16 x 64) ----
        float sa[8][4];
#pragma unroll
        for (int ni = 0; ni < 8; ni++)
#pragma unroll
            for (int r = 0; r < 4; r++) sa[ni][r] = 0.f;

#pragma unroll
        for (int ks = 0; ks < 8; ks++) {
            const int kc = ks * 16;
            uint32_t a[4], bfr[8][2];
            {
                uint32_t addr = sbQ + (uint32_t)((wq + l7 + lb3 * 8) * QP + kc + lb4 * 8) * 2;
                ldsm4(a[0], a[1], a[2], a[3], addr);
            }
#pragma unroll
            for (int nip = 0; nip < 4; nip++) {
                uint32_t addr = sK + (uint32_t)((nip * 16 + l7 + lb4 * 8) * QP + kc + lb3 * 8) * 2;
                ldsm4(bfr[nip*2][0], bfr[nip*2][1], bfr[nip*2+1][0], bfr[nip*2+1][1], addr);
            }
#pragma unroll
            for (int ni = 0; ni < 8; ni++)
                mma_f16(sa[ni], a, bfr[ni][0], bfr[ni][1]);
        }

        // ---- causal mask (diagonal tile only: kb == qi) ----
        if (kb == qi) {
            int r0 = qi * 64 + wq + g;
#pragma unroll
            for (int ni = 0; ni < 8; ni++) {
                int c0 = kb * 64 + ni * 8 + 2 * tig;
                if (c0 > r0)         sa[ni][0] = -INFINITY;
                if (c0 + 1 > r0)     sa[ni][1] = -INFINITY;
                if (c0 > r0 + 8)     sa[ni][2] = -INFINITY;
                if (c0 + 1 > r0 + 8) sa[ni][3] = -INFINITY;
            }
        }

        // ---- online softmax ----
        float mx0 = -INFINITY, mx1 = -INFINITY;
#pragma unroll
        for (int ni = 0; ni < 8; ni++) {
            mx0 = fmaxf(mx0, fmaxf(sa[ni][0], sa[ni][1]));
            mx1 = fmaxf(mx1, fmaxf(sa[ni][2], sa[ni][3]));
        }
        mx0 = fmaxf(mx0, __shfl_xor_sync(0xffffffffu, mx0, 1));
        mx0 = fmaxf(mx0, __shfl_xor_sync(0xffffffffu, mx0, 2));
        mx1 = fmaxf(mx1, __shfl_xor_sync(0xffffffffu, mx1, 1));
        mx1 = fmaxf(mx1, __shfl_xor_sync(0xffffffffu, mx1, 2));

        float mm0 = fmaxf(m0, mx0), mm1 = fmaxf(m1, mx1);
        float sub0 = (mm0 == -INFINITY) ? 0.f : mm0;
        float sub1 = (mm1 == -INFINITY) ? 0.f : mm1;
        float al0 = exp2f(m0 - sub0);
        float al1 = exp2f(m1 - sub1);
        m0 = mm0; m1 = mm1;

        float ls0 = 0.f, ls1 = 0.f;
#pragma unroll
        for (int ni = 0; ni < 8; ni++) {
            float p0 = exp2f(sa[ni][0] - sub0);
            float p1 = exp2f(sa[ni][1] - sub0);
            float p2 = exp2f(sa[ni][2] - sub1);
            float p3 = exp2f(sa[ni][3] - sub1);
            ls0 += p0 + p1; ls1 += p2 + p3;
            P2[(wq + g) * (VP/2) + ni * 4 + tig]     = __floats2half2_rn(p0, p1);
            P2[(wq + g + 8) * (VP/2) + ni * 4 + tig] = __floats2half2_rn(p2, p3);
        }
        ls0 += __shfl_xor_sync(0xffffffffu, ls0, 1);
        ls0 += __shfl_xor_sync(0xffffffffu, ls0, 2);
        ls1 += __shfl_xor_sync(0xffffffffu, ls1, 1);
        ls1 += __shfl_xor_sync(0xffffffffu, ls1, 2);
        l0 = l0 * al0 + ls0;
        l1 = l1 * al1 + ls1;

#pragma unroll
        for (int ni = 0; ni < 16; ni++) {
            oa[ni][0] *= al0; oa[ni][1] *= al0;
            oa[ni][2] *= al1; oa[ni][3] *= al1;
        }
        __syncwarp();   // Ps visibility within warp

        // ---- O += P @ V  (B = V via ldmatrix.trans) ----
#pragma unroll
        for (int ks = 0; ks < 4; ks++) {
            const int kc = ks * 16;
            uint32_t a[4];
            {
                uint32_t addr = sbP + (uint32_t)((wq + l7 + lb3 * 8) * VP + kc + lb4 * 8) * 2;
                ldsm4(a[0], a[1], a[2], a[3], addr);
            }
#pragma unroll
            for (int nip = 0; nip < 8; nip++) {
                uint32_t bf0, bf1, bf2, bf3;
                uint32_t addr = sV + (uint32_t)((kc + l7 + lb3 * 8) * QP + nip * 16 + lb4 * 8) * 2;
                ldsm4t(bf0, bf1, bf2, bf3, addr);
                mma_f16(oa[nip*2],     a, bf0, bf1);
                mma_f16(oa[nip*2 + 1], a, bf2, bf3);
            }
        }
    }

    // ---- epilogue ----
    float inv0 = 1.0f / l0, inv1 = 1.0f / l1;
    __half* Og = O + (size_t)(b * SEQ + qi * 64 + wq) * QDIM + h * HD;
#pragma unroll
    for (int ni = 0; ni < 16; ni++) {
        int col = ni * 8 + 2 * tig;
        *(__half2*)(Og + (size_t)g * QDIM + col) =
            __floats2half2_rn(oa[ni][0] * inv0, oa[ni][1] * inv0);
        *(__half2*)(Og + (size_t)(g + 8) * QDIM + col) =
            __floats2half2_rn(oa[ni][2] * inv1, oa[ni][3] * inv1);
    }
}

// ---------------------------------------------------------------------------
// Launch: conv_all -> grouped QKV gemm -> flash -> O gemm
// ---------------------------------------------------------------------------
extern "C" void kernel_launch(void* const* d_in, const int* in_sizes, int n_in,
                              void* d_out, int out_size)
{
    const float* query = (const float*)d_in[0];
    const float* key   = (const float*)d_in[1];
    const float* value = (const float*)d_in[2];
    const float* Wq = (const float*)d_in[5];
    const float* Wk = (const float*)d_in[6];
    const float* Wv = (const float*)d_in[7];
    const float* Wo = (const float*)d_in[8];
    float* out = (float*)d_out;

    __half *pQa, *pKa, *pVa, *pQh, *pKh, *pVh, *pAOh, *pWqh, *pWkh, *pWvh, *pWoh;
    cudaGetSymbolAddress((void**)&pQa,  g_Qa);
    cudaGetSymbolAddress((void**)&pKa,  g_Ka);
    cudaGetSymbolAddress((void**)&pVa,  g_Va);
    cudaGetSymbolAddress((void**)&pQh,  g_Qh);
    cudaGetSymbolAddress((void**)&pKh,  g_Kh);
    cudaGetSymbolAddress((void**)&pVh,  g_Vh);
    cudaGetSymbolAddress((void**)&pAOh, g_AOh);
    cudaGetSymbolAddress((void**)&pWqh, g_Wqh);
    cudaGetSymbolAddress((void**)&pWkh, g_Wkh);
    cudaGetSymbolAddress((void**)&pWvh, g_Wvh);
    cudaGetSymbolAddress((void**)&pWoh, g_Woh);

    cudaFuncSetAttribute(gemm_grp, cudaFuncAttributeMaxDynamicSharedMemorySize, GN_SMEM);
    cudaFuncSetAttribute(flash5,   cudaFuncAttributeMaxDynamicSharedMemorySize, FL5_SMEM);

    // one-shot conversion of everything to half
    ConvDesc cd;
    cd.src[0] = query; cd.dst[0] = pQa;  cd.nblk[0] = (MROWS * EMB) / 1024;
    cd.src[1] = key;   cd.dst[1] = pKa;  cd.nblk[1] = (MROWS * EMB) / 1024;
    cd.src[2] = value; cd.dst[2] = pVa;  cd.nblk[2] = (MROWS * EMB) / 1024;
    cd.src[3] = Wq;    cd.dst[3] = pWqh; cd.nblk[3] = (EMB * QDIM) / 1024;
    cd.src[4] = Wk;    cd.dst[4] = pWkh; cd.nblk[4] = (EMB * KVDIM) / 1024;
    cd.src[5] = Wv;    cd.dst[5] = pWvh; cd.nblk[5] = (EMB * KVDIM) / 1024;
    cd.src[6] = Wo;    cd.dst[6] = pWoh; cd.nblk[6] = (QDIM * EMB) / 1024;
    int total_blk = cd.nblk[0] + cd.nblk[1] + cd.nblk[2] + cd.nblk[3]
                  + cd.nblk[4] + cd.nblk[5] + cd.nblk[6];
    conv_all<<<total_blk, 256>>>(cd);

    // grouped Q+K+V projections (one launch; rope fused for Q,K)
    GroupArgs gq;
    gq.A[0] = pQa; gq.B[0] = pWqh; gq.C[0] = pQh; gq.N[0] = QDIM;  gq.mode[0] = 2; gq.rsc[0] = QSCALE; gq.xend[0] = 32;
    gq.A[1] = pKa; gq.B[1] = pWkh; gq.C[1] = pKh; gq.N[1] = KVDIM; gq.mode[1] = 2; gq.rsc[1] = 1.0f;   gq.xend[1] = 40;
    gq.A[2] = pVa; gq.B[2] = pWvh; gq.C[2] = pVh; gq.N[2] = KVDIM; gq.mode[2] = 1; gq.rsc[2] = 0.0f;   gq.xend[2] = 48;
    gq.nseg = 3;
    gemm_grp<<<dim3(48, MROWS / 128), 256, GN_SMEM>>>(gq, EMB);

    // attention (Q tile 64, 2 CTAs/SM)
    flash5<<<dim3(SEQ / 64, NH, BSZ), 128, FL5_SMEM>>>(pQh, pKh, pVh, pAOh);

    // output projection
    GroupArgs go;
    go.A[0] = pAOh; go.B[0] = pWoh; go.C[0] = out; go.N[0] = EMB; go.mode[0] = 0; go.rsc[0] = 0.0f; go.xend[0] = 32;
    go.nseg = 1;
    gemm_grp<<<dim3(32, MROWS / 128), 256, GN_SMEM>>>(go, QDIM);
}

// round 11
// speedup vs baseline: 1.0904x; 1.0630x over previous
#include <cuda_runtime.h>
#include <cuda_fp16.h>
#include <math.h>
#include <stdint.h>

#define BSZ   2
#define SEQ   2048
#define EMB   4096
#define NH    32
#define NKVH  8
#define HD    128
#define GROUPS (NH / NKVH)
#define MROWS (BSZ * SEQ)          // 4096
#define QDIM  (NH * HD)            // 4096
#define KVDIM (NKVH * HD)          // 1024

// log2(e)/sqrt(128), folded into Q so softmax uses bare exp2
#define QSCALE 0.12751744f

// Scratch (device globals)
__device__ __half g_Qa [(size_t)MROWS * EMB];    // half activations
__device__ __half g_Ka [(size_t)MROWS * EMB];
__device__ __half g_Va [(size_t)MROWS * EMB];
__device__ __half g_Qh [(size_t)MROWS * QDIM];   // post-rope half
__device__ __half g_Kh [(size_t)MROWS * KVDIM];
__device__ __half g_Vh [(size_t)MROWS * KVDIM];
__device__ __half g_AOh[(size_t)MROWS * QDIM];
__device__ __half g_Wqh[(size_t)EMB * QDIM];     // [K][N] half (no transpose)
__device__ __half g_Wkh[(size_t)EMB * KVDIM];
__device__ __half g_Wvh[(size_t)EMB * KVDIM];
__device__ __half g_Woh[(size_t)QDIM * EMB];

// ---------------------------------------------------------------------------
// Helpers
// ---------------------------------------------------------------------------
__device__ __forceinline__ uint32_t smem_u32(const void* p) {
    uint32_t a;
    asm("{ .reg .u64 t; cvta.to.shared.u64 t, %1; cvt.u32.u64 %0, t; }" : "=r"(a) : "l"(p));
    return a;
}
__device__ __forceinline__ void cpasync16(uint32_t dst, const void* src) {
    asm volatile("cp.async.cg.shared.global [%0], [%1], 16;" :: "r"(dst), "l"(src) : "memory");
}
#define CP_COMMIT() asm volatile("cp.async.commit_group;" ::: "memory")
#define CP_WAIT(n)  asm volatile("cp.async.wait_group %0;" :: "n"(n) : "memory")

__device__ __forceinline__ void mma_f16(float* d, const uint32_t* a, uint32_t b0, uint32_t b1) {
    asm volatile("mma.sync.aligned.m16n8k16.row.col.f32.f16.f16.f32 "
        "{%0,%1,%2,%3}, {%4,%5,%6,%7}, {%8,%9}, {%0,%1,%2,%3};"
        : "+f"(d[0]), "+f"(d[1]), "+f"(d[2]), "+f"(d[3])
        : "r"(a[0]), "r"(a[1]), "r"(a[2]), "r"(a[3]), "r"(b0), "r"(b1));
}
__device__ __forceinline__ void ldsm4(uint32_t& r0, uint32_t& r1, uint32_t& r2, uint32_t& r3,
                                      uint32_t addr) {
    asm volatile("ldmatrix.sync.aligned.m8n8.x4.shared.b16 {%0,%1,%2,%3}, [%4];"
        : "=r"(r0), "=r"(r1), "=r"(r2), "=r"(r3) : "r"(addr));
}
__device__ __forceinline__ void ldsm4t(uint32_t& r0, uint32_t& r1, uint32_t& r2, uint32_t& r3,
                                       uint32_t addr) {
    asm volatile("ldmatrix.sync.aligned.m8n8.x4.trans.shared.b16 {%0,%1,%2,%3}, [%4];"
        : "=r"(r0), "=r"(r1), "=r"(r2), "=r"(r3) : "r"(addr));
}

// ---------------------------------------------------------------------------
// One-shot fp32->half conversion of all 7 tensors. 1024 elems per block.
// ---------------------------------------------------------------------------
struct ConvDesc {
    const float* src[7];
    __half*      dst[7];
    int          nblk[7];
};

__global__ void conv_all(ConvDesc cd)
{
    int b = blockIdx.x;
    int seg = 0;
#pragma unroll
    for (int i = 0; i < 7; i++) {
        if (b >= cd.nblk[i]) { b -= cd.nblk[i]; seg = i + 1; }
        else break;
    }
    const float* src = cd.src[seg];
    __half* dst = cd.dst[seg];
    size_t i = ((size_t)b * 256 + threadIdx.x) * 4;
    float4 v = *(const float4*)(src + i);
    *(__half2*)(dst + i)     = __floats2half2_rn(v.x, v.y);
    *(__half2*)(dst + i + 2) = __floats2half2_rn(v.z, v.w);
}

// ---------------------------------------------------------------------------
// Grouped fp16 tensor-core GEMM: per segment C[M,N] = A[M,K] @ B[K,N]
// CTA tile 128x128, BK=64, 8 warps (64x32 warp tile), cp.async 3-stage,
// 2 CTAs/SM, single barrier per k-iter, ks+1 fragment double buffering,
// prefetch cp.async DE-BUNCHED across the 4 ks-steps.
// mode: 0 = fp32 out, 1 = half out, 2 = rope(+scale) half out.
// ---------------------------------------------------------------------------
#define HP  72                    // A row pitch (halves)
#define BPN 136                   // B row pitch (halves)
#define SPN 132                   // fp32 staging pitch (floats), mode 2
#define A_ST (128 * HP)           // halves
#define B_ST (64 * BPN)           // halves
#define STG_B ((A_ST + B_ST) * 2)            // 35840 bytes
#define GN_SMEM (3 * STG_B)                  // 107520 bytes

struct GroupArgs {
    const __half* A[3];
    const __half* B[3];
    void*         C[3];
    int           N[3];
    int           mode[3];
    float         rsc[3];
    int           xend[3];   // exclusive prefix ends in blockIdx.x
    int           nseg;
};

__global__ __launch_bounds__(256, 2) void gemm_grp(GroupArgs ga, int K)
{
    extern __shared__ __half smh[];
    const uint32_t sb = smem_u32(smh);

    // segment select (uniform per CTA)
    int bx = blockIdx.x;
    int seg = 0;
#pragma unroll
    for (int i = 0; i < 2; i++)
        if (i + 1 < ga.nseg && bx >= ga.xend[i]) seg = i + 1;
    const int xbase = (seg == 0) ? 0 : ga.xend[seg - 1];
    const __half* A = ga.A[seg];
    const __half* B = ga.B[seg];
    void* Cv        = ga.C[seg];
    const int N     = ga.N[seg];
    const int mode  = ga.mode[seg];
    const float rsc = ga.rsc[seg];

    const int tid  = threadIdx.x;
    const int wid  = tid >> 5, lane = tid & 31;
    const int g    = lane >> 2, tig = lane & 3;
    const int wm   = (wid >> 2) * 64;        // 0,64
    const int wn   = (wid & 3) * 32;         // 0..96
    const int bm   = blockIdx.y * 128, bn = (bx - xbase) * 128;

    auto load_tile = [&](int c, int s) {
        const __half* Ab = A + (size_t)bm * K + c * 64;
        const __half* Bb = B + (size_t)(c * 64) * N + bn;
        uint32_t sa  = sb + (uint32_t)s * STG_B;
        uint32_t sbb = sa + A_ST * 2;
#pragma unroll
        for (int l = 0; l < 4; l++) {
            int id = l * 256 + tid;
            int ra = id >> 3, ca = (id & 7) * 8;         // A: 128 x 64
            cpasync16(sa + (uint32_t)(ra * HP + ca) * 2, Ab + (size_t)ra * K + ca);
            int rb = id >> 4, cb = (id & 15) * 8;        // B: 64 x 128
            cpasync16(sbb + (uint32_t)(rb * BPN + cb) * 2, Bb + (size_t)rb * N + cb);
        }
        CP_COMMIT();
    };

    const int l7  = lane & 7;
    const int lb3 = (lane >> 3) & 1;
    const int lb4 = lane >> 4;

    float acc[4][4][4];
#pragma unroll
    for (int mi = 0; mi < 4; mi++)
#pragma unroll
        for (int ni = 0; ni < 4; ni++)
#pragma unroll
            for (int r = 0; r < 4; r++) acc[mi][ni][r] = 0.0f;

    const int iters = K / 64;
    load_tile(0, 0);
    load_tile(1, 1);

    uint32_t sA = 0, sBb = 0;
    uint32_t af[2][4][4], bf[2][2][4];

    auto load_frag = [&](int ks, int pb) {
        const int kb = ks * 16;
#pragma unroll
        for (int mi = 0; mi < 4; mi++) {
            uint32_t addr = sA + (uint32_t)((wm + mi * 16 + l7 + lb3 * 8) * HP
                                            + kb + lb4 * 8) * 2;
            ldsm4(af[pb][mi][0], af[pb][mi][1], af[pb][mi][2], af[pb][mi][3], addr);
        }
#pragma unroll
        for (int nj = 0; nj < 2; nj++) {
            uint32_t addr = sBb + (uint32_t)((kb + l7 + lb3 * 8) * BPN
                                             + wn + nj * 16 + lb4 * 8) * 2;
            ldsm4t(bf[pb][nj][0], bf[pb][nj][1], bf[pb][nj][2], bf[pb][nj][3], addr);
        }
    };

    for (int c = 0; c < iters; c++) {
        const int s = c % 3;
        if (c + 1 < iters) { CP_WAIT(1); } else { CP_WAIT(0); }
        __syncthreads();

        sA  = sb + (uint32_t)s * STG_B;
        sBb = sA + A_ST * 2;

        // next-next tile prefetch, de-bunched across ks-steps
        const bool pf = (c + 2 < iters);
        const __half* Abn = nullptr;
        const __half* Bbn = nullptr;
        uint32_t san = 0, sbn = 0;
        if (pf) {
            const int cn = c + 2, sn = cn % 3;
            Abn = A + (size_t)bm * K + cn * 64;
            Bbn = B + (size_t)(cn * 64) * N + bn;
            san = sb + (uint32_t)sn * STG_B;
            sbn = san + A_ST * 2;
        }

        load_frag(0, 0);
#pragma unroll
        for (int ks = 0; ks < 4; ks++) {
            if (pf) {
                int id = ks * 256 + tid;
                int ra = id >> 3, ca = (id & 7) * 8;
                cpasync16(san + (uint32_t)(ra * HP + ca) * 2, Abn + (size_t)ra * K + ca);
                int rb = id >> 4, cb = (id & 15) * 8;
                cpasync16(sbn + (uint32_t)(rb * BPN + cb) * 2, Bbn + (size_t)rb * N + cb);
            }
            const int cur = ks & 1;
            if (ks < 3) load_frag(ks + 1, cur ^ 1);
#pragma unroll
            for (int mi = 0; mi < 4; mi++)
#pragma unroll
                for (int nj = 0; nj < 2; nj++) {
                    mma_f16(acc[mi][nj * 2],     af[cur][mi], bf[cur][nj][0], bf[cur][nj][1]);
                    mma_f16(acc[mi][nj * 2 + 1], af[cur][mi], bf[cur][nj][2], bf[cur][nj][3]);
                }
        }
        if (pf) CP_COMMIT();
    }

    if (mode == 2) {
        // stage fp32 tile in smem, apply RoPE (+scale), write half
        __syncthreads();
        float* S = (float*)smh;
#pragma unroll
        for (int mi = 0; mi < 4; mi++) {
            int r0 = wm + mi * 16 + g;
#pragma unroll
            for (int ni = 0; ni < 4; ni++) {
                int cc = wn + ni * 8 + tig * 2;
                *(float2*)(S + (size_t)r0 * SPN + cc)       = make_float2(acc[mi][ni][0], acc[mi][ni][1]);
                *(float2*)(S + (size_t)(r0 + 8) * SPN + cc) = make_float2(acc[mi][ni][2], acc[mi][ni][3]);
            }
        }
        __syncthreads();
        // tile is 128 wide = exactly one head (bn head-aligned)
        __half* C = (__half*)Cv;
        const float LG = 0.2076205059304640f;   // 2*log2(10000)/128
#pragma unroll 4
        for (int l = 0; l < 32; l++) {
            int idx = l * 256 + tid;             // 8192 rotation pairs
            int r  = idx >> 6;
            int d  = idx & 63;
            float x1 = S[(size_t)r * SPN + d];
            float x2 = S[(size_t)r * SPN + d + 64];
            int grow = bm + r;
            float pos = (float)(grow & (SEQ - 1));
            float invf = exp2f(-LG * (float)d);
            float ang = pos * invf;
            float sn, cs;
            sincosf(ang, &sn, &cs);
            size_t o = (size_t)grow * N + bn + d;
            C[o]      = __float2half((x1 * cs - x2 * sn) * rsc);
            C[o + 64] = __float2half((x2 * cs + x1 * sn) * rsc);
        }
    } else if (mode == 1) {
        __half* C = (__half*)Cv;
#pragma unroll
        for (int mi = 0; mi < 4; mi++) {
            int row0 = bm + wm + mi * 16 + g;
#pragma unroll
            for (int ni = 0; ni < 4; ni++) {
                int col = bn + wn + ni * 8 + tig * 2;
                *(__half2*)(C + (size_t)row0 * N + col) =
                    __floats2half2_rn(acc[mi][ni][0], acc[mi][ni][1]);
                *(__half2*)(C + (size_t)(row0 + 8) * N + col) =
                    __floats2half2_rn(acc[mi][ni][2], acc[mi][ni][3]);
            }
        }
    } else {
        float* C = (float*)Cv;
#pragma unroll
        for (int mi = 0; mi < 4; mi++) {
            int row0 = bm + wm + mi * 16 + g;
#pragma unroll
            for (int ni = 0; ni < 4; ni++) {
                int col = bn + wn + ni * 8 + tig * 2;
                *(float2*)(C + (size_t)row0 * N + col)       = make_float2(acc[mi][ni][0], acc[mi][ni][1]);
                *(float2*)(C + (size_t)(row0 + 8) * N + col) = make_float2(acc[mi][ni][2], acc[mi][ni][3]);
            }
        }
    }
}

// ---------------------------------------------------------------------------
// Flash attention v6: 128 threads (4 warps), Q tile 64, K tile 64,
// 2-stage cp.async K/V (issues de-bunched across the S ks-loop), 2 CTAs/SM.
// smem: Qs[64][136], KV 2x([64][136]+[64][136]), Ps[64][72]  = 96256 B
// ---------------------------------------------------------------------------
#define QP 136
#define VP 72
#define KVST (2 * 64 * QP)                      // halves per stage (K+V)
#define FL6_SMEM ((64*QP + 2*KVST + 64*VP) * 2) // 96256 bytes

__global__ __launch_bounds__(128, 2) void flash6(const __half* __restrict__ Q,
                                                 const __half* __restrict__ K,
                                                 const __half* __restrict__ V,
                                                 __half* __restrict__ O)
{
    extern __shared__ __half hs[];
    __half* Qs  = hs;                        // [64][136]
    __half* KV0 = Qs + 64 * QP;              // 2 stages: K[64][136] then V[64][136]
    __half* Ps  = KV0 + 2 * KVST;            // [64][72]

    const uint32_t sbQ  = smem_u32(Qs);
    const uint32_t sbKV = smem_u32(KV0);
    const uint32_t sbP  = smem_u32(Ps);
    __half2* P2 = (__half2*)Ps;

    const int qi  = (int)gridDim.x - 1 - (int)blockIdx.x;   // big tiles first
    const int h   = blockIdx.y;
    const int b   = blockIdx.z;
    const int kvh = h / GROUPS;
    const int tid = threadIdx.x;
    const int wid = tid >> 5, lane = tid & 31;
    const int g   = lane >> 2, tig = lane & 3;
    const int wq  = wid * 16;                 // 0..48
    const int l7  = lane & 7;
    const int lb3 = (lane >> 3) & 1;
    const int lb4 = lane >> 4;

    const __half* Qg = Q + (size_t)(b * SEQ + qi * 64) * QDIM + h * HD;
    const __half* Kg = K + (size_t)(b * SEQ) * KVDIM + kvh * HD;
    const __half* Vg = V + (size_t)(b * SEQ) * KVDIM + kvh * HD;

    auto load_kv_full = [&](int kb, int s) {
        const __half* Kt = Kg + (size_t)(kb * 64) * KVDIM;
        const __half* Vt = Vg + (size_t)(kb * 64) * KVDIM;
        uint32_t ks_ = sbKV + (uint32_t)s * (KVST * 2);
        uint32_t vs_ = ks_ + 64 * QP * 2;
#pragma unroll
        for (int l = 0; l < 8; l++) {
            int id = l * 128 + tid;
            int r = id >> 4, c8 = (id & 15) * 8;
            cpasync16(ks_ + (uint32_t)(r * QP + c8) * 2, Kt + (size_t)r * KVDIM + c8);
            cpasync16(vs_ + (uint32_t)(r * QP + c8) * 2, Vt + (size_t)r * KVDIM + c8);
        }
        CP_COMMIT();
    };

    // load Q tile (64 x 128 halves)
#pragma unroll
    for (int l = 0; l < 8; l++) {
        int id = l * 128 + tid;
        int r = id >> 4, c8 = (id & 15) * 8;
        *(uint4*)(Qs + r * QP + c8) = *(const uint4*)(Qg + (size_t)r * QDIM + c8);
    }

    float m0 = -INFINITY, m1 = -INFINITY, l0 = 0.f, l1 = 0.f;
    float oa[16][4];
#pragma unroll
    for (int ni = 0; ni < 16; ni++)
#pragma unroll
        for (int r = 0; r < 4; r++) oa[ni][r] = 0.f;

    const int kmax = qi + 1;
    load_kv_full(0, 0);

    for (int kb = 0; kb < kmax; kb++) {
        const int s = kb & 1;
        CP_WAIT(0);
        __syncthreads();

        const uint32_t sK = sbKV + (uint32_t)s * (KVST * 2);
        const uint32_t sV = sK + 64 * QP * 2;

        // next K/V prefetch, de-bunched over S ks-loop
        const bool pf = (kb + 1 < kmax);
        const __half *Ktn = nullptr, *Vtn = nullptr;
        uint32_t ksn = 0, vsn = 0;
        if (pf) {
            Ktn = Kg + (size_t)((kb + 1) * 64) * KVDIM;
            Vtn = Vg + (size_t)((kb + 1) * 64) * KVDIM;
            ksn = sbKV + (uint32_t)(s ^ 1) * (KVST * 2);
            vsn = ksn + 64 * QP * 2;
        }

        // ---- S = Q K^T (warp: 16 x 64) ----
        float sa[8][4];
#pragma unroll
        for (int ni = 0; ni < 8; ni++)
#pragma unroll
            for (int r = 0; r < 4; r++) sa[ni][r] = 0.f;

#pragma unroll
        for (int ks = 0; ks < 8; ks++) {
            if (pf) {
                int id = ks * 128 + tid;
                int r = id >> 4, c8 = (id & 15) * 8;
                cpasync16(ksn + (uint32_t)(r * QP + c8) * 2, Ktn + (size_t)r * KVDIM + c8);
                cpasync16(vsn + (uint32_t)(r * QP + c8) * 2, Vtn + (size_t)r * KVDIM + c8);
            }
            const int kc = ks * 16;
            uint32_t a[4], bfr[8][2];
            {
                uint32_t addr = sbQ + (uint32_t)((wq + l7 + lb3 * 8) * QP + kc + lb4 * 8) * 2;
                ldsm4(a[0], a[1], a[2], a[3], addr);
            }
#pragma unroll
            for (int nip = 0; nip < 4; nip++) {
                uint32_t addr = sK + (uint32_t)((nip * 16 + l7 + lb4 * 8) * QP + kc + lb3 * 8) * 2;
                ldsm4(bfr[nip*2][0], bfr[nip*2][1], bfr[nip*2+1][0], bfr[nip*2+1][1], addr);
            }
#pragma unroll
            for (int ni = 0; ni < 8; ni++)
                mma_f16(sa[ni], a, bfr[ni][0], bfr[ni][1]);
        }
        if (pf) CP_COMMIT();

        // ---- causal mask (diagonal tile only: kb == qi) ----
        if (kb == qi) {
            int r0 = qi * 64 + wq + g;
#pragma unroll
            for (int ni = 0; ni < 8; ni++) {
                int c0 = kb * 64 + ni * 8 + 2 * tig;
                if (c0 > r0)         sa[ni][0] = -INFINITY;
                if (c0 + 1 > r0)     sa[ni][1] = -INFINITY;
                if (c0 > r0 + 8)     sa[ni][2] = -INFINITY;
                if (c0 + 1 > r0 + 8) sa[ni][3] = -INFINITY;
            }
        }

        // ---- online softmax ----
        float mx0 = -INFINITY, mx1 = -INFINITY;
#pragma unroll
        for (int ni = 0; ni < 8; ni++) {
            mx0 = fmaxf(mx0, fmaxf(sa[ni][0], sa[ni][1]));
            mx1 = fmaxf(mx1, fmaxf(sa[ni][2], sa[ni][3]));
        }
        mx0 = fmaxf(mx0, __shfl_xor_sync(0xffffffffu, mx0, 1));
        mx0 = fmaxf(mx0, __shfl_xor_sync(0xffffffffu, mx0, 2));
        mx1 = fmaxf(mx1, __shfl_xor_sync(0xffffffffu, mx1, 1));
        mx1 = fmaxf(mx1, __shfl_xor_sync(0xffffffffu, mx1, 2));

        float mm0 = fmaxf(m0, mx0), mm1 = fmaxf(m1, mx1);
        float sub0 = (mm0 == -INFINITY) ? 0.f : mm0;
        float sub1 = (mm1 == -INFINITY) ? 0.f : mm1;
        float al0 = exp2f(m0 - sub0);
        float al1 = exp2f(m1 - sub1);
        m0 = mm0; m1 = mm1;

        float ls0 = 0.f, ls1 = 0.f;
#pragma unroll
        for (int ni = 0; ni < 8; ni++) {
            float p0 = exp2f(sa[ni][0] - sub0);
            float p1 = exp2f(sa[ni][1] - sub0);
            float p2 = exp2f(sa[ni][2] - sub1);
            float p3 = exp2f(sa[ni][3] - sub1);
            ls0 += p0 + p1; ls1 += p2 + p3;
            P2[(wq + g) * (VP/2) + ni * 4 + tig]     = __floats2half2_rn(p0, p1);
            P2[(wq + g + 8) * (VP/2) + ni * 4 + tig] = __floats2half2_rn(p2, p3);
        }
        ls0 += __shfl_xor_sync(0xffffffffu, ls0, 1);
        ls0 += __shfl_xor_sync(0xffffffffu, ls0, 2);
        ls1 += __shfl_xor_sync(0xffffffffu, ls1, 1);
        ls1 += __shfl_xor_sync(0xffffffffu, ls1, 2);
        l0 = l0 * al0 + ls0;
        l1 = l1 * al1 + ls1;

#pragma unroll
        for (int ni = 0; ni < 16; ni++) {
            oa[ni][0] *= al0; oa[ni][1] *= al0;
            oa[ni][2] *= al1; oa[ni][3] *= al1;
        }
        __syncwarp();   // Ps visibility within warp

        // ---- O += P @ V  (B = V via ldmatrix.trans) ----
#pragma unroll
        for (int ks = 0; ks < 4; ks++) {
            const int kc = ks * 16;
            uint32_t a[4];
            {
                uint32_t addr = sbP + (uint32_t)((wq + l7 + lb3 * 8) * VP + kc + lb4 * 8) * 2;
                ldsm4(a[0], a[1], a[2], a[3], addr);
            }
#pragma unroll
            for (int nip = 0; nip < 8; nip++) {
                uint32_t bf0, bf1, bf2, bf3;
                uint32_t addr = sV + (uint32_t)((kc + l7 + lb3 * 8) * QP + nip * 16 + lb4 * 8) * 2;
                ldsm4t(bf0, bf1, bf2, bf3, addr);
                mma_f16(oa[nip*2],     a, bf0, bf1);
                mma_f16(oa[nip*2 + 1], a, bf2, bf3);
            }
        }
    }

    // ---- epilogue ----
    float inv0 = 1.0f / l0, inv1 = 1.0f / l1;
    __half* Og = O + (size_t)(b * SEQ + qi * 64 + wq) * QDIM + h * HD;
#pragma unroll
    for (int ni = 0; ni < 16; ni++) {
        int col = ni * 8 + 2 * tig;
        *(__half2*)(Og + (size_t)g * QDIM + col) =
            __floats2half2_rn(oa[ni][0] * inv0, oa[ni][1] * inv0);
        *(__half2*)(Og + (size_t)(g + 8) * QDIM + col) =
            __floats2half2_rn(oa[ni][2] * inv1, oa[ni][3] * inv1);
    }
}

// ---------------------------------------------------------------------------
// Launch: conv_all -> grouped QKV gemm -> flash -> O gemm
// ---------------------------------------------------------------------------
extern "C" void kernel_launch(void* const* d_in, const int* in_sizes, int n_in,
                              void* d_out, int out_size)
{
    const float* query = (const float*)d_in[0];
    const float* key   = (const float*)d_in[1];
    const float* value = (const float*)d_in[2];
    const float* Wq = (const float*)d_in[5];
    const float* Wk = (const float*)d_in[6];
    const float* Wv = (const float*)d_in[7];
    const float* Wo = (const float*)d_in[8];
    float* out = (float*)d_out;

    __half *pQa, *pKa, *pVa, *pQh, *pKh, *pVh, *pAOh, *pWqh, *pWkh, *pWvh, *pWoh;
    cudaGetSymbolAddress((void**)&pQa,  g_Qa);
    cudaGetSymbolAddress((void**)&pKa,  g_Ka);
    cudaGetSymbolAddress((void**)&pVa,  g_Va);
    cudaGetSymbolAddress((void**)&pQh,  g_Qh);
    cudaGetSymbolAddress((void**)&pKh,  g_Kh);
    cudaGetSymbolAddress((void**)&pVh,  g_Vh);
    cudaGetSymbolAddress((void**)&pAOh, g_AOh);
    cudaGetSymbolAddress((void**)&pWqh, g_Wqh);
    cudaGetSymbolAddress((void**)&pWkh, g_Wkh);
    cudaGetSymbolAddress((void**)&pWvh, g_Wvh);
    cudaGetSymbolAddress((void**)&pWoh, g_Woh);

    cudaFuncSetAttribute(gemm_grp, cudaFuncAttributeMaxDynamicSharedMemorySize, GN_SMEM);
    cudaFuncSetAttribute(flash6,   cudaFuncAttributeMaxDynamicSharedMemorySize, FL6_SMEM);

    // one-shot conversion of everything to half
    ConvDesc cd;
    cd.src[0] = query; cd.dst[0] = pQa;  cd.nblk[0] = (MROWS * EMB) / 1024;
    cd.src[1] = key;   cd.dst[1] = pKa;  cd.nblk[1] = (MROWS * EMB) / 1024;
    cd.src[2] = value; cd.dst[2] = pVa;  cd.nblk[2] = (MROWS * EMB) / 1024;
    cd.src[3] = Wq;    cd.dst[3] = pWqh; cd.nblk[3] = (EMB * QDIM) / 1024;
    cd.src[4] = Wk;    cd.dst[4] = pWkh; cd.nblk[4] = (EMB * KVDIM) / 1024;
    cd.src[5] = Wv;    cd.dst[5] = pWvh; cd.nblk[5] = (EMB * KVDIM) / 1024;
    cd.src[6] = Wo;    cd.dst[6] = pWoh; cd.nblk[6] = (QDIM * EMB) / 1024;
    int total_blk = cd.nblk[0] + cd.nblk[1] + cd.nblk[2] + cd.nblk[3]
                  + cd.nblk[4] + cd.nblk[5] + cd.nblk[6];
    conv_all<<<total_blk, 256>>>(cd);

    // grouped Q+K+V projections (one launch; rope fused for Q,K)
    GroupArgs gq;
    gq.A[0] = pQa; gq.B[0] = pWqh; gq.C[0] = pQh; gq.N[0] = QDIM;  gq.mode[0] = 2; gq.rsc[0] = QSCALE; gq.xend[0] = 32;
    gq.A[1] = pKa; gq.B[1] = pWkh; gq.C[1] = pKh; gq.N[1] = KVDIM; gq.mode[1] = 2; gq.rsc[1] = 1.0f;   gq.xend[1] = 40;
    gq.A[2] = pVa; gq.B[2] = pWvh; gq.C[2] = pVh; gq.N[2] = KVDIM; gq.mode[2] = 1; gq.rsc[2] = 0.0f;   gq.xend[2] = 48;
    gq.nseg = 3;
    gemm_grp<<<dim3(48, MROWS / 128), 256, GN_SMEM>>>(gq, EMB);

    // attention (Q tile 64, 2 CTAs/SM, de-bunched prefetch)
    flash6<<<dim3(SEQ / 64, NH, BSZ), 128, FL6_SMEM>>>(pQh, pKh, pVh, pAOh);

    // output projection
    GroupArgs go;
    go.A[0] = pAOh; go.B[0] = pWoh; go.C[0] = out; go.N[0] = EMB; go.mode[0] = 0; go.rsc[0] = 0.0f; go.xend[0] = 32;
    go.nseg = 1;
    gemm_grp<<<dim3(32, MROWS / 128), 256, GN_SMEM>>>(go, QDIM);
}

// round 12
// speedup vs baseline: 1.1022x; 1.0108x over previous
#include <cuda_runtime.h>
#include <cuda_fp16.h>
#include <math.h>
#include <stdint.h>

#define BSZ   2
#define SEQ   2048
#define EMB   4096
#define NH    32
#define NKVH  8
#define HD    128
#define GROUPS (NH / NKVH)
#define MROWS (BSZ * SEQ)          // 4096
#define QDIM  (NH * HD)            // 4096
#define KVDIM (NKVH * HD)          // 1024

// log2(e)/sqrt(128), folded into Q so softmax uses bare exp2
#define QSCALE 0.12751744f

// Scratch (device globals)
__device__ __half g_Qa [(size_t)MROWS * EMB];    // half activations
__device__ __half g_Ka [(size_t)MROWS * EMB];
__device__ __half g_Va [(size_t)MROWS * EMB];
__device__ __half g_Qh [(size_t)MROWS * QDIM];   // post-rope half
__device__ __half g_Kh [(size_t)MROWS * KVDIM];
__device__ __half g_Vh [(size_t)MROWS * KVDIM];
__device__ __half g_AOh[(size_t)MROWS * QDIM];
__device__ __half g_Wqh[(size_t)EMB * QDIM];     // [K][N] half (no transpose)
__device__ __half g_Wkh[(size_t)EMB * KVDIM];
__device__ __half g_Wvh[(size_t)EMB * KVDIM];
__device__ __half g_Woh[(size_t)QDIM * EMB];

// ---------------------------------------------------------------------------
// Helpers
// ---------------------------------------------------------------------------
__device__ __forceinline__ uint32_t smem_u32(const void* p) {
    uint32_t a;
    asm("{ .reg .u64 t; cvta.to.shared.u64 t, %1; cvt.u32.u64 %0, t; }" : "=r"(a) : "l"(p));
    return a;
}
__device__ __forceinline__ void cpasync16(uint32_t dst, const void* src) {
    asm volatile("cp.async.cg.shared.global [%0], [%1], 16;" :: "r"(dst), "l"(src) : "memory");
}
#define CP_COMMIT() asm volatile("cp.async.commit_group;" ::: "memory")
#define CP_WAIT(n)  asm volatile("cp.async.wait_group %0;" :: "n"(n) : "memory")

__device__ __forceinline__ void mma_f16(float* d, const uint32_t* a, uint32_t b0, uint32_t b1) {
    asm volatile("mma.sync.aligned.m16n8k16.row.col.f32.f16.f16.f32 "
        "{%0,%1,%2,%3}, {%4,%5,%6,%7}, {%8,%9}, {%0,%1,%2,%3};"
        : "+f"(d[0]), "+f"(d[1]), "+f"(d[2]), "+f"(d[3])
        : "r"(a[0]), "r"(a[1]), "r"(a[2]), "r"(a[3]), "r"(b0), "r"(b1));
}
__device__ __forceinline__ void ldsm4(uint32_t& r0, uint32_t& r1, uint32_t& r2, uint32_t& r3,
                                      uint32_t addr) {
    asm volatile("ldmatrix.sync.aligned.m8n8.x4.shared.b16 {%0,%1,%2,%3}, [%4];"
        : "=r"(r0), "=r"(r1), "=r"(r2), "=r"(r3) : "r"(addr));
}
__device__ __forceinline__ void ldsm4t(uint32_t& r0, uint32_t& r1, uint32_t& r2, uint32_t& r3,
                                       uint32_t addr) {
    asm volatile("ldmatrix.sync.aligned.m8n8.x4.trans.shared.b16 {%0,%1,%2,%3}, [%4];"
        : "=r"(r0), "=r"(r1), "=r"(r2), "=r"(r3) : "r"(addr));
}
__device__ __forceinline__ uint32_t pack_h2(float a, float b) {
    __half2 h = __floats2half2_rn(a, b);
    return *(uint32_t*)&h;
}

// ---------------------------------------------------------------------------
// One-shot fp32->half conversion of all 7 tensors. 1024 elems per block.
// ---------------------------------------------------------------------------
struct ConvDesc {
    const float* src[7];
    __half*      dst[7];
    int          nblk[7];
};

__global__ void conv_all(ConvDesc cd)
{
    int b = blockIdx.x;
    int seg = 0;
#pragma unroll
    for (int i = 0; i < 7; i++) {
        if (b >= cd.nblk[i]) { b -= cd.nblk[i]; seg = i + 1; }
        else break;
    }
    const float* src = cd.src[seg];
    __half* dst = cd.dst[seg];
    size_t i = ((size_t)b * 256 + threadIdx.x) * 4;
    float4 v = *(const float4*)(src + i);
    *(__half2*)(dst + i)     = __floats2half2_rn(v.x, v.y);
    *(__half2*)(dst + i + 2) = __floats2half2_rn(v.z, v.w);
}

// ---------------------------------------------------------------------------
// Grouped fp16 tensor-core GEMM (unchanged from R11).
// ---------------------------------------------------------------------------
#define HP  72
#define BPN 136
#define SPN 132
#define A_ST (128 * HP)
#define B_ST (64 * BPN)
#define STG_B ((A_ST + B_ST) * 2)
#define GN_SMEM (3 * STG_B)

struct GroupArgs {
    const __half* A[3];
    const __half* B[3];
    void*         C[3];
    int           N[3];
    int           mode[3];
    float         rsc[3];
    int           xend[3];
    int           nseg;
};

__global__ __launch_bounds__(256, 2) void gemm_grp(GroupArgs ga, int K)
{
    extern __shared__ __half smh[];
    const uint32_t sb = smem_u32(smh);

    int bx = blockIdx.x;
    int seg = 0;
#pragma unroll
    for (int i = 0; i < 2; i++)
        if (i + 1 < ga.nseg && bx >= ga.xend[i]) seg = i + 1;
    const int xbase = (seg == 0) ? 0 : ga.xend[seg - 1];
    const __half* A = ga.A[seg];
    const __half* B = ga.B[seg];
    void* Cv        = ga.C[seg];
    const int N     = ga.N[seg];
    const int mode  = ga.mode[seg];
    const float rsc = ga.rsc[seg];

    const int tid  = threadIdx.x;
    const int wid  = tid >> 5, lane = tid & 31;
    const int g    = lane >> 2, tig = lane & 3;
    const int wm   = (wid >> 2) * 64;
    const int wn   = (wid & 3) * 32;
    const int bm   = blockIdx.y * 128, bn = (bx - xbase) * 128;

    auto load_tile = [&](int c, int s) {
        const __half* Ab = A + (size_t)bm * K + c * 64;
        const __half* Bb = B + (size_t)(c * 64) * N + bn;
        uint32_t sa  = sb + (uint32_t)s * STG_B;
        uint32_t sbb = sa + A_ST * 2;
#pragma unroll
        for (int l = 0; l < 4; l++) {
            int id = l * 256 + tid;
            int ra = id >> 3, ca = (id & 7) * 8;
            cpasync16(sa + (uint32_t)(ra * HP + ca) * 2, Ab + (size_t)ra * K + ca);
            int rb = id >> 4, cb = (id & 15) * 8;
            cpasync16(sbb + (uint32_t)(rb * BPN + cb) * 2, Bb + (size_t)rb * N + cb);
        }
        CP_COMMIT();
    };

    const int l7  = lane & 7;
    const int lb3 = (lane >> 3) & 1;
    const int lb4 = lane >> 4;

    float acc[4][4][4];
#pragma unroll
    for (int mi = 0; mi < 4; mi++)
#pragma unroll
        for (int ni = 0; ni < 4; ni++)
#pragma unroll
            for (int r = 0; r < 4; r++) acc[mi][ni][r] = 0.0f;

    const int iters = K / 64;
    load_tile(0, 0);
    load_tile(1, 1);

    uint32_t sA = 0, sBb = 0;
    uint32_t af[2][4][4], bf[2][2][4];

    auto load_frag = [&](int ks, int pb) {
        const int kb = ks * 16;
#pragma unroll
        for (int mi = 0; mi < 4; mi++) {
            uint32_t addr = sA + (uint32_t)((wm + mi * 16 + l7 + lb3 * 8) * HP
                                            + kb + lb4 * 8) * 2;
            ldsm4(af[pb][mi][0], af[pb][mi][1], af[pb][mi][2], af[pb][mi][3], addr);
        }
#pragma unroll
        for (int nj = 0; nj < 2; nj++) {
            uint32_t addr = sBb + (uint32_t)((kb + l7 + lb3 * 8) * BPN
                                             + wn + nj * 16 + lb4 * 8) * 2;
            ldsm4t(bf[pb][nj][0], bf[pb][nj][1], bf[pb][nj][2], bf[pb][nj][3], addr);
        }
    };

    for (int c = 0; c < iters; c++) {
        const int s = c % 3;
        if (c + 1 < iters) { CP_WAIT(1); } else { CP_WAIT(0); }
        __syncthreads();

        sA  = sb + (uint32_t)s * STG_B;
        sBb = sA + A_ST * 2;

        const bool pf = (c + 2 < iters);
        const __half* Abn = nullptr;
        const __half* Bbn = nullptr;
        uint32_t san = 0, sbn = 0;
        if (pf) {
            const int cn = c + 2, sn = cn % 3;
            Abn = A + (size_t)bm * K + cn * 64;
            Bbn = B + (size_t)(cn * 64) * N + bn;
            san = sb + (uint32_t)sn * STG_B;
            sbn = san + A_ST * 2;
        }

        load_frag(0, 0);
#pragma unroll
        for (int ks = 0; ks < 4; ks++) {
            if (pf) {
                int id = ks * 256 + tid;
                int ra = id >> 3, ca = (id & 7) * 8;
                cpasync16(san + (uint32_t)(ra * HP + ca) * 2, Abn + (size_t)ra * K + ca);
                int rb = id >> 4, cb = (id & 15) * 8;
                cpasync16(sbn + (uint32_t)(rb * BPN + cb) * 2, Bbn + (size_t)rb * N + cb);
            }
            const int cur = ks & 1;
            if (ks < 3) load_frag(ks + 1, cur ^ 1);
#pragma unroll
            for (int mi = 0; mi < 4; mi++)
#pragma unroll
                for (int nj = 0; nj < 2; nj++) {
                    mma_f16(acc[mi][nj * 2],     af[cur][mi], bf[cur][nj][0], bf[cur][nj][1]);
                    mma_f16(acc[mi][nj * 2 + 1], af[cur][mi], bf[cur][nj][2], bf[cur][nj][3]);
                }
        }
        if (pf) CP_COMMIT();
    }

    if (mode == 2) {
        __syncthreads();
        float* S = (float*)smh;
#pragma unroll
        for (int mi = 0; mi < 4; mi++) {
            int r0 = wm + mi * 16 + g;
#pragma unroll
            for (int ni = 0; ni < 4; ni++) {
                int cc = wn + ni * 8 + tig * 2;
                *(float2*)(S + (size_t)r0 * SPN + cc)       = make_float2(acc[mi][ni][0], acc[mi][ni][1]);
                *(float2*)(S + (size_t)(r0 + 8) * SPN + cc) = make_float2(acc[mi][ni][2], acc[mi][ni][3]);
            }
        }
        __syncthreads();
        __half* C = (__half*)Cv;
        const float LG = 0.2076205059304640f;   // 2*log2(10000)/128
#pragma unroll 4
        for (int l = 0; l < 32; l++) {
            int idx = l * 256 + tid;
            int r  = idx >> 6;
            int d  = idx & 63;
            float x1 = S[(size_t)r * SPN + d];
            float x2 = S[(size_t)r * SPN + d + 64];
            int grow = bm + r;
            float pos = (float)(grow & (SEQ - 1));
            float invf = exp2f(-LG * (float)d);
            float ang = pos * invf;
            float sn, cs;
            sincosf(ang, &sn, &cs);
            size_t o = (size_t)grow * N + bn + d;
            C[o]      = __float2half((x1 * cs - x2 * sn) * rsc);
            C[o + 64] = __float2half((x2 * cs + x1 * sn) * rsc);
        }
    } else if (mode == 1) {
        __half* C = (__half*)Cv;
#pragma unroll
        for (int mi = 0; mi < 4; mi++) {
            int row0 = bm + wm + mi * 16 + g;
#pragma unroll
            for (int ni = 0; ni < 4; ni++) {
                int col = bn + wn + ni * 8 + tig * 2;
                *(__half2*)(C + (size_t)row0 * N + col) =
                    __floats2half2_rn(acc[mi][ni][0], acc[mi][ni][1]);
                *(__half2*)(C + (size_t)(row0 + 8) * N + col) =
                    __floats2half2_rn(acc[mi][ni][2], acc[mi][ni][3]);
            }
        }
    } else {
        float* C = (float*)Cv;
#pragma unroll
        for (int mi = 0; mi < 4; mi++) {
            int row0 = bm + wm + mi * 16 + g;
#pragma unroll
            for (int ni = 0; ni < 4; ni++) {
                int col = bn + wn + ni * 8 + tig * 2;
                *(float2*)(C + (size_t)row0 * N + col)       = make_float2(acc[mi][ni][0], acc[mi][ni][1]);
                *(float2*)(C + (size_t)(row0 + 8) * N + col) = make_float2(acc[mi][ni][2], acc[mi][ni][3]);
            }
        }
    }
}

// ---------------------------------------------------------------------------
// Flash attention v7: P kept in registers (S C-fragment == PV A-fragment),
// no P smem, no syncwarp. 128 threads, Q tile 64, K tile 64, 2-stage
// de-bunched cp.async K/V, 2 CTAs/SM.
// smem: Qs[64][136], KV 2x([64][136]+[64][136])  = 87040 B
// ---------------------------------------------------------------------------
#define QP 136
#define KVST (2 * 64 * QP)                      // halves per stage (K+V)
#define FL7_SMEM ((64*QP + 2*KVST) * 2)         // 87040 bytes

__global__ __launch_bounds__(128, 2) void flash7(const __half* __restrict__ Q,
                                                 const __half* __restrict__ K,
                                                 const __half* __restrict__ V,
                                                 __half* __restrict__ O)
{
    extern __shared__ __half hs[];
    __half* Qs  = hs;                        // [64][136]
    __half* KV0 = Qs + 64 * QP;              // 2 stages: K[64][136] then V[64][136]

    const uint32_t sbQ  = smem_u32(Qs);
    const uint32_t sbKV = smem_u32(KV0);

    const int qi  = (int)gridDim.x - 1 - (int)blockIdx.x;   // big tiles first
    const int h   = blockIdx.y;
    const int b   = blockIdx.z;
    const int kvh = h / GROUPS;
    const int tid = threadIdx.x;
    const int wid = tid >> 5, lane = tid & 31;
    const int g   = lane >> 2, tig = lane & 3;
    const int wq  = wid * 16;                 // 0..48
    const int l7  = lane & 7;
    const int lb3 = (lane >> 3) & 1;
    const int lb4 = lane >> 4;

    const __half* Qg = Q + (size_t)(b * SEQ + qi * 64) * QDIM + h * HD;
    const __half* Kg = K + (size_t)(b * SEQ) * KVDIM + kvh * HD;
    const __half* Vg = V + (size_t)(b * SEQ) * KVDIM + kvh * HD;

    auto load_kv_full = [&](int kb, int s) {
        const __half* Kt = Kg + (size_t)(kb * 64) * KVDIM;
        const __half* Vt = Vg + (size_t)(kb * 64) * KVDIM;
        uint32_t ks_ = sbKV + (uint32_t)s * (KVST * 2);
        uint32_t vs_ = ks_ + 64 * QP * 2;
#pragma unroll
        for (int l = 0; l < 8; l++) {
            int id = l * 128 + tid;
            int r = id >> 4, c8 = (id & 15) * 8;
            cpasync16(ks_ + (uint32_t)(r * QP + c8) * 2, Kt + (size_t)r * KVDIM + c8);
            cpasync16(vs_ + (uint32_t)(r * QP + c8) * 2, Vt + (size_t)r * KVDIM + c8);
        }
        CP_COMMIT();
    };

    // load Q tile (64 x 128 halves)
#pragma unroll
    for (int l = 0; l < 8; l++) {
        int id = l * 128 + tid;
        int r = id >> 4, c8 = (id & 15) * 8;
        *(uint4*)(Qs + r * QP + c8) = *(const uint4*)(Qg + (size_t)r * QDIM + c8);
    }

    float m0 = -INFINITY, m1 = -INFINITY, l0 = 0.f, l1 = 0.f;
    float oa[16][4];
#pragma unroll
    for (int ni = 0; ni < 16; ni++)
#pragma unroll
        for (int r = 0; r < 4; r++) oa[ni][r] = 0.f;

    const int kmax = qi + 1;
    load_kv_full(0, 0);

    for (int kb = 0; kb < kmax; kb++) {
        const int s = kb & 1;
        CP_WAIT(0);
        __syncthreads();

        const uint32_t sK = sbKV + (uint32_t)s * (KVST * 2);
        const uint32_t sV = sK + 64 * QP * 2;

        const bool pf = (kb + 1 < kmax);
        const __half *Ktn = nullptr, *Vtn = nullptr;
        uint32_t ksn = 0, vsn = 0;
        if (pf) {
            Ktn = Kg + (size_t)((kb + 1) * 64) * KVDIM;
            Vtn = Vg + (size_t)((kb + 1) * 64) * KVDIM;
            ksn = sbKV + (uint32_t)(s ^ 1) * (KVST * 2);
            vsn = ksn + 64 * QP * 2;
        }

        // ---- S = Q K^T (warp: 16 x 64) ----
        float sa[8][4];
#pragma unroll
        for (int ni = 0; ni < 8; ni++)
#pragma unroll
            for (int r = 0; r < 4; r++) sa[ni][r] = 0.f;

#pragma unroll
        for (int ks = 0; ks < 8; ks++) {
            if (pf) {
                int id = ks * 128 + tid;
                int r = id >> 4, c8 = (id & 15) * 8;
                cpasync16(ksn + (uint32_t)(r * QP + c8) * 2, Ktn + (size_t)r * KVDIM + c8);
                cpasync16(vsn + (uint32_t)(r * QP + c8) * 2, Vtn + (size_t)r * KVDIM + c8);
            }
            const int kc = ks * 16;
            uint32_t a[4], bfr[8][2];
            {
                uint32_t addr = sbQ + (uint32_t)((wq + l7 + lb3 * 8) * QP + kc + lb4 * 8) * 2;
                ldsm4(a[0], a[1], a[2], a[3], addr);
            }
#pragma unroll
            for (int nip = 0; nip < 4; nip++) {
                uint32_t addr = sK + (uint32_t)((nip * 16 + l7 + lb4 * 8) * QP + kc + lb3 * 8) * 2;
                ldsm4(bfr[nip*2][0], bfr[nip*2][1], bfr[nip*2+1][0], bfr[nip*2+1][1], addr);
            }
#pragma unroll
            for (int ni = 0; ni < 8; ni++)
                mma_f16(sa[ni], a, bfr[ni][0], bfr[ni][1]);
        }
        if (pf) CP_COMMIT();

        // ---- causal mask (diagonal tile only: kb == qi) ----
        if (kb == qi) {
            int r0 = qi * 64 + wq + g;
#pragma unroll
            for (int ni = 0; ni < 8; ni++) {
                int c0 = kb * 64 + ni * 8 + 2 * tig;
                if (c0 > r0)         sa[ni][0] = -INFINITY;
                if (c0 + 1 > r0)     sa[ni][1] = -INFINITY;
                if (c0 > r0 + 8)     sa[ni][2] = -INFINITY;
                if (c0 + 1 > r0 + 8) sa[ni][3] = -INFINITY;
            }
        }

        // ---- online softmax; pack P directly into A-fragments ----
        float mx0 = -INFINITY, mx1 = -INFINITY;
#pragma unroll
        for (int ni = 0; ni < 8; ni++) {
            mx0 = fmaxf(mx0, fmaxf(sa[ni][0], sa[ni][1]));
            mx1 = fmaxf(mx1, fmaxf(sa[ni][2], sa[ni][3]));
        }
        mx0 = fmaxf(mx0, __shfl_xor_sync(0xffffffffu, mx0, 1));
        mx0 = fmaxf(mx0, __shfl_xor_sync(0xffffffffu, mx0, 2));
        mx1 = fmaxf(mx1, __shfl_xor_sync(0xffffffffu, mx1, 1));
        mx1 = fmaxf(mx1, __shfl_xor_sync(0xffffffffu, mx1, 2));

        float mm0 = fmaxf(m0, mx0), mm1 = fmaxf(m1, mx1);
        float sub0 = (mm0 == -INFINITY) ? 0.f : mm0;
        float sub1 = (mm1 == -INFINITY) ? 0.f : mm1;
        float al0 = exp2f(m0 - sub0);
        float al1 = exp2f(m1 - sub1);
        m0 = mm0; m1 = mm1;

        uint32_t ph[8][2];   // ph[ni][0]=row g pair, ph[ni][1]=row g+8 pair
        float ls0 = 0.f, ls1 = 0.f;
#pragma unroll
        for (int ni = 0; ni < 8; ni++) {
            float p0 = exp2f(sa[ni][0] - sub0);
            float p1 = exp2f(sa[ni][1] - sub0);
            float p2 = exp2f(sa[ni][2] - sub1);
            float p3 = exp2f(sa[ni][3] - sub1);
            ls0 += p0 + p1; ls1 += p2 + p3;
            ph[ni][0] = pack_h2(p0, p1);
            ph[ni][1] = pack_h2(p2, p3);
        }
        ls0 += __shfl_xor_sync(0xffffffffu, ls0, 1);
        ls0 += __shfl_xor_sync(0xffffffffu, ls0, 2);
        ls1 += __shfl_xor_sync(0xffffffffu, ls1, 1);
        ls1 += __shfl_xor_sync(0xffffffffu, ls1, 2);
        l0 = l0 * al0 + ls0;
        l1 = l1 * al1 + ls1;

#pragma unroll
        for (int ni = 0; ni < 16; ni++) {
            oa[ni][0] *= al0; oa[ni][1] *= al0;
            oa[ni][2] *= al1; oa[ni][3] *= al1;
        }

        // ---- O += P @ V  (A = register P fragments; B = V via ldmatrix.trans) ----
#pragma unroll
        for (int ks = 0; ks < 4; ks++) {
            const int kc = ks * 16;
            uint32_t a[4];
            a[0] = ph[2 * ks][0];
            a[1] = ph[2 * ks][1];
            a[2] = ph[2 * ks + 1][0];
            a[3] = ph[2 * ks + 1][1];
#pragma unroll
            for (int nip = 0; nip < 8; nip++) {
                uint32_t bf0, bf1, bf2, bf3;
                uint32_t addr = sV + (uint32_t)((kc + l7 + lb3 * 8) * QP + nip * 16 + lb4 * 8) * 2;
                ldsm4t(bf0, bf1, bf2, bf3, addr);
                mma_f16(oa[nip*2],     a, bf0, bf1);
                mma_f16(oa[nip*2 + 1], a, bf2, bf3);
            }
        }
    }

    // ---- epilogue ----
    float inv0 = 1.0f / l0, inv1 = 1.0f / l1;
    __half* Og = O + (size_t)(b * SEQ + qi * 64 + wq) * QDIM + h * HD;
#pragma unroll
    for (int ni = 0; ni < 16; ni++) {
        int col = ni * 8 + 2 * tig;
        *(__half2*)(Og + (size_t)g * QDIM + col) =
            __floats2half2_rn(oa[ni][0] * inv0, oa[ni][1] * inv0);
        *(__half2*)(Og + (size_t)(g + 8) * QDIM + col) =
            __floats2half2_rn(oa[ni][2] * inv1, oa[ni][3] * inv1);
    }
}

// ---------------------------------------------------------------------------
// Launch: conv_all -> grouped QKV gemm -> flash -> O gemm
// ---------------------------------------------------------------------------
extern "C" void kernel_launch(void* const* d_in, const int* in_sizes, int n_in,
                              void* d_out, int out_size)
{
    const float* query = (const float*)d_in[0];
    const float* key   = (const float*)d_in[1];
    const float* value = (const float*)d_in[2];
    const float* Wq = (const float*)d_in[5];
    const float* Wk = (const float*)d_in[6];
    const float* Wv = (const float*)d_in[7];
    const float* Wo = (const float*)d_in[8];
    float* out = (float*)d_out;

    __half *pQa, *pKa, *pVa, *pQh, *pKh, *pVh, *pAOh, *pWqh, *pWkh, *pWvh, *pWoh;
    cudaGetSymbolAddress((void**)&pQa,  g_Qa);
    cudaGetSymbolAddress((void**)&pKa,  g_Ka);
    cudaGetSymbolAddress((void**)&pVa,  g_Va);
    cudaGetSymbolAddress((void**)&pQh,  g_Qh);
    cudaGetSymbolAddress((void**)&pKh,  g_Kh);
    cudaGetSymbolAddress((void**)&pVh,  g_Vh);
    cudaGetSymbolAddress((void**)&pAOh, g_AOh);
    cudaGetSymbolAddress((void**)&pWqh, g_Wqh);
    cudaGetSymbolAddress((void**)&pWkh, g_Wkh);
    cudaGetSymbolAddress((void**)&pWvh, g_Wvh);
    cudaGetSymbolAddress((void**)&pWoh, g_Woh);

    cudaFuncSetAttribute(gemm_grp, cudaFuncAttributeMaxDynamicSharedMemorySize, GN_SMEM);
    cudaFuncSetAttribute(flash7,   cudaFuncAttributeMaxDynamicSharedMemorySize, FL7_SMEM);

    // one-shot conversion of everything to half
    ConvDesc cd;
    cd.src[0] = query; cd.dst[0] = pQa;  cd.nblk[0] = (MROWS * EMB) / 1024;
    cd.src[1] = key;   cd.dst[1] = pKa;  cd.nblk[1] = (MROWS * EMB) / 1024;
    cd.src[2] = value; cd.dst[2] = pVa;  cd.nblk[2] = (MROWS * EMB) / 1024;
    cd.src[3] = Wq;    cd.dst[3] = pWqh; cd.nblk[3] = (EMB * QDIM) / 1024;
    cd.src[4] = Wk;    cd.dst[4] = pWkh; cd.nblk[4] = (EMB * KVDIM) / 1024;
    cd.src[5] = Wv;    cd.dst[5] = pWvh; cd.nblk[5] = (EMB * KVDIM) / 1024;
    cd.src[6] = Wo;    cd.dst[6] = pWoh; cd.nblk[6] = (QDIM * EMB) / 1024;
    int total_blk = cd.nblk[0] + cd.nblk[1] + cd.nblk[2] + cd.nblk[3]
                  + cd.nblk[4] + cd.nblk[5] + cd.nblk[6];
    conv_all<<<total_blk, 256>>>(cd);

    // grouped Q+K+V projections (one launch; rope fused for Q,K)
    GroupArgs gq;
    gq.A[0] = pQa; gq.B[0] = pWqh; gq.C[0] = pQh; gq.N[0] = QDIM;  gq.mode[0] = 2; gq.rsc[0] = QSCALE; gq.xend[0] = 32;
    gq.A[1] = pKa; gq.B[1] = pWkh; gq.C[1] = pKh; gq.N[1] = KVDIM; gq.mode[1] = 2; gq.rsc[1] = 1.0f;   gq.xend[1] = 40;
    gq.A[2] = pVa; gq.B[2] = pWvh; gq.C[2] = pVh; gq.N[2] = KVDIM; gq.mode[2] = 1; gq.rsc[2] = 0.0f;   gq.xend[2] = 48;
    gq.nseg = 3;
    gemm_grp<<<dim3(48, MROWS / 128), 256, GN_SMEM>>>(gq, EMB);

    // attention (register-resident P)
    flash7<<<dim3(SEQ / 64, NH, BSZ), 128, FL7_SMEM>>>(pQh, pKh, pVh, pAOh);

    // output projection
    GroupArgs go;
    go.A[0] = pAOh; go.B[0] = pWoh; go.C[0] = out; go.N[0] = EMB; go.mode[0] = 0; go.rsc[0] = 0.0f; go.xend[0] = 32;
    go.nseg = 1;
    gemm_grp<<<dim3(32, MROWS / 128), 256, GN_SMEM>>>(go, QDIM);
}

// round 14
// speedup vs baseline: 1.1214x; 1.0174x over previous
#include <cuda_runtime.h>
#include <cuda_fp16.h>
#include <math.h>
#include <stdint.h>

#define BSZ   2
#define SEQ   2048
#define EMB   4096
#define NH    32
#define NKVH  8
#define HD    128
#define GROUPS (NH / NKVH)
#define MROWS (BSZ * SEQ)          // 4096
#define QDIM  (NH * HD)            // 4096
#define KVDIM (NKVH * HD)          // 1024

// log2(e)/sqrt(128), folded into Q so softmax uses bare exp2
#define QSCALE 0.12751744f

// Scratch (device globals)
__device__ __half g_Qa [(size_t)MROWS * EMB];    // half activations
__device__ __half g_Ka [(size_t)MROWS * EMB];
__device__ __half g_Va [(size_t)MROWS * EMB];
__device__ __half g_Qh [(size_t)MROWS * QDIM];   // post-rope half
__device__ __half g_Kh [(size_t)MROWS * KVDIM];
__device__ __half g_Vh [(size_t)MROWS * KVDIM];
__device__ __half g_AOh[(size_t)MROWS * QDIM];
__device__ __half g_Wqh[(size_t)EMB * QDIM];     // [K][N] half (no transpose)
__device__ __half g_Wkh[(size_t)EMB * KVDIM];
__device__ __half g_Wvh[(size_t)EMB * KVDIM];
__device__ __half g_Woh[(size_t)QDIM * EMB];

// ---------------------------------------------------------------------------
// Helpers
// ---------------------------------------------------------------------------
__device__ __forceinline__ uint32_t smem_u32(const void* p) {
    uint32_t a;
    asm("{ .reg .u64 t; cvta.to.shared.u64 t, %1; cvt.u32.u64 %0, t; }" : "=r"(a) : "l"(p));
    return a;
}
__device__ __forceinline__ void cpasync16(uint32_t dst, const void* src) {
    asm volatile("cp.async.cg.shared.global [%0], [%1], 16;" :: "r"(dst), "l"(src) : "memory");
}
#define CP_COMMIT() asm volatile("cp.async.commit_group;" ::: "memory")
#define CP_WAIT(n)  asm volatile("cp.async.wait_group %0;" :: "n"(n) : "memory")

__device__ __forceinline__ void mma_f16(float* d, const uint32_t* a, uint32_t b0, uint32_t b1) {
    asm volatile("mma.sync.aligned.m16n8k16.row.col.f32.f16.f16.f32 "
        "{%0,%1,%2,%3}, {%4,%5,%6,%7}, {%8,%9}, {%0,%1,%2,%3};"
        : "+f"(d[0]), "+f"(d[1]), "+f"(d[2]), "+f"(d[3])
        : "r"(a[0]), "r"(a[1]), "r"(a[2]), "r"(a[3]), "r"(b0), "r"(b1));
}
__device__ __forceinline__ void ldsm4(uint32_t& r0, uint32_t& r1, uint32_t& r2, uint32_t& r3,
                                      uint32_t addr) {
    asm volatile("ldmatrix.sync.aligned.m8n8.x4.shared.b16 {%0,%1,%2,%3}, [%4];"
        : "=r"(r0), "=r"(r1), "=r"(r2), "=r"(r3) : "r"(addr));
}
__device__ __forceinline__ void ldsm4t(uint32_t& r0, uint32_t& r1, uint32_t& r2, uint32_t& r3,
                                       uint32_t addr) {
    asm volatile("ldmatrix.sync.aligned.m8n8.x4.trans.shared.b16 {%0,%1,%2,%3}, [%4];"
        : "=r"(r0), "=r"(r1), "=r"(r2), "=r"(r3) : "r"(addr));
}
__device__ __forceinline__ uint32_t pack_h2(float a, float b) {
    __half2 h = __floats2half2_rn(a, b);
    return *(uint32_t*)&h;
}

// ---------------------------------------------------------------------------
// One-shot fp32->half conversion of all 7 tensors. 2048 elems per block
// (8 per thread). FIXED base index: block covers [b*2048, (b+1)*2048).
// ---------------------------------------------------------------------------
struct ConvDesc {
    const float* src[7];
    __half*      dst[7];
    int          nblk[7];
};

__global__ void conv_all(ConvDesc cd)
{
    int b = blockIdx.x;
    int seg = 0;
#pragma unroll
    for (int i = 0; i < 7; i++) {
        if (b >= cd.nblk[i]) { b -= cd.nblk[i]; seg = i + 1; }
        else break;
    }
    const float* src = cd.src[seg];
    __half* dst = cd.dst[seg];
    size_t i = (size_t)b * 2048 + (size_t)threadIdx.x * 4;
    float4 v0 = *(const float4*)(src + i);
    float4 v1 = *(const float4*)(src + i + 1024);
    *(__half2*)(dst + i)     = __floats2half2_rn(v0.x, v0.y);
    *(__half2*)(dst + i + 2) = __floats2half2_rn(v0.z, v0.w);
    *(__half2*)(dst + i + 1024)     = __floats2half2_rn(v1.x, v1.y);
    *(__half2*)(dst + i + 1024 + 2) = __floats2half2_rn(v1.z, v1.w);
}

// ---------------------------------------------------------------------------
// Grouped fp16 tensor-core GEMM (unchanged from R11/12).
// ---------------------------------------------------------------------------
#define HP  72
#define BPN 136
#define SPN 132
#define A_ST (128 * HP)
#define B_ST (64 * BPN)
#define STG_B ((A_ST + B_ST) * 2)
#define GN_SMEM (3 * STG_B)

struct GroupArgs {
    const __half* A[3];
    const __half* B[3];
    void*         C[3];
    int           N[3];
    int           mode[3];
    float         rsc[3];
    int           xend[3];
    int           nseg;
};

__global__ __launch_bounds__(256, 2) void gemm_grp(GroupArgs ga, int K)
{
    extern __shared__ __half smh[];
    const uint32_t sb = smem_u32(smh);

    int bx = blockIdx.x;
    int seg = 0;
#pragma unroll
    for (int i = 0; i < 2; i++)
        if (i + 1 < ga.nseg && bx >= ga.xend[i]) seg = i + 1;
    const int xbase = (seg == 0) ? 0 : ga.xend[seg - 1];
    const __half* A = ga.A[seg];
    const __half* B = ga.B[seg];
    void* Cv        = ga.C[seg];
    const int N     = ga.N[seg];
    const int mode  = ga.mode[seg];
    const float rsc = ga.rsc[seg];

    const int tid  = threadIdx.x;
    const int wid  = tid >> 5, lane = tid & 31;
    const int g    = lane >> 2, tig = lane & 3;
    const int wm   = (wid >> 2) * 64;
    const int wn   = (wid & 3) * 32;
    const int bm   = blockIdx.y * 128, bn = (bx - xbase) * 128;

    auto load_tile = [&](int c, int s) {
        const __half* Ab = A + (size_t)bm * K + c * 64;
        const __half* Bb = B + (size_t)(c * 64) * N + bn;
        uint32_t sa  = sb + (uint32_t)s * STG_B;
        uint32_t sbb = sa + A_ST * 2;
#pragma unroll
        for (int l = 0; l < 4; l++) {
            int id = l * 256 + tid;
            int ra = id >> 3, ca = (id & 7) * 8;
            cpasync16(sa + (uint32_t)(ra * HP + ca) * 2, Ab + (size_t)ra * K + ca);
            int rb = id >> 4, cb = (id & 15) * 8;
            cpasync16(sbb + (uint32_t)(rb * BPN + cb) * 2, Bb + (size_t)rb * N + cb);
        }
        CP_COMMIT();
    };

    const int l7  = lane & 7;
    const int lb3 = (lane >> 3) & 1;
    const int lb4 = lane >> 4;

    float acc[4][4][4];
#pragma unroll
    for (int mi = 0; mi < 4; mi++)
#pragma unroll
        for (int ni = 0; ni < 4; ni++)
#pragma unroll
            for (int r = 0; r < 4; r++) acc[mi][ni][r] = 0.0f;

    const int iters = K / 64;
    load_tile(0, 0);
    load_tile(1, 1);

    uint32_t sA = 0, sBb = 0;
    uint32_t af[2][4][4], bf[2][2][4];

    auto load_frag = [&](int ks, int pb) {
        const int kb = ks * 16;
#pragma unroll
        for (int mi = 0; mi < 4; mi++) {
            uint32_t addr = sA + (uint32_t)((wm + mi * 16 + l7 + lb3 * 8) * HP
                                            + kb + lb4 * 8) * 2;
            ldsm4(af[pb][mi][0], af[pb][mi][1], af[pb][mi][2], af[pb][mi][3], addr);
        }
#pragma unroll
        for (int nj = 0; nj < 2; nj++) {
            uint32_t addr = sBb + (uint32_t)((kb + l7 + lb3 * 8) * BPN
                                             + wn + nj * 16 + lb4 * 8) * 2;
            ldsm4t(bf[pb][nj][0], bf[pb][nj][1], bf[pb][nj][2], bf[pb][nj][3], addr);
        }
    };

    for (int c = 0; c < iters; c++) {
        const int s = c % 3;
        if (c + 1 < iters) { CP_WAIT(1); } else { CP_WAIT(0); }
        __syncthreads();

        sA  = sb + (uint32_t)s * STG_B;
        sBb = sA + A_ST * 2;

        const bool pf = (c + 2 < iters);
        const __half* Abn = nullptr;
        const __half* Bbn = nullptr;
        uint32_t san = 0, sbn = 0;
        if (pf) {
            const int cn = c + 2, sn = cn % 3;
            Abn = A + (size_t)bm * K + cn * 64;
            Bbn = B + (size_t)(cn * 64) * N + bn;
            san = sb + (uint32_t)sn * STG_B;
            sbn = san + A_ST * 2;
        }

        load_frag(0, 0);
#pragma unroll
        for (int ks = 0; ks < 4; ks++) {
            if (pf) {
                int id = ks * 256 + tid;
                int ra = id >> 3, ca = (id & 7) * 8;
                cpasync16(san + (uint32_t)(ra * HP + ca) * 2, Abn + (size_t)ra * K + ca);
                int rb = id >> 4, cb = (id & 15) * 8;
                cpasync16(sbn + (uint32_t)(rb * BPN + cb) * 2, Bbn + (size_t)rb * N + cb);
            }
            const int cur = ks & 1;
            if (ks < 3) load_frag(ks + 1, cur ^ 1);
#pragma unroll
            for (int mi = 0; mi < 4; mi++)
#pragma unroll
                for (int nj = 0; nj < 2; nj++) {
                    mma_f16(acc[mi][nj * 2],     af[cur][mi], bf[cur][nj][0], bf[cur][nj][1]);
                    mma_f16(acc[mi][nj * 2 + 1], af[cur][mi], bf[cur][nj][2], bf[cur][nj][3]);
                }
        }
        if (pf) CP_COMMIT();
    }

    if (mode == 2) {
        __syncthreads();
        float* S = (float*)smh;
#pragma unroll
        for (int mi = 0; mi < 4; mi++) {
            int r0 = wm + mi * 16 + g;
#pragma unroll
            for (int ni = 0; ni < 4; ni++) {
                int cc = wn + ni * 8 + tig * 2;
                *(float2*)(S + (size_t)r0 * SPN + cc)       = make_float2(acc[mi][ni][0], acc[mi][ni][1]);
                *(float2*)(S + (size_t)(r0 + 8) * SPN + cc) = make_float2(acc[mi][ni][2], acc[mi][ni][3]);
            }
        }
        __syncthreads();
        __half* C = (__half*)Cv;
        const float LG = 0.2076205059304640f;   // 2*log2(10000)/128
#pragma unroll 4
        for (int l = 0; l < 32; l++) {
            int idx = l * 256 + tid;
            int r  = idx >> 6;
            int d  = idx & 63;
            float x1 = S[(size_t)r * SPN + d];
            float x2 = S[(size_t)r * SPN + d + 64];
            int grow = bm + r;
            float pos = (float)(grow & (SEQ - 1));
            float invf = exp2f(-LG * (float)d);
            float ang = pos * invf;
            float sn, cs;
            sincosf(ang, &sn, &cs);
            size_t o = (size_t)grow * N + bn + d;
            C[o]      = __float2half((x1 * cs - x2 * sn) * rsc);
            C[o + 64] = __float2half((x2 * cs + x1 * sn) * rsc);
        }
    } else if (mode == 1) {
        __half* C = (__half*)Cv;
#pragma unroll
        for (int mi = 0; mi < 4; mi++) {
            int row0 = bm + wm + mi * 16 + g;
#pragma unroll
            for (int ni = 0; ni < 4; ni++) {
                int col = bn + wn + ni * 8 + tig * 2;
                *(__half2*)(C + (size_t)row0 * N + col) =
                    __floats2half2_rn(acc[mi][ni][0], acc[mi][ni][1]);
                *(__half2*)(C + (size_t)(row0 + 8) * N + col) =
                    __floats2half2_rn(acc[mi][ni][2], acc[mi][ni][3]);
            }
        }
    } else {
        float* C = (float*)Cv;
#pragma unroll
        for (int mi = 0; mi < 4; mi++) {
            int row0 = bm + wm + mi * 16 + g;
#pragma unroll
            for (int ni = 0; ni < 4; ni++) {
                int col = bn + wn + ni * 8 + tig * 2;
                *(float2*)(C + (size_t)row0 * N + col)       = make_float2(acc[mi][ni][0], acc[mi][ni][1]);
                *(float2*)(C + (size_t)(row0 + 8) * N + col) = make_float2(acc[mi][ni][2], acc[mi][ni][3]);
            }
        }
    }
}

// ---------------------------------------------------------------------------
// Flash attention v8: register-resident P, deferred l reduction.
// 128 threads, Q tile 64, K tile 64, 2-stage de-bunched cp.async, 2 CTAs/SM.
// ---------------------------------------------------------------------------
#define QP 136
#define KVST (2 * 64 * QP)                      // halves per stage (K+V)
#define FL8_SMEM ((64*QP + 2*KVST) * 2)         // 87040 bytes

__global__ __launch_bounds__(128, 2) void flash8(const __half* __restrict__ Q,
                                                 const __half* __restrict__ K,
                                                 const __half* __restrict__ V,
                                                 __half* __restrict__ O)
{
    extern __shared__ __half hs[];
    __half* Qs  = hs;                        // [64][136]
    __half* KV0 = Qs + 64 * QP;              // 2 stages: K[64][136] then V[64][136]

    const uint32_t sbQ  = smem_u32(Qs);
    const uint32_t sbKV = smem_u32(KV0);

    const int qi  = (int)gridDim.x - 1 - (int)blockIdx.x;   // big tiles first
    const int h   = blockIdx.y;
    const int b   = blockIdx.z;
    const int kvh = h / GROUPS;
    const int tid = threadIdx.x;
    const int wid = tid >> 5, lane = tid & 31;
    const int g   = lane >> 2, tig = lane & 3;
    const int wq  = wid * 16;                 // 0..48
    const int l7  = lane & 7;
    const int lb3 = (lane >> 3) & 1;
    const int lb4 = lane >> 4;

    const __half* Qg = Q + (size_t)(b * SEQ + qi * 64) * QDIM + h * HD;
    const __half* Kg = K + (size_t)(b * SEQ) * KVDIM + kvh * HD;
    const __half* Vg = V + (size_t)(b * SEQ) * KVDIM + kvh * HD;

    auto load_kv_full = [&](int kb, int s) {
        const __half* Kt = Kg + (size_t)(kb * 64) * KVDIM;
        const __half* Vt = Vg + (size_t)(kb * 64) * KVDIM;
        uint32_t ks_ = sbKV + (uint32_t)s * (KVST * 2);
        uint32_t vs_ = ks_ + 64 * QP * 2;
#pragma unroll
        for (int l = 0; l < 8; l++) {
            int id = l * 128 + tid;
            int r = id >> 4, c8 = (id & 15) * 8;
            cpasync16(ks_ + (uint32_t)(r * QP + c8) * 2, Kt + (size_t)r * KVDIM + c8);
            cpasync16(vs_ + (uint32_t)(r * QP + c8) * 2, Vt + (size_t)r * KVDIM + c8);
        }
        CP_COMMIT();
    };

    // load Q tile (64 x 128 halves)
#pragma unroll
    for (int l = 0; l < 8; l++) {
        int id = l * 128 + tid;
        int r = id >> 4, c8 = (id & 15) * 8;
        *(uint4*)(Qs + r * QP + c8) = *(const uint4*)(Qg + (size_t)r * QDIM + c8);
    }

    float m0 = -INFINITY, m1 = -INFINITY;
    float l0p = 0.f, l1p = 0.f;              // lane-local partial row sums
    float oa[16][4];
#pragma unroll
    for (int ni = 0; ni < 16; ni++)
#pragma unroll
        for (int r = 0; r < 4; r++) oa[ni][r] = 0.f;

    const int kmax = qi + 1;
    load_kv_full(0, 0);

    for (int kb = 0; kb < kmax; kb++) {
        const int s = kb & 1;
        CP_WAIT(0);
        __syncthreads();

        const uint32_t sK = sbKV + (uint32_t)s * (KVST * 2);
        const uint32_t sV = sK + 64 * QP * 2;

        const bool pf = (kb + 1 < kmax);
        const __half* Ktn = nullptr;
        const __half* Vtn = nullptr;
        uint32_t ksn = 0, vsn = 0;
        if (pf) {
            Ktn = Kg + (size_t)((kb + 1) * 64) * KVDIM;
            Vtn = Vg + (size_t)((kb + 1) * 64) * KVDIM;
            ksn = sbKV + (uint32_t)(s ^ 1) * (KVST * 2);
            vsn = ksn + 64 * QP * 2;
        }

        // ---- S = Q K^T (warp: 16 x 64) ----
        float sa[8][4];
#pragma unroll
        for (int ni = 0; ni < 8; ni++)
#pragma unroll
            for (int r = 0; r < 4; r++) sa[ni][r] = 0.f;

#pragma unroll
        for (int ks = 0; ks < 8; ks++) {
            if (pf) {
                int id = ks * 128 + tid;
                int r = id >> 4, c8 = (id & 15) * 8;
                cpasync16(ksn + (uint32_t)(r * QP + c8) * 2, Ktn + (size_t)r * KVDIM + c8);
                cpasync16(vsn + (uint32_t)(r * QP + c8) * 2, Vtn + (size_t)r * KVDIM + c8);
            }
            const int kc = ks * 16;
            uint32_t a[4], bfr[8][2];
            {
                uint32_t addr = sbQ + (uint32_t)((wq + l7 + lb3 * 8) * QP + kc + lb4 * 8) * 2;
                ldsm4(a[0], a[1], a[2], a[3], addr);
            }
#pragma unroll
            for (int nip = 0; nip < 4; nip++) {
                uint32_t addr = sK + (uint32_t)((nip * 16 + l7 + lb4 * 8) * QP + kc + lb3 * 8) * 2;
                ldsm4(bfr[nip*2][0], bfr[nip*2][1], bfr[nip*2+1][0], bfr[nip*2+1][1], addr);
            }
#pragma unroll
            for (int ni = 0; ni < 8; ni++)
                mma_f16(sa[ni], a, bfr[ni][0], bfr[ni][1]);
        }
        if (pf) CP_COMMIT();

        // ---- causal mask (diagonal tile only: kb == qi) ----
        if (kb == qi) {
            int r0 = qi * 64 + wq + g;
#pragma unroll
            for (int ni = 0; ni < 8; ni++) {
                int c0 = kb * 64 + ni * 8 + 2 * tig;
                if (c0 > r0)         sa[ni][0] = -INFINITY;
                if (c0 + 1 > r0)     sa[ni][1] = -INFINITY;
                if (c0 > r0 + 8)     sa[ni][2] = -INFINITY;
                if (c0 + 1 > r0 + 8) sa[ni][3] = -INFINITY;
            }
        }

        // ---- online softmax (max reduce only; l kept lane-local) ----
        float mx0 = -INFINITY, mx1 = -INFINITY;
#pragma unroll
        for (int ni = 0; ni < 8; ni++) {
            mx0 = fmaxf(mx0, fmaxf(sa[ni][0], sa[ni][1]));
            mx1 = fmaxf(mx1, fmaxf(sa[ni][2], sa[ni][3]));
        }
        mx0 = fmaxf(mx0, __shfl_xor_sync(0xffffffffu, mx0, 1));
        mx0 = fmaxf(mx0, __shfl_xor_sync(0xffffffffu, mx0, 2));
        mx1 = fmaxf(mx1, __shfl_xor_sync(0xffffffffu, mx1, 1));
        mx1 = fmaxf(mx1, __shfl_xor_sync(0xffffffffu, mx1, 2));

        float mm0 = fmaxf(m0, mx0), mm1 = fmaxf(m1, mx1);
        float sub0 = (mm0 == -INFINITY) ? 0.f : mm0;
        float sub1 = (mm1 == -INFINITY) ? 0.f : mm1;
        float al0 = exp2f(m0 - sub0);
        float al1 = exp2f(m1 - sub1);
        m0 = mm0; m1 = mm1;

        uint32_t ph[8][2];
        float ls0 = 0.f, ls1 = 0.f;
#pragma unroll
        for (int ni = 0; ni < 8; ni++) {
            float p0 = exp2f(sa[ni][0] - sub0);
            float p1 = exp2f(sa[ni][1] - sub0);
            float p2 = exp2f(sa[ni][2] - sub1);
            float p3 = exp2f(sa[ni][3] - sub1);
            ls0 += p0 + p1; ls1 += p2 + p3;
            ph[ni][0] = pack_h2(p0, p1);
            ph[ni][1] = pack_h2(p2, p3);
        }
        l0p = l0p * al0 + ls0;    // lane-local partial; quad-reduced at end
        l1p = l1p * al1 + ls1;

#pragma unroll
        for (int ni = 0; ni < 16; ni++) {
            oa[ni][0] *= al0; oa[ni][1] *= al0;
            oa[ni][2] *= al1; oa[ni][3] *= al1;
        }

        // ---- O += P @ V  (A = register P; B = V via ldmatrix.trans) ----
#pragma unroll
        for (int ks = 0; ks < 4; ks++) {
            const int kc = ks * 16;
            uint32_t a[4];
            a[0] = ph[2 * ks][0];
            a[1] = ph[2 * ks][1];
            a[2] = ph[2 * ks + 1][0];
            a[3] = ph[2 * ks + 1][1];
#pragma unroll
            for (int nip = 0; nip < 8; nip++) {
                uint32_t bf0, bf1, bf2, bf3;
                uint32_t addr = sV + (uint32_t)((kc + l7 + lb3 * 8) * QP + nip * 16 + lb4 * 8) * 2;
                ldsm4t(bf0, bf1, bf2, bf3, addr);
                mma_f16(oa[nip*2],     a, bf0, bf1);
                mma_f16(oa[nip*2 + 1], a, bf2, bf3);
            }
        }
    }

    // ---- final l reduction across the quad, then epilogue ----
    float l0 = l0p, l1 = l1p;
    l0 += __shfl_xor_sync(0xffffffffu, l0, 1);
    l0 += __shfl_xor_sync(0xffffffffu, l0, 2);
    l1 += __shfl_xor_sync(0xffffffffu, l1, 1);
    l1 += __shfl_xor_sync(0xffffffffu, l1, 2);

    float inv0 = 1.0f / l0, inv1 = 1.0f / l1;
    __half* Og = O + (size_t)(b * SEQ + qi * 64 + wq) * QDIM + h * HD;
#pragma unroll
    for (int ni = 0; ni < 16; ni++) {
        int col = ni * 8 + 2 * tig;
        *(__half2*)(Og + (size_t)g * QDIM + col) =
            __floats2half2_rn(oa[ni][0] * inv0, oa[ni][1] * inv0);
        *(__half2*)(Og + (size_t)(g + 8) * QDIM + col) =
            __floats2half2_rn(oa[ni][2] * inv1, oa[ni][3] * inv1);
    }
}

// ---------------------------------------------------------------------------
// Launch: conv_all -> grouped QKV gemm -> flash -> O gemm
// ---------------------------------------------------------------------------
extern "C" void kernel_launch(void* const* d_in, const int* in_sizes, int n_in,
                              void* d_out, int out_size)
{
    const float* query = (const float*)d_in[0];
    const float* key   = (const float*)d_in[1];
    const float* value = (const float*)d_in[2];
    const float* Wq = (const float*)d_in[5];
    const float* Wk = (const float*)d_in[6];
    const float* Wv = (const float*)d_in[7];
    const float* Wo = (const float*)d_in[8];
    float* out = (float*)d_out;

    __half *pQa, *pKa, *pVa, *pQh, *pKh, *pVh, *pAOh, *pWqh, *pWkh, *pWvh, *pWoh;
    cudaGetSymbolAddress((void**)&pQa,  g_Qa);
    cudaGetSymbolAddress((void**)&pKa,  g_Ka);
    cudaGetSymbolAddress((void**)&pVa,  g_Va);
    cudaGetSymbolAddress((void**)&pQh,  g_Qh);
    cudaGetSymbolAddress((void**)&pKh,  g_Kh);
    cudaGetSymbolAddress((void**)&pVh,  g_Vh);
    cudaGetSymbolAddress((void**)&pAOh, g_AOh);
    cudaGetSymbolAddress((void**)&pWqh, g_Wqh);
    cudaGetSymbolAddress((void**)&pWkh, g_Wkh);
    cudaGetSymbolAddress((void**)&pWvh, g_Wvh);
    cudaGetSymbolAddress((void**)&pWoh, g_Woh);

    cudaFuncSetAttribute(gemm_grp, cudaFuncAttributeMaxDynamicSharedMemorySize, GN_SMEM);
    cudaFuncSetAttribute(flash8,   cudaFuncAttributeMaxDynamicSharedMemorySize, FL8_SMEM);

    // one-shot conversion of everything to half (2048 elems per block)
    ConvDesc cd;
    cd.src[0] = query; cd.dst[0] = pQa;  cd.nblk[0] = (MROWS * EMB) / 2048;
    cd.src[1] = key;   cd.dst[1] = pKa;  cd.nblk[1] = (MROWS * EMB) / 2048;
    cd.src[2] = value; cd.dst[2] = pVa;  cd.nblk[2] = (MROWS * EMB) / 2048;
    cd.src[3] = Wq;    cd.dst[3] = pWqh; cd.nblk[3] = (EMB * QDIM) / 2048;
    cd.src[4] = Wk;    cd.dst[4] = pWkh; cd.nblk[4] = (EMB * KVDIM) / 2048;
    cd.src[5] = Wv;    cd.dst[5] = pWvh; cd.nblk[5] = (EMB * KVDIM) / 2048;
    cd.src[6] = Wo;    cd.dst[6] = pWoh; cd.nblk[6] = (QDIM * EMB) / 2048;
    int total_blk = cd.nblk[0] + cd.nblk[1] + cd.nblk[2] + cd.nblk[3]
                  + cd.nblk[4] + cd.nblk[5] + cd.nblk[6];
    conv_all<<<total_blk, 256>>>(cd);

    // grouped Q+K+V projections (one launch; rope fused for Q,K)
    GroupArgs gq;
    gq.A[0] = pQa; gq.B[0] = pWqh; gq.C[0] = pQh; gq.N[0] = QDIM;  gq.mode[0] = 2; gq.rsc[0] = QSCALE; gq.xend[0] = 32;
    gq.A[1] = pKa; gq.B[1] = pWkh; gq.C[1] = pKh; gq.N[1] = KVDIM; gq.mode[1] = 2; gq.rsc[1] = 1.0f;   gq.xend[1] = 40;
    gq.A[2] = pVa; gq.B[2] = pWvh; gq.C[2] = pVh; gq.N[2] = KVDIM; gq.mode[2] = 1; gq.rsc[2] = 0.0f;   gq.xend[2] = 48;
    gq.nseg = 3;
    gemm_grp<<<dim3(48, MROWS / 128), 256, GN_SMEM>>>(gq, EMB);

    // attention
    flash8<<<dim3(SEQ / 64, NH, BSZ), 128, FL8_SMEM>>>(pQh, pKh, pVh, pAOh);

    // output projection
    GroupArgs go;
    go.A[0] = pAOh; go.B[0] = pWoh; go.C[0] = out; go.N[0] = EMB; go.mode[0] = 0; go.rsc[0] = 0.0f; go.xend[0] = 32;
    go.nseg = 1;
    gemm_grp<<<dim3(32, MROWS / 128), 256, GN_SMEM>>>(go, QDIM);
}

// round 15
// speedup vs baseline: 1.1229x; 1.0013x over previous
#include <cuda_runtime.h>
#include <cuda_fp16.h>
#include <math.h>
#include <stdint.h>

#define BSZ   2
#define SEQ   2048
#define EMB   4096
#define NH    32
#define NKVH  8
#define HD    128
#define GROUPS (NH / NKVH)
#define MROWS (BSZ * SEQ)          // 4096
#define QDIM  (NH * HD)            // 4096
#define KVDIM (NKVH * HD)          // 1024

// log2(e)/sqrt(128), folded into Q so softmax uses bare exp2
#define QSCALE 0.12751744f

// Scratch (device globals)
__device__ __half g_Qa [(size_t)MROWS * EMB];    // half activations
__device__ __half g_Ka [(size_t)MROWS * EMB];
__device__ __half g_Va [(size_t)MROWS * EMB];
__device__ __half g_Qh [(size_t)MROWS * QDIM];   // post-rope half
__device__ __half g_Kh [(size_t)MROWS * KVDIM];
__device__ __half g_Vh [(size_t)MROWS * KVDIM];
__device__ __half g_AOh[(size_t)MROWS * QDIM];
__device__ __half g_Wqh[(size_t)EMB * QDIM];     // [K][N] half (no transpose)
__device__ __half g_Wkh[(size_t)EMB * KVDIM];
__device__ __half g_Wvh[(size_t)EMB * KVDIM];
__device__ __half g_Woh[(size_t)QDIM * EMB];
__device__ float2 g_rope[(size_t)SEQ * 64];      // (cos, sin) per (pos, d)

// ---------------------------------------------------------------------------
// Helpers
// ---------------------------------------------------------------------------
__device__ __forceinline__ uint32_t smem_u32(const void* p) {
    uint32_t a;
    asm("{ .reg .u64 t; cvta.to.shared.u64 t, %1; cvt.u32.u64 %0, t; }" : "=r"(a) : "l"(p));
    return a;
}
__device__ __forceinline__ void cpasync16(uint32_t dst, const void* src) {
    asm volatile("cp.async.cg.shared.global [%0], [%1], 16;" :: "r"(dst), "l"(src) : "memory");
}
#define CP_COMMIT() asm volatile("cp.async.commit_group;" ::: "memory")
#define CP_WAIT(n)  asm volatile("cp.async.wait_group %0;" :: "n"(n) : "memory")

__device__ __forceinline__ void mma_f16(float* d, const uint32_t* a, uint32_t b0, uint32_t b1) {
    asm volatile("mma.sync.aligned.m16n8k16.row.col.f32.f16.f16.f32 "
        "{%0,%1,%2,%3}, {%4,%5,%6,%7}, {%8,%9}, {%0,%1,%2,%3};"
        : "+f"(d[0]), "+f"(d[1]), "+f"(d[2]), "+f"(d[3])
        : "r"(a[0]), "r"(a[1]), "r"(a[2]), "r"(a[3]), "r"(b0), "r"(b1));
}
__device__ __forceinline__ void ldsm4(uint32_t& r0, uint32_t& r1, uint32_t& r2, uint32_t& r3,
                                      uint32_t addr) {
    asm volatile("ldmatrix.sync.aligned.m8n8.x4.shared.b16 {%0,%1,%2,%3}, [%4];"
        : "=r"(r0), "=r"(r1), "=r"(r2), "=r"(r3) : "r"(addr));
}
__device__ __forceinline__ void ldsm4t(uint32_t& r0, uint32_t& r1, uint32_t& r2, uint32_t& r3,
                                       uint32_t addr) {
    asm volatile("ldmatrix.sync.aligned.m8n8.x4.trans.shared.b16 {%0,%1,%2,%3}, [%4];"
        : "=r"(r0), "=r"(r1), "=r"(r2), "=r"(r3) : "r"(addr));
}
__device__ __forceinline__ uint32_t pack_h2(float a, float b) {
    __half2 h = __floats2half2_rn(a, b);
    return *(uint32_t*)&h;
}

// ---------------------------------------------------------------------------
// RoPE cos/sin table: bit-identical math to the old in-epilogue computation.
// ---------------------------------------------------------------------------
__global__ void rope_table(float2* __restrict__ T)
{
    int i = blockIdx.x * 256 + threadIdx.x;      // SEQ*64 threads
    int pos = i >> 6, d = i & 63;
    const float LG = 0.2076205059304640f;        // 2*log2(10000)/128
    float invf = exp2f(-LG * (float)d);
    float ang = (float)pos * invf;
    float sn, cs;
    sincosf(ang, &sn, &cs);
    T[i] = make_float2(cs, sn);
}

// ---------------------------------------------------------------------------
// One-shot fp32->half conversion of all 7 tensors. 2048 elems per block.
// ---------------------------------------------------------------------------
struct ConvDesc {
    const float* src[7];
    __half*      dst[7];
    int          nblk[7];
};

__global__ void conv_all(ConvDesc cd)
{
    int b = blockIdx.x;
    int seg = 0;
#pragma unroll
    for (int i = 0; i < 7; i++) {
        if (b >= cd.nblk[i]) { b -= cd.nblk[i]; seg = i + 1; }
        else break;
    }
    const float* src = cd.src[seg];
    __half* dst = cd.dst[seg];
    size_t i = (size_t)b * 2048 + (size_t)threadIdx.x * 4;
    float4 v0 = *(const float4*)(src + i);
    float4 v1 = *(const float4*)(src + i + 1024);
    *(__half2*)(dst + i)     = __floats2half2_rn(v0.x, v0.y);
    *(__half2*)(dst + i + 2) = __floats2half2_rn(v0.z, v0.w);
    *(__half2*)(dst + i + 1024)     = __floats2half2_rn(v1.x, v1.y);
    *(__half2*)(dst + i + 1024 + 2) = __floats2half2_rn(v1.z, v1.w);
}

// ---------------------------------------------------------------------------
// Grouped fp16 tensor-core GEMM. CTA 128x128, BK=64, 8 warps, 3-stage
// cp.async (de-bunched, hoisted offsets), frag double-buffer, 2 CTAs/SM.
// mode: 0 = fp32 out, 1 = half out, 2 = rope(+scale, table) half out.
// ---------------------------------------------------------------------------
#define HP  72
#define BPN 136
#define SPN 132
#define A_ST (128 * HP)
#define B_ST (64 * BPN)
#define STG_B ((A_ST + B_ST) * 2)
#define GN_SMEM (3 * STG_B)

struct GroupArgs {
    const __half* A[3];
    const __half* B[3];
    void*         C[3];
    int           N[3];
    int           mode[3];
    float         rsc[3];
    int           xend[3];
    int           nseg;
};

__global__ __launch_bounds__(256, 2) void gemm_grp(GroupArgs ga, int K)
{
    extern __shared__ __half smh[];
    const uint32_t sb = smem_u32(smh);

    int bx = blockIdx.x;
    int seg = 0;
#pragma unroll
    for (int i = 0; i < 2; i++)
        if (i + 1 < ga.nseg && bx >= ga.xend[i]) seg = i + 1;
    const int xbase = (seg == 0) ? 0 : ga.xend[seg - 1];
    const __half* A = ga.A[seg];
    const __half* B = ga.B[seg];
    void* Cv        = ga.C[seg];
    const int N     = ga.N[seg];
    const int mode  = ga.mode[seg];
    const float rsc = ga.rsc[seg];

    const int tid  = threadIdx.x;
    const int wid  = tid >> 5, lane = tid & 31;
    const int g    = lane >> 2, tig = lane & 3;
    const int wm   = (wid >> 2) * 64;
    const int wn   = (wid & 3) * 32;
    const int bm   = blockIdx.y * 128, bn = (bx - xbase) * 128;

    // hoisted per-thread loader offsets (loop-invariant)
    size_t   gA[4], gB[4];
    uint32_t sAo[4], sBo[4];
#pragma unroll
    for (int ks = 0; ks < 4; ks++) {
        int id = ks * 256 + tid;
        int ra = id >> 3, ca = (id & 7) * 8;
        int rb = id >> 4, cb = (id & 15) * 8;
        gA[ks]  = (size_t)ra * K + ca;
        gB[ks]  = (size_t)rb * N + cb;
        sAo[ks] = (uint32_t)(ra * HP + ca) * 2;
        sBo[ks] = (uint32_t)(rb * BPN + cb) * 2;
    }

    auto load_tile = [&](int c, int s) {
        const __half* Ab = A + (size_t)bm * K + c * 64;
        const __half* Bb = B + (size_t)(c * 64) * N + bn;
        uint32_t sa  = sb + (uint32_t)s * STG_B;
        uint32_t sbb = sa + A_ST * 2;
#pragma unroll
        for (int l = 0; l < 4; l++) {
            cpasync16(sa  + sAo[l], Ab + gA[l]);
            cpasync16(sbb + sBo[l], Bb + gB[l]);
        }
        CP_COMMIT();
    };

    const int l7  = lane & 7;
    const int lb3 = (lane >> 3) & 1;
    const int lb4 = lane >> 4;

    float acc[4][4][4];
#pragma unroll
    for (int mi = 0; mi < 4; mi++)
#pragma unroll
        for (int ni = 0; ni < 4; ni++)
#pragma unroll
            for (int r = 0; r < 4; r++) acc[mi][ni][r] = 0.0f;

    const int iters = K / 64;
    load_tile(0, 0);
    load_tile(1, 1);

    uint32_t sA = 0, sBb = 0;
    uint32_t af[2][4][4], bf[2][2][4];

    auto load_frag = [&](int ks, int pb) {
        const int kb = ks * 16;
#pragma unroll
        for (int mi = 0; mi < 4; mi++) {
            uint32_t addr = sA + (uint32_t)((wm + mi * 16 + l7 + lb3 * 8) * HP
                                            + kb + lb4 * 8) * 2;
            ldsm4(af[pb][mi][0], af[pb][mi][1], af[pb][mi][2], af[pb][mi][3], addr);
        }
#pragma unroll
        for (int nj = 0; nj < 2; nj++) {
            uint32_t addr = sBb + (uint32_t)((kb + l7 + lb3 * 8) * BPN
                                             + wn + nj * 16 + lb4 * 8) * 2;
            ldsm4t(bf[pb][nj][0], bf[pb][nj][1], bf[pb][nj][2], bf[pb][nj][3], addr);
        }
    };

    for (int c = 0; c < iters; c++) {
        const int s = c % 3;
        if (c + 1 < iters) { CP_WAIT(1); } else { CP_WAIT(0); }
        __syncthreads();

        sA  = sb + (uint32_t)s * STG_B;
        sBb = sA + A_ST * 2;

        const bool pf = (c + 2 < iters);
        const __half* Abn = nullptr;
        const __half* Bbn = nullptr;
        uint32_t san = 0, sbn = 0;
        if (pf) {
            const int cn = c + 2, sn = cn % 3;
            Abn = A + (size_t)bm * K + cn * 64;
            Bbn = B + (size_t)(cn * 64) * N + bn;
            san = sb + (uint32_t)sn * STG_B;
            sbn = san + A_ST * 2;
        }

        load_frag(0, 0);
#pragma unroll
        for (int ks = 0; ks < 4; ks++) {
            if (pf) {
                cpasync16(san + sAo[ks], Abn + gA[ks]);
                cpasync16(sbn + sBo[ks], Bbn + gB[ks]);
            }
            const int cur = ks & 1;
            if (ks < 3) load_frag(ks + 1, cur ^ 1);
#pragma unroll
            for (int mi = 0; mi < 4; mi++)
#pragma unroll
                for (int nj = 0; nj < 2; nj++) {
                    mma_f16(acc[mi][nj * 2],     af[cur][mi], bf[cur][nj][0], bf[cur][nj][1]);
                    mma_f16(acc[mi][nj * 2 + 1], af[cur][mi], bf[cur][nj][2], bf[cur][nj][3]);
                }
        }
        if (pf) CP_COMMIT();
    }

    if (mode == 2) {
        __syncthreads();
        float* S = (float*)smh;
#pragma unroll
        for (int mi = 0; mi < 4; mi++) {
            int r0 = wm + mi * 16 + g;
#pragma unroll
            for (int ni = 0; ni < 4; ni++) {
                int cc = wn + ni * 8 + tig * 2;
                *(float2*)(S + (size_t)r0 * SPN + cc)       = make_float2(acc[mi][ni][0], acc[mi][ni][1]);
                *(float2*)(S + (size_t)(r0 + 8) * SPN + cc) = make_float2(acc[mi][ni][2], acc[mi][ni][3]);
            }
        }
        __syncthreads();
        __half* C = (__half*)Cv;
#pragma unroll 4
        for (int l = 0; l < 32; l++) {
            int idx = l * 256 + tid;
            int r  = idx >> 6;
            int d  = idx & 63;
            float x1 = S[(size_t)r * SPN + d];
            float x2 = S[(size_t)r * SPN + d + 64];
            int grow = bm + r;
            float2 cs2 = g_rope[(size_t)(grow & (SEQ - 1)) * 64 + d];
            float cs = cs2.x, sn = cs2.y;
            size_t o = (size_t)grow * N + bn + d;
            C[o]      = __float2half((x1 * cs - x2 * sn) * rsc);
            C[o + 64] = __float2half((x2 * cs + x1 * sn) * rsc);
        }
    } else if (mode == 1) {
        __half* C = (__half*)Cv;
#pragma unroll
        for (int mi = 0; mi < 4; mi++) {
            int row0 = bm + wm + mi * 16 + g;
#pragma unroll
            for (int ni = 0; ni < 4; ni++) {
                int col = bn + wn + ni * 8 + tig * 2;
                *(__half2*)(C + (size_t)row0 * N + col) =
                    __floats2half2_rn(acc[mi][ni][0], acc[mi][ni][1]);
                *(__half2*)(C + (size_t)(row0 + 8) * N + col) =
                    __floats2half2_rn(acc[mi][ni][2], acc[mi][ni][3]);
            }
        }
    } else {
        float* C = (float*)Cv;
#pragma unroll
        for (int mi = 0; mi < 4; mi++) {
            int row0 = bm + wm + mi * 16 + g;
#pragma unroll
            for (int ni = 0; ni < 4; ni++) {
                int col = bn + wn + ni * 8 + tig * 2;
                *(float2*)(C + (size_t)row0 * N + col)       = make_float2(acc[mi][ni][0], acc[mi][ni][1]);
                *(float2*)(C + (size_t)(row0 + 8) * N + col) = make_float2(acc[mi][ni][2], acc[mi][ni][3]);
            }
        }
    }
}

// ---------------------------------------------------------------------------
// Flash attention v8: register-resident P, deferred l reduction, hoisted
// prefetch offsets. 128 threads, Q tile 64, K tile 64, 2-stage cp.async,
// 2 CTAs/SM.
// ---------------------------------------------------------------------------
#define QP 136
#define KVST (2 * 64 * QP)                      // halves per stage (K+V)
#define FL8_SMEM ((64*QP + 2*KVST) * 2)         // 87040 bytes

__global__ __launch_bounds__(128, 2) void flash8(const __half* __restrict__ Q,
                                                 const __half* __restrict__ K,
                                                 const __half* __restrict__ V,
                                                 __half* __restrict__ O)
{
    extern __shared__ __half hs[];
    __half* Qs  = hs;                        // [64][136]
    __half* KV0 = Qs + 64 * QP;              // 2 stages: K[64][136] then V[64][136]

    const uint32_t sbQ  = smem_u32(Qs);
    const uint32_t sbKV = smem_u32(KV0);

    const int qi  = (int)gridDim.x - 1 - (int)blockIdx.x;   // big tiles first
    const int h   = blockIdx.y;
    const int b   = blockIdx.z;
    const int kvh = h / GROUPS;
    const int tid = threadIdx.x;
    const int wid = tid >> 5, lane = tid & 31;
    const int g   = lane >> 2, tig = lane & 3;
    const int wq  = wid * 16;                 // 0..48
    const int l7  = lane & 7;
    const int lb3 = (lane >> 3) & 1;
    const int lb4 = lane >> 4;

    const __half* Qg = Q + (size_t)(b * SEQ + qi * 64) * QDIM + h * HD;
    const __half* Kg = K + (size_t)(b * SEQ) * KVDIM + kvh * HD;
    const __half* Vg = V + (size_t)(b * SEQ) * KVDIM + kvh * HD;

    // hoisted per-thread loader offsets (iteration-invariant)
    size_t   gKV[8];
    uint32_t sKV[8];
#pragma unroll
    for (int l = 0; l < 8; l++) {
        int id = l * 128 + tid;
        int r = id >> 4, c8 = (id & 15) * 8;
        gKV[l] = (size_t)r * KVDIM + c8;
        sKV[l] = (uint32_t)(r * QP + c8) * 2;
    }

    auto load_kv_full = [&](int kb, int s) {
        const __half* Kt = Kg + (size_t)(kb * 64) * KVDIM;
        const __half* Vt = Vg + (size_t)(kb * 64) * KVDIM;
        uint32_t ks_ = sbKV + (uint32_t)s * (KVST * 2);
        uint32_t vs_ = ks_ + 64 * QP * 2;
#pragma unroll
        for (int l = 0; l < 8; l++) {
            cpasync16(ks_ + sKV[l], Kt + gKV[l]);
            cpasync16(vs_ + sKV[l], Vt + gKV[l]);
        }
        CP_COMMIT();
    };

    // load Q tile (64 x 128 halves)
#pragma unroll
    for (int l = 0; l < 8; l++) {
        int id = l * 128 + tid;
        int r = id >> 4, c8 = (id & 15) * 8;
        *(uint4*)(Qs + r * QP + c8) = *(const uint4*)(Qg + (size_t)r * QDIM + c8);
    }

    float m0 = -INFINITY, m1 = -INFINITY;
    float l0p = 0.f, l1p = 0.f;              // lane-local partial row sums
    float oa[16][4];
#pragma unroll
    for (int ni = 0; ni < 16; ni++)
#pragma unroll
        for (int r = 0; r < 4; r++) oa[ni][r] = 0.f;

    const int kmax = qi + 1;
    load_kv_full(0, 0);

    for (int kb = 0; kb < kmax; kb++) {
        const int s = kb & 1;
        CP_WAIT(0);
        __syncthreads();

        const uint32_t sK = sbKV + (uint32_t)s * (KVST * 2);
        const uint32_t sV = sK + 64 * QP * 2;

        const bool pf = (kb + 1 < kmax);
        const __half* Ktn = Kg + (size_t)((kb + 1) * 64) * KVDIM;
        const __half* Vtn = Vg + (size_t)((kb + 1) * 64) * KVDIM;
        const uint32_t ksn = sbKV + (uint32_t)(s ^ 1) * (KVST * 2);
        const uint32_t vsn = ksn + 64 * QP * 2;

        // ---- S = Q K^T (warp: 16 x 64) ----
        float sa[8][4];
#pragma unroll
        for (int ni = 0; ni < 8; ni++)
#pragma unroll
            for (int r = 0; r < 4; r++) sa[ni][r] = 0.f;

#pragma unroll
        for (int ks = 0; ks < 8; ks++) {
            if (pf) {
                cpasync16(ksn + sKV[ks], Ktn + gKV[ks]);
                cpasync16(vsn + sKV[ks], Vtn + gKV[ks]);
            }
            const int kc = ks * 16;
            uint32_t a[4], bfr[8][2];
            {
                uint32_t addr = sbQ + (uint32_t)((wq + l7 + lb3 * 8) * QP + kc + lb4 * 8) * 2;
                ldsm4(a[0], a[1], a[2], a[3], addr);
            }
#pragma unroll
            for (int nip = 0; nip < 4; nip++) {
                uint32_t addr = sK + (uint32_t)((nip * 16 + l7 + lb4 * 8) * QP + kc + lb3 * 8) * 2;
                ldsm4(bfr[nip*2][0], bfr[nip*2][1], bfr[nip*2+1][0], bfr[nip*2+1][1], addr);
            }
#pragma unroll
            for (int ni = 0; ni < 8; ni++)
                mma_f16(sa[ni], a, bfr[ni][0], bfr[ni][1]);
        }
        if (pf) CP_COMMIT();

        // ---- causal mask (diagonal tile only: kb == qi) ----
        if (kb == qi) {
            int r0 = qi * 64 + wq + g;
#pragma unroll
            for (int ni = 0; ni < 8; ni++) {
                int c0 = kb * 64 + ni * 8 + 2 * tig;
                if (c0 > r0)         sa[ni][0] = -INFINITY;
                if (c0 + 1 > r0)     sa[ni][1] = -INFINITY;
                if (c0 > r0 + 8)     sa[ni][2] = -INFINITY;
                if (c0 + 1 > r0 + 8) sa[ni][3] = -INFINITY;
            }
        }

        // ---- online softmax (max reduce only; l kept lane-local) ----
        float mx0 = -INFINITY, mx1 = -INFINITY;
#pragma unroll
        for (int ni = 0; ni < 8; ni++) {
            mx0 = fmaxf(mx0, fmaxf(sa[ni][0], sa[ni][1]));
            mx1 = fmaxf(mx1, fmaxf(sa[ni][2], sa[ni][3]));
        }
        mx0 = fmaxf(mx0, __shfl_xor_sync(0xffffffffu, mx0, 1));
        mx0 = fmaxf(mx0, __shfl_xor_sync(0xffffffffu, mx0, 2));
        mx1 = fmaxf(mx1, __shfl_xor_sync(0xffffffffu, mx1, 1));
        mx1 = fmaxf(mx1, __shfl_xor_sync(0xffffffffu, mx1, 2));

        float mm0 = fmaxf(m0, mx0), mm1 = fmaxf(m1, mx1);
        float sub0 = (mm0 == -INFINITY) ? 0.f : mm0;
        float sub1 = (mm1 == -INFINITY) ? 0.f : mm1;
        float al0 = exp2f(m0 - sub0);
        float al1 = exp2f(m1 - sub1);
        m0 = mm0; m1 = mm1;

        uint32_t ph[8][2];
        float ls0 = 0.f, ls1 = 0.f;
#pragma unroll
        for (int ni = 0; ni < 8; ni++) {
            float p0 = exp2f(sa[ni][0] - sub0);
            float p1 = exp2f(sa[ni][1] - sub0);
            float p2 = exp2f(sa[ni][2] - sub1);
            float p3 = exp2f(sa[ni][3] - sub1);
            ls0 += p0 + p1; ls1 += p2 + p3;
            ph[ni][0] = pack_h2(p0, p1);
            ph[ni][1] = pack_h2(p2, p3);
        }
        l0p = l0p * al0 + ls0;    // lane-local partial; quad-reduced at end
        l1p = l1p * al1 + ls1;

#pragma unroll
        for (int ni = 0; ni < 16; ni++) {
            oa[ni][0] *= al0; oa[ni][1] *= al0;
            oa[ni][2] *= al1; oa[ni][3] *= al1;
        }

        // ---- O += P @ V  (A = register P; B = V via ldmatrix.trans) ----
#pragma unroll
        for (int ks = 0; ks < 4; ks++) {
            const int kc = ks * 16;
            uint32_t a[4];
            a[0] = ph[2 * ks][0];
            a[1] = ph[2 * ks][1];
            a[2] = ph[2 * ks + 1][0];
            a[3] = ph[2 * ks + 1][1];
#pragma unroll
            for (int nip = 0; nip < 8; nip++) {
                uint32_t bf0, bf1, bf2, bf3;
                uint32_t addr = sV + (uint32_t)((kc + l7 + lb3 * 8) * QP + nip * 16 + lb4 * 8) * 2;
                ldsm4t(bf0, bf1, bf2, bf3, addr);
                mma_f16(oa[nip*2],     a, bf0, bf1);
                mma_f16(oa[nip*2 + 1], a, bf2, bf3);
            }
        }
    }

    // ---- final l reduction across the quad, then epilogue ----
    float l0 = l0p, l1 = l1p;
    l0 += __shfl_xor_sync(0xffffffffu, l0, 1);
    l0 += __shfl_xor_sync(0xffffffffu, l0, 2);
    l1 += __shfl_xor_sync(0xffffffffu, l1, 1);
    l1 += __shfl_xor_sync(0xffffffffu, l1, 2);

    float inv0 = 1.0f / l0, inv1 = 1.0f / l1;
    __half* Og = O + (size_t)(b * SEQ + qi * 64 + wq) * QDIM + h * HD;
#pragma unroll
    for (int ni = 0; ni < 16; ni++) {
        int col = ni * 8 + 2 * tig;
        *(__half2*)(Og + (size_t)g * QDIM + col) =
            __floats2half2_rn(oa[ni][0] * inv0, oa[ni][1] * inv0);
        *(__half2*)(Og + (size_t)(g + 8) * QDIM + col) =
            __floats2half2_rn(oa[ni][2] * inv1, oa[ni][3] * inv1);
    }
}

// ---------------------------------------------------------------------------
// Launch: rope_table + conv_all -> grouped QKV gemm -> flash -> O gemm
// ---------------------------------------------------------------------------
extern "C" void kernel_launch(void* const* d_in, const int* in_sizes, int n_in,
                              void* d_out, int out_size)
{
    const float* query = (const float*)d_in[0];
    const float* key   = (const float*)d_in[1];
    const float* value = (const float*)d_in[2];
    const float* Wq = (const float*)d_in[5];
    const float* Wk = (const float*)d_in[6];
    const float* Wv = (const float*)d_in[7];
    const float* Wo = (const float*)d_in[8];
    float* out = (float*)d_out;

    __half *pQa, *pKa, *pVa, *pQh, *pKh, *pVh, *pAOh, *pWqh, *pWkh, *pWvh, *pWoh;
    float2* pRope;
    cudaGetSymbolAddress((void**)&pQa,   g_Qa);
    cudaGetSymbolAddress((void**)&pKa,   g_Ka);
    cudaGetSymbolAddress((void**)&pVa,   g_Va);
    cudaGetSymbolAddress((void**)&pQh,   g_Qh);
    cudaGetSymbolAddress((void**)&pKh,   g_Kh);
    cudaGetSymbolAddress((void**)&pVh,   g_Vh);
    cudaGetSymbolAddress((void**)&pAOh,  g_AOh);
    cudaGetSymbolAddress((void**)&pWqh,  g_Wqh);
    cudaGetSymbolAddress((void**)&pWkh,  g_Wkh);
    cudaGetSymbolAddress((void**)&pWvh,  g_Wvh);
    cudaGetSymbolAddress((void**)&pWoh,  g_Woh);
    cudaGetSymbolAddress((void**)&pRope, g_rope);

    cudaFuncSetAttribute(gemm_grp, cudaFuncAttributeMaxDynamicSharedMemorySize, GN_SMEM);
    cudaFuncSetAttribute(flash8,   cudaFuncAttributeMaxDynamicSharedMemorySize, FL8_SMEM);

    // rope table (tiny) + one-shot conversion of everything to half
    rope_table<<<(SEQ * 64) / 256, 256>>>(pRope);

    ConvDesc cd;
    cd.src[0] = query; cd.dst[0] = pQa;  cd.nblk[0] = (MROWS * EMB) / 2048;
    cd.src[1] = key;   cd.dst[1] = pKa;  cd.nblk[1] = (MROWS * EMB) / 2048;
    cd.src[2] = value; cd.dst[2] = pVa;  cd.nblk[2] = (MROWS * EMB) / 2048;
    cd.src[3] = Wq;    cd.dst[3] = pWqh; cd.nblk[3] = (EMB * QDIM) / 2048;
    cd.src[4] = Wk;    cd.dst[4] = pWkh; cd.nblk[4] = (EMB * KVDIM) / 2048;
    cd.src[5] = Wv;    cd.dst[5] = pWvh; cd.nblk[5] = (EMB * KVDIM) / 2048;
    cd.src[6] = Wo;    cd.dst[6] = pWoh; cd.nblk[6] = (QDIM * EMB) / 2048;
    int total_blk = cd.nblk[0] + cd.nblk[1] + cd.nblk[2] + cd.nblk[3]
                  + cd.nblk[4] + cd.nblk[5] + cd.nblk[6];
    conv_all<<<total_blk, 256>>>(cd);

    // grouped Q+K+V projections (one launch; rope fused for Q,K)
    GroupArgs gq;
    gq.A[0] = pQa; gq.B[0] = pWqh; gq.C[0] = pQh; gq.N[0] = QDIM;  gq.mode[0] = 2; gq.rsc[0] = QSCALE; gq.xend[0] = 32;
    gq.A[1] = pKa; gq.B[1] = pWkh; gq.C[1] = pKh; gq.N[1] = KVDIM; gq.mode[1] = 2; gq.rsc[1] = 1.0f;   gq.xend[1] = 40;
    gq.A[2] = pVa; gq.B[2] = pWvh; gq.C[2] = pVh; gq.N[2] = KVDIM; gq.mode[2] = 1; gq.rsc[2] = 0.0f;   gq.xend[2] = 48;
    gq.nseg = 3;
    gemm_grp<<<dim3(48, MROWS / 128), 256, GN_SMEM>>>(gq, EMB);

    // attention
    flash8<<<dim3(SEQ / 64, NH, BSZ), 128, FL8_SMEM>>>(pQh, pKh, pVh, pAOh);

    // output projection
    GroupArgs go;
    go.A[0] = pAOh; go.B[0] = pWoh; go.C[0] = out; go.N[0] = EMB; go.mode[0] = 0; go.rsc[0] = 0.0f; go.xend[0] = 32;
    go.nseg = 1;
    gemm_grp<<<dim3(32, MROWS / 128), 256, GN_SMEM>>>(go, QDIM);
}

// round 16
// speedup vs baseline: 1.1268x; 1.0035x over previous
#include <cuda_runtime.h>
#include <cuda_fp16.h>
#include <math.h>
#include <stdint.h>

#define BSZ   2
#define SEQ   2048
#define EMB   4096
#define NH    32
#define NKVH  8
#define HD    128
#define GROUPS (NH / NKVH)
#define MROWS (BSZ * SEQ)          // 4096
#define QDIM  (NH * HD)            // 4096
#define KVDIM (NKVH * HD)          // 1024

// log2(e)/sqrt(128), folded into Q so softmax uses bare exp2
#define QSCALE 0.12751744f

// Scratch (device globals)
__device__ __half g_Qa [(size_t)MROWS * EMB];    // half activations
__device__ __half g_Ka [(size_t)MROWS * EMB];
__device__ __half g_Va [(size_t)MROWS * EMB];
__device__ __half g_Qh [(size_t)MROWS * QDIM];   // post-rope half
__device__ __half g_Kh [(size_t)MROWS * KVDIM];
__device__ __half g_Vh [(size_t)MROWS * KVDIM];
__device__ __half g_AOh[(size_t)MROWS * QDIM];
__device__ __half g_Wqh[(size_t)EMB * QDIM];     // [K][N] half (no transpose)
__device__ __half g_Wkh[(size_t)EMB * KVDIM];
__device__ __half g_Wvh[(size_t)EMB * KVDIM];
__device__ __half g_Woh[(size_t)QDIM * EMB];
__device__ float2 g_rope[(size_t)SEQ * 64];      // (cos, sin) per (pos, d)

// ---------------------------------------------------------------------------
// Helpers
// ---------------------------------------------------------------------------
__device__ __forceinline__ uint32_t smem_u32(const void* p) {
    uint32_t a;
    asm("{ .reg .u64 t; cvta.to.shared.u64 t, %1; cvt.u32.u64 %0, t; }" : "=r"(a) : "l"(p));
    return a;
}
__device__ __forceinline__ void cpasync16(uint32_t dst, const void* src) {
    asm volatile("cp.async.cg.shared.global [%0], [%1], 16;" :: "r"(dst), "l"(src) : "memory");
}
#define CP_COMMIT() asm volatile("cp.async.commit_group;" ::: "memory")
#define CP_WAIT(n)  asm volatile("cp.async.wait_group %0;" :: "n"(n) : "memory")

__device__ __forceinline__ void mma_f16(float* d, const uint32_t* a, uint32_t b0, uint32_t b1) {
    asm volatile("mma.sync.aligned.m16n8k16.row.col.f32.f16.f16.f32 "
        "{%0,%1,%2,%3}, {%4,%5,%6,%7}, {%8,%9}, {%0,%1,%2,%3};"
        : "+f"(d[0]), "+f"(d[1]), "+f"(d[2]), "+f"(d[3])
        : "r"(a[0]), "r"(a[1]), "r"(a[2]), "r"(a[3]), "r"(b0), "r"(b1));
}
__device__ __forceinline__ void ldsm4(uint32_t& r0, uint32_t& r1, uint32_t& r2, uint32_t& r3,
                                      uint32_t addr) {
    asm volatile("ldmatrix.sync.aligned.m8n8.x4.shared.b16 {%0,%1,%2,%3}, [%4];"
        : "=r"(r0), "=r"(r1), "=r"(r2), "=r"(r3) : "r"(addr));
}
__device__ __forceinline__ void ldsm4t(uint32_t& r0, uint32_t& r1, uint32_t& r2, uint32_t& r3,
                                       uint32_t addr) {
    asm volatile("ldmatrix.sync.aligned.m8n8.x4.trans.shared.b16 {%0,%1,%2,%3}, [%4];"
        : "=r"(r0), "=r"(r1), "=r"(r2), "=r"(r3) : "r"(addr));
}
__device__ __forceinline__ uint32_t pack_h2(float a, float b) {
    __half2 h = __floats2half2_rn(a, b);
    return *(uint32_t*)&h;
}

// ---------------------------------------------------------------------------
// RoPE cos/sin table: bit-identical math to the in-epilogue computation.
// ---------------------------------------------------------------------------
__global__ void rope_table(float2* __restrict__ T)
{
    int i = blockIdx.x * 256 + threadIdx.x;      // SEQ*64 threads
    int pos = i >> 6, d = i & 63;
    const float LG = 0.2076205059304640f;        // 2*log2(10000)/128
    float invf = exp2f(-LG * (float)d);
    float ang = (float)pos * invf;
    float sn, cs;
    sincosf(ang, &sn, &cs);
    T[i] = make_float2(cs, sn);
}

// ---------------------------------------------------------------------------
// One-shot fp32->half conversion of all 7 tensors. 2048 elems per block.
// ---------------------------------------------------------------------------
struct ConvDesc {
    const float* src[7];
    __half*      dst[7];
    int          nblk[7];
};

__global__ void conv_all(ConvDesc cd)
{
    int b = blockIdx.x;
    int seg = 0;
#pragma unroll
    for (int i = 0; i < 7; i++) {
        if (b >= cd.nblk[i]) { b -= cd.nblk[i]; seg = i + 1; }
        else break;
    }
    const float* src = cd.src[seg];
    __half* dst = cd.dst[seg];
    size_t i = (size_t)b * 2048 + (size_t)threadIdx.x * 4;
    float4 v0 = *(const float4*)(src + i);
    float4 v1 = *(const float4*)(src + i + 1024);
    *(__half2*)(dst + i)     = __floats2half2_rn(v0.x, v0.y);
    *(__half2*)(dst + i + 2) = __floats2half2_rn(v0.z, v0.w);
    *(__half2*)(dst + i + 1024)     = __floats2half2_rn(v1.x, v1.y);
    *(__half2*)(dst + i + 1024 + 2) = __floats2half2_rn(v1.z, v1.w);
}

// ---------------------------------------------------------------------------
// Grouped fp16 tensor-core GEMM (unchanged from R15).
// ---------------------------------------------------------------------------
#define HP  72
#define BPN 136
#define SPN 132
#define A_ST (128 * HP)
#define B_ST (64 * BPN)
#define STG_B ((A_ST + B_ST) * 2)
#define GN_SMEM (3 * STG_B)

struct GroupArgs {
    const __half* A[3];
    const __half* B[3];
    void*         C[3];
    int           N[3];
    int           mode[3];
    float         rsc[3];
    int           xend[3];
    int           nseg;
};

__global__ __launch_bounds__(256, 2) void gemm_grp(GroupArgs ga, int K)
{
    extern __shared__ __half smh[];
    const uint32_t sb = smem_u32(smh);

    int bx = blockIdx.x;
    int seg = 0;
#pragma unroll
    for (int i = 0; i < 2; i++)
        if (i + 1 < ga.nseg && bx >= ga.xend[i]) seg = i + 1;
    const int xbase = (seg == 0) ? 0 : ga.xend[seg - 1];
    const __half* A = ga.A[seg];
    const __half* B = ga.B[seg];
    void* Cv        = ga.C[seg];
    const int N     = ga.N[seg];
    const int mode  = ga.mode[seg];
    const float rsc = ga.rsc[seg];

    const int tid  = threadIdx.x;
    const int wid  = tid >> 5, lane = tid & 31;
    const int g    = lane >> 2, tig = lane & 3;
    const int wm   = (wid >> 2) * 64;
    const int wn   = (wid & 3) * 32;
    const int bm   = blockIdx.y * 128, bn = (bx - xbase) * 128;

    size_t   gA[4], gB[4];
    uint32_t sAo[4], sBo[4];
#pragma unroll
    for (int ks = 0; ks < 4; ks++) {
        int id = ks * 256 + tid;
        int ra = id >> 3, ca = (id & 7) * 8;
        int rb = id >> 4, cb = (id & 15) * 8;
        gA[ks]  = (size_t)ra * K + ca;
        gB[ks]  = (size_t)rb * N + cb;
        sAo[ks] = (uint32_t)(ra * HP + ca) * 2;
        sBo[ks] = (uint32_t)(rb * BPN + cb) * 2;
    }

    auto load_tile = [&](int c, int s) {
        const __half* Ab = A + (size_t)bm * K + c * 64;
        const __half* Bb = B + (size_t)(c * 64) * N + bn;
        uint32_t sa  = sb + (uint32_t)s * STG_B;
        uint32_t sbb = sa + A_ST * 2;
#pragma unroll
        for (int l = 0; l < 4; l++) {
            cpasync16(sa  + sAo[l], Ab + gA[l]);
            cpasync16(sbb + sBo[l], Bb + gB[l]);
        }
        CP_COMMIT();
    };

    const int l7  = lane & 7;
    const int lb3 = (lane >> 3) & 1;
    const int lb4 = lane >> 4;

    float acc[4][4][4];
#pragma unroll
    for (int mi = 0; mi < 4; mi++)
#pragma unroll
        for (int ni = 0; ni < 4; ni++)
#pragma unroll
            for (int r = 0; r < 4; r++) acc[mi][ni][r] = 0.0f;

    const int iters = K / 64;
    load_tile(0, 0);
    load_tile(1, 1);

    uint32_t sA = 0, sBb = 0;
    uint32_t af[2][4][4], bf[2][2][4];

    auto load_frag = [&](int ks, int pb) {
        const int kb = ks * 16;
#pragma unroll
        for (int mi = 0; mi < 4; mi++) {
            uint32_t addr = sA + (uint32_t)((wm + mi * 16 + l7 + lb3 * 8) * HP
                                            + kb + lb4 * 8) * 2;
            ldsm4(af[pb][mi][0], af[pb][mi][1], af[pb][mi][2], af[pb][mi][3], addr);
        }
#pragma unroll
        for (int nj = 0; nj < 2; nj++) {
            uint32_t addr = sBb + (uint32_t)((kb + l7 + lb3 * 8) * BPN
                                             + wn + nj * 16 + lb4 * 8) * 2;
            ldsm4t(bf[pb][nj][0], bf[pb][nj][1], bf[pb][nj][2], bf[pb][nj][3], addr);
        }
    };

    for (int c = 0; c < iters; c++) {
        const int s = c % 3;
        if (c + 1 < iters) { CP_WAIT(1); } else { CP_WAIT(0); }
        __syncthreads();

        sA  = sb + (uint32_t)s * STG_B;
        sBb = sA + A_ST * 2;

        const bool pf = (c + 2 < iters);
        const __half* Abn = nullptr;
        const __half* Bbn = nullptr;
        uint32_t san = 0, sbn = 0;
        if (pf) {
            const int cn = c + 2, sn = cn % 3;
            Abn = A + (size_t)bm * K + cn * 64;
            Bbn = B + (size_t)(cn * 64) * N + bn;
            san = sb + (uint32_t)sn * STG_B;
            sbn = san + A_ST * 2;
        }

        load_frag(0, 0);
#pragma unroll
        for (int ks = 0; ks < 4; ks++) {
            if (pf) {
                cpasync16(san + sAo[ks], Abn + gA[ks]);
                cpasync16(sbn + sBo[ks], Bbn + gB[ks]);
            }
            const int cur = ks & 1;
            if (ks < 3) load_frag(ks + 1, cur ^ 1);
#pragma unroll
            for (int mi = 0; mi < 4; mi++)
#pragma unroll
                for (int nj = 0; nj < 2; nj++) {
                    mma_f16(acc[mi][nj * 2],     af[cur][mi], bf[cur][nj][0], bf[cur][nj][1]);
                    mma_f16(acc[mi][nj * 2 + 1], af[cur][mi], bf[cur][nj][2], bf[cur][nj][3]);
                }
        }
        if (pf) CP_COMMIT();
    }

    if (mode == 2) {
        __syncthreads();
        float* S = (float*)smh;
#pragma unroll
        for (int mi = 0; mi < 4; mi++) {
            int r0 = wm + mi * 16 + g;
#pragma unroll
            for (int ni = 0; ni < 4; ni++) {
                int cc = wn + ni * 8 + tig * 2;
                *(float2*)(S + (size_t)r0 * SPN + cc)       = make_float2(acc[mi][ni][0], acc[mi][ni][1]);
                *(float2*)(S + (size_t)(r0 + 8) * SPN + cc) = make_float2(acc[mi][ni][2], acc[mi][ni][3]);
            }
        }
        __syncthreads();
        __half* C = (__half*)Cv;
#pragma unroll 4
        for (int l = 0; l < 32; l++) {
            int idx = l * 256 + tid;
            int r  = idx >> 6;
            int d  = idx & 63;
            float x1 = S[(size_t)r * SPN + d];
            float x2 = S[(size_t)r * SPN + d + 64];
            int grow = bm + r;
            float2 cs2 = g_rope[(size_t)(grow & (SEQ - 1)) * 64 + d];
            float cs = cs2.x, sn = cs2.y;
            size_t o = (size_t)grow * N + bn + d;
            C[o]      = __float2half((x1 * cs - x2 * sn) * rsc);
            C[o + 64] = __float2half((x2 * cs + x1 * sn) * rsc);
        }
    } else if (mode == 1) {
        __half* C = (__half*)Cv;
#pragma unroll
        for (int mi = 0; mi < 4; mi++) {
            int row0 = bm + wm + mi * 16 + g;
#pragma unroll
            for (int ni = 0; ni < 4; ni++) {
                int col = bn + wn + ni * 8 + tig * 2;
                *(__half2*)(C + (size_t)row0 * N + col) =
                    __floats2half2_rn(acc[mi][ni][0], acc[mi][ni][1]);
                *(__half2*)(C + (size_t)(row0 + 8) * N + col) =
                    __floats2half2_rn(acc[mi][ni][2], acc[mi][ni][3]);
            }
        }
    } else {
        float* C = (float*)Cv;
#pragma unroll
        for (int mi = 0; mi < 4; mi++) {
            int row0 = bm + wm + mi * 16 + g;
#pragma unroll
            for (int ni = 0; ni < 4; ni++) {
                int col = bn + wn + ni * 8 + tig * 2;
                *(float2*)(C + (size_t)row0 * N + col)       = make_float2(acc[mi][ni][0], acc[mi][ni][1]);
                *(float2*)(C + (size_t)(row0 + 8) * N + col) = make_float2(acc[mi][ni][2], acc[mi][ni][3]);
            }
        }
    }
}

// ---------------------------------------------------------------------------
// Flash attention v9: Q fragments hoisted to registers (loaded once),
// register-resident P, deferred l reduction. 128 threads, Q tile 64,
// K tile 64, 2-stage de-bunched cp.async, 2 CTAs/SM.
// ---------------------------------------------------------------------------
#define QP 136
#define KVST (2 * 64 * QP)                      // halves per stage (K+V)
#define FL9_SMEM ((64*QP + 2*KVST) * 2)         // 87040 bytes

__global__ __launch_bounds__(128, 2) void flash9(const __half* __restrict__ Q,
                                                 const __half* __restrict__ K,
                                                 const __half* __restrict__ V,
                                                 __half* __restrict__ O)
{
    extern __shared__ __half hs[];
    __half* Qs  = hs;                        // [64][136]
    __half* KV0 = Qs + 64 * QP;              // 2 stages: K[64][136] then V[64][136]

    const uint32_t sbQ  = smem_u32(Qs);
    const uint32_t sbKV = smem_u32(KV0);

    const int qi  = (int)gridDim.x - 1 - (int)blockIdx.x;   // big tiles first
    const int h   = blockIdx.y;
    const int b   = blockIdx.z;
    const int kvh = h / GROUPS;
    const int tid = threadIdx.x;
    const int wid = tid >> 5, lane = tid & 31;
    const int g   = lane >> 2, tig = lane & 3;
    const int wq  = wid * 16;                 // 0..48
    const int l7  = lane & 7;
    const int lb3 = (lane >> 3) & 1;
    const int lb4 = lane >> 4;

    const __half* Qg = Q + (size_t)(b * SEQ + qi * 64) * QDIM + h * HD;
    const __half* Kg = K + (size_t)(b * SEQ) * KVDIM + kvh * HD;
    const __half* Vg = V + (size_t)(b * SEQ) * KVDIM + kvh * HD;

    // hoisted per-thread loader offsets (iteration-invariant)
    size_t   gKV[8];
    uint32_t sKV[8];
#pragma unroll
    for (int l = 0; l < 8; l++) {
        int id = l * 128 + tid;
        int r = id >> 4, c8 = (id & 15) * 8;
        gKV[l] = (size_t)r * KVDIM + c8;
        sKV[l] = (uint32_t)(r * QP + c8) * 2;
    }

    auto load_kv_full = [&](int kb, int s) {
        const __half* Kt = Kg + (size_t)(kb * 64) * KVDIM;
        const __half* Vt = Vg + (size_t)(kb * 64) * KVDIM;
        uint32_t ks_ = sbKV + (uint32_t)s * (KVST * 2);
        uint32_t vs_ = ks_ + 64 * QP * 2;
#pragma unroll
        for (int l = 0; l < 8; l++) {
            cpasync16(ks_ + sKV[l], Kt + gKV[l]);
            cpasync16(vs_ + sKV[l], Vt + gKV[l]);
        }
        CP_COMMIT();
    };

    // load Q tile (64 x 128 halves)
#pragma unroll
    for (int l = 0; l < 8; l++) {
        int id = l * 128 + tid;
        int r = id >> 4, c8 = (id & 15) * 8;
        *(uint4*)(Qs + r * QP + c8) = *(const uint4*)(Qg + (size_t)r * QDIM + c8);
    }

    const int kmax = qi + 1;
    load_kv_full(0, 0);

    // Q fragments: hoist once (barrier needed: cross-thread STS -> LDSM)
    __syncthreads();
    uint32_t qf[8][4];
#pragma unroll
    for (int ks = 0; ks < 8; ks++) {
        uint32_t addr = sbQ + (uint32_t)((wq + l7 + lb3 * 8) * QP + ks * 16 + lb4 * 8) * 2;
        ldsm4(qf[ks][0], qf[ks][1], qf[ks][2], qf[ks][3], addr);
    }

    float m0 = -INFINITY, m1 = -INFINITY;
    float l0p = 0.f, l1p = 0.f;              // lane-local partial row sums
    float oa[16][4];
#pragma unroll
    for (int ni = 0; ni < 16; ni++)
#pragma unroll
        for (int r = 0; r < 4; r++) oa[ni][r] = 0.f;

    for (int kb = 0; kb < kmax; kb++) {
        const int s = kb & 1;
        CP_WAIT(0);
        __syncthreads();

        const uint32_t sK = sbKV + (uint32_t)s * (KVST * 2);
        const uint32_t sV = sK + 64 * QP * 2;

        const bool pf = (kb + 1 < kmax);
        const __half* Ktn = Kg + (size_t)((kb + 1) * 64) * KVDIM;
        const __half* Vtn = Vg + (size_t)((kb + 1) * 64) * KVDIM;
        const uint32_t ksn = sbKV + (uint32_t)(s ^ 1) * (KVST * 2);
        const uint32_t vsn = ksn + 64 * QP * 2;

        // ---- S = Q K^T (warp: 16 x 64) ----
        float sa[8][4];
#pragma unroll
        for (int ni = 0; ni < 8; ni++)
#pragma unroll
            for (int r = 0; r < 4; r++) sa[ni][r] = 0.f;

#pragma unroll
        for (int ks = 0; ks < 8; ks++) {
            if (pf) {
                cpasync16(ksn + sKV[ks], Ktn + gKV[ks]);
                cpasync16(vsn + sKV[ks], Vtn + gKV[ks]);
            }
            const int kc = ks * 16;
            uint32_t bfr[8][2];
#pragma unroll
            for (int nip = 0; nip < 4; nip++) {
                uint32_t addr = sK + (uint32_t)((nip * 16 + l7 + lb4 * 8) * QP + kc + lb3 * 8) * 2;
                ldsm4(bfr[nip*2][0], bfr[nip*2][1], bfr[nip*2+1][0], bfr[nip*2+1][1], addr);
            }
#pragma unroll
            for (int ni = 0; ni < 8; ni++)
                mma_f16(sa[ni], qf[ks], bfr[ni][0], bfr[ni][1]);
        }
        if (pf) CP_COMMIT();

        // ---- causal mask (diagonal tile only: kb == qi) ----
        if (kb == qi) {
            int r0 = qi * 64 + wq + g;
#pragma unroll
            for (int ni = 0; ni < 8; ni++) {
                int c0 = kb * 64 + ni * 8 + 2 * tig;
                if (c0 > r0)         sa[ni][0] = -INFINITY;
                if (c0 + 1 > r0)     sa[ni][1] = -INFINITY;
                if (c0 > r0 + 8)     sa[ni][2] = -INFINITY;
                if (c0 + 1 > r0 + 8) sa[ni][3] = -INFINITY;
            }
        }

        // ---- online softmax (max reduce only; l kept lane-local) ----
        float mx0 = -INFINITY, mx1 = -INFINITY;
#pragma unroll
        for (int ni = 0; ni < 8; ni++) {
            mx0 = fmaxf(mx0, fmaxf(sa[ni][0], sa[ni][1]));
            mx1 = fmaxf(mx1, fmaxf(sa[ni][2], sa[ni][3]));
        }
        mx0 = fmaxf(mx0, __shfl_xor_sync(0xffffffffu, mx0, 1));
        mx0 = fmaxf(mx0, __shfl_xor_sync(0xffffffffu, mx0, 2));
        mx1 = fmaxf(mx1, __shfl_xor_sync(0xffffffffu, mx1, 1));
        mx1 = fmaxf(mx1, __shfl_xor_sync(0xffffffffu, mx1, 2));

        float mm0 = fmaxf(m0, mx0), mm1 = fmaxf(m1, mx1);
        float sub0 = (mm0 == -INFINITY) ? 0.f : mm0;
        float sub1 = (mm1 == -INFINITY) ? 0.f : mm1;
        float al0 = exp2f(m0 - sub0);
        float al1 = exp2f(m1 - sub1);
        m0 = mm0; m1 = mm1;

        uint32_t ph[8][2];
        float ls0 = 0.f, ls1 = 0.f;
#pragma unroll
        for (int ni = 0; ni < 8; ni++) {
            float p0 = exp2f(sa[ni][0] - sub0);
            float p1 = exp2f(sa[ni][1] - sub0);
            float p2 = exp2f(sa[ni][2] - sub1);
            float p3 = exp2f(sa[ni][3] - sub1);
            ls0 += p0 + p1; ls1 += p2 + p3;
            ph[ni][0] = pack_h2(p0, p1);
            ph[ni][1] = pack_h2(p2, p3);
        }
        l0p = l0p * al0 + ls0;    // lane-local partial; quad-reduced at end
        l1p = l1p * al1 + ls1;

#pragma unroll
        for (int ni = 0; ni < 16; ni++) {
            oa[ni][0] *= al0; oa[ni][1] *= al0;
            oa[ni][2] *= al1; oa[ni][3] *= al1;
        }

        // ---- O += P @ V  (A = register P; B = V via ldmatrix.trans) ----
#pragma unroll
        for (int ks = 0; ks < 4; ks++) {
            const int kc = ks * 16;
            uint32_t a[4];
            a[0] = ph[2 * ks][0];
            a[1] = ph[2 * ks][1];
            a[2] = ph[2 * ks + 1][0];
            a[3] = ph[2 * ks + 1][1];
#pragma unroll
            for (int nip = 0; nip < 8; nip++) {
                uint32_t bf0, bf1, bf2, bf3;
                uint32_t addr = sV + (uint32_t)((kc + l7 + lb3 * 8) * QP + nip * 16 + lb4 * 8) * 2;
                ldsm4t(bf0, bf1, bf2, bf3, addr);
                mma_f16(oa[nip*2],     a, bf0, bf1);
                mma_f16(oa[nip*2 + 1], a, bf2, bf3);
            }
        }
    }

    // ---- final l reduction across the quad, then epilogue ----
    float l0 = l0p, l1 = l1p;
    l0 += __shfl_xor_sync(0xffffffffu, l0, 1);
    l0 += __shfl_xor_sync(0xffffffffu, l0, 2);
    l1 += __shfl_xor_sync(0xffffffffu, l1, 1);
    l1 += __shfl_xor_sync(0xffffffffu, l1, 2);

    float inv0 = 1.0f / l0, inv1 = 1.0f / l1;
    __half* Og = O + (size_t)(b * SEQ + qi * 64 + wq) * QDIM + h * HD;
#pragma unroll
    for (int ni = 0; ni < 16; ni++) {
        int col = ni * 8 + 2 * tig;
        *(__half2*)(Og + (size_t)g * QDIM + col) =
            __floats2half2_rn(oa[ni][0] * inv0, oa[ni][1] * inv0);
        *(__half2*)(Og + (size_t)(g + 8) * QDIM + col) =
            __floats2half2_rn(oa[ni][2] * inv1, oa[ni][3] * inv1);
    }
}

// ---------------------------------------------------------------------------
// Launch: rope_table + conv_all -> grouped QKV gemm -> flash -> O gemm
// ---------------------------------------------------------------------------
extern "C" void kernel_launch(void* const* d_in, const int* in_sizes, int n_in,
                              void* d_out, int out_size)
{
    const float* query = (const float*)d_in[0];
    const float* key   = (const float*)d_in[1];
    const float* value = (const float*)d_in[2];
    const float* Wq = (const float*)d_in[5];
    const float* Wk = (const float*)d_in[6];
    const float* Wv = (const float*)d_in[7];
    const float* Wo = (const float*)d_in[8];
    float* out = (float*)d_out;

    __half *pQa, *pKa, *pVa, *pQh, *pKh, *pVh, *pAOh, *pWqh, *pWkh, *pWvh, *pWoh;
    float2* pRope;
    cudaGetSymbolAddress((void**)&pQa,   g_Qa);
    cudaGetSymbolAddress((void**)&pKa,   g_Ka);
    cudaGetSymbolAddress((void**)&pVa,   g_Va);
    cudaGetSymbolAddress((void**)&pQh,   g_Qh);
    cudaGetSymbolAddress((void**)&pKh,   g_Kh);
    cudaGetSymbolAddress((void**)&pVh,   g_Vh);
    cudaGetSymbolAddress((void**)&pAOh,  g_AOh);
    cudaGetSymbolAddress((void**)&pWqh,  g_Wqh);
    cudaGetSymbolAddress((void**)&pWkh,  g_Wkh);
    cudaGetSymbolAddress((void**)&pWvh,  g_Wvh);
    cudaGetSymbolAddress((void**)&pWoh,  g_Woh);
    cudaGetSymbolAddress((void**)&pRope, g_rope);

    cudaFuncSetAttribute(gemm_grp, cudaFuncAttributeMaxDynamicSharedMemorySize, GN_SMEM);
    cudaFuncSetAttribute(flash9,   cudaFuncAttributeMaxDynamicSharedMemorySize, FL9_SMEM);

    // rope table (tiny) + one-shot conversion of everything to half
    rope_table<<<(SEQ * 64) / 256, 256>>>(pRope);

    ConvDesc cd;
    cd.src[0] = query; cd.dst[0] = pQa;  cd.nblk[0] = (MROWS * EMB) / 2048;
    cd.src[1] = key;   cd.dst[1] = pKa;  cd.nblk[1] = (MROWS * EMB) / 2048;
    cd.src[2] = value; cd.dst[2] = pVa;  cd.nblk[2] = (MROWS * EMB) / 2048;
    cd.src[3] = Wq;    cd.dst[3] = pWqh; cd.nblk[3] = (EMB * QDIM) / 2048;
    cd.src[4] = Wk;    cd.dst[4] = pWkh; cd.nblk[4] = (EMB * KVDIM) / 2048;
    cd.src[5] = Wv;    cd.dst[5] = pWvh; cd.nblk[5] = (EMB * KVDIM) / 2048;
    cd.src[6] = Wo;    cd.dst[6] = pWoh; cd.nblk[6] = (QDIM * EMB) / 2048;
    int total_blk = cd.nblk[0] + cd.nblk[1] + cd.nblk[2] + cd.nblk[3]
                  + cd.nblk[4] + cd.nblk[5] + cd.nblk[6];
    conv_all<<<total_blk, 256>>>(cd);

    // grouped Q+K+V projections (one launch; rope fused for Q,K)
    GroupArgs gq;
    gq.A[0] = pQa; gq.B[0] = pWqh; gq.C[0] = pQh; gq.N[0] = QDIM;  gq.mode[0] = 2; gq.rsc[0] = QSCALE; gq.xend[0] = 32;
    gq.A[1] = pKa; gq.B[1] = pWkh; gq.C[1] = pKh; gq.N[1] = KVDIM; gq.mode[1] = 2; gq.rsc[1] = 1.0f;   gq.xend[1] = 40;
    gq.A[2] = pVa; gq.B[2] = pWvh; gq.C[2] = pVh; gq.N[2] = KVDIM; gq.mode[2] = 1; gq.rsc[2] = 0.0f;   gq.xend[2] = 48;
    gq.nseg = 3;
    gemm_grp<<<dim3(48, MROWS / 128), 256, GN_SMEM>>>(gq, EMB);

    // attention
    flash9<<<dim3(SEQ / 64, NH, BSZ), 128, FL9_SMEM>>>(pQh, pKh, pVh, pAOh);

    // output projection
    GroupArgs go;
    go.A[0] = pAOh; go.B[0] = pWoh; go.C[0] = out; go.N[0] = EMB; go.mode[0] = 0; go.rsc[0] = 0.0f; go.xend[0] = 32;
    go.nseg = 1;
    gemm_grp<<<dim3(32, MROWS / 128), 256, GN_SMEM>>>(go, QDIM);
}

// round 17
// speedup vs baseline: 1.1283x; 1.0013x over previous
#include <cuda_runtime.h>
#include <cuda_fp16.h>
#include <math.h>
#include <stdint.h>

#define BSZ   2
#define SEQ   2048
#define EMB   4096
#define NH    32
#define NKVH  8
#define HD    128
#define GROUPS (NH / NKVH)
#define MROWS (BSZ * SEQ)          // 4096
#define QDIM  (NH * HD)            // 4096
#define KVDIM (NKVH * HD)          // 1024

// log2(e)/sqrt(128), folded into Q so softmax uses bare exp2
#define QSCALE 0.12751744f

// Scratch (device globals)
__device__ __half g_Qa [(size_t)MROWS * EMB];    // half activations
__device__ __half g_Ka [(size_t)MROWS * EMB];
__device__ __half g_Va [(size_t)MROWS * EMB];
__device__ __half g_Qh [(size_t)MROWS * QDIM];   // post-rope half
__device__ __half g_Kh [(size_t)MROWS * KVDIM];
__device__ __half g_Vh [(size_t)MROWS * KVDIM];
__device__ __half g_AOh[(size_t)MROWS * QDIM];
__device__ __half g_Wqh[(size_t)EMB * QDIM];     // [K][N] half (no transpose)
__device__ __half g_Wkh[(size_t)EMB * KVDIM];
__device__ __half g_Wvh[(size_t)EMB * KVDIM];
__device__ __half g_Woh[(size_t)QDIM * EMB];
__device__ float2 g_rope[(size_t)SEQ * 64];      // (cos, sin) per (pos, d)

// ---------------------------------------------------------------------------
// Helpers
// ---------------------------------------------------------------------------
__device__ __forceinline__ uint32_t smem_u32(const void* p) {
    uint32_t a;
    asm("{ .reg .u64 t; cvta.to.shared.u64 t, %1; cvt.u32.u64 %0, t; }" : "=r"(a) : "l"(p));
    return a;
}
__device__ __forceinline__ void cpasync16(uint32_t dst, const void* src) {
    asm volatile("cp.async.cg.shared.global [%0], [%1], 16;" :: "r"(dst), "l"(src) : "memory");
}
#define CP_COMMIT() asm volatile("cp.async.commit_group;" ::: "memory")
#define CP_WAIT(n)  asm volatile("cp.async.wait_group %0;" :: "n"(n) : "memory")

__device__ __forceinline__ void mma_f16(float* d, const uint32_t* a, uint32_t b0, uint32_t b1) {
    asm volatile("mma.sync.aligned.m16n8k16.row.col.f32.f16.f16.f32 "
        "{%0,%1,%2,%3}, {%4,%5,%6,%7}, {%8,%9}, {%0,%1,%2,%3};"
        : "+f"(d[0]), "+f"(d[1]), "+f"(d[2]), "+f"(d[3])
        : "r"(a[0]), "r"(a[1]), "r"(a[2]), "r"(a[3]), "r"(b0), "r"(b1));
}
__device__ __forceinline__ void ldsm4(uint32_t& r0, uint32_t& r1, uint32_t& r2, uint32_t& r3,
                                      uint32_t addr) {
    asm volatile("ldmatrix.sync.aligned.m8n8.x4.shared.b16 {%0,%1,%2,%3}, [%4];"
        : "=r"(r0), "=r"(r1), "=r"(r2), "=r"(r3) : "r"(addr));
}
__device__ __forceinline__ void ldsm4t(uint32_t& r0, uint32_t& r1, uint32_t& r2, uint32_t& r3,
                                       uint32_t addr) {
    asm volatile("ldmatrix.sync.aligned.m8n8.x4.trans.shared.b16 {%0,%1,%2,%3}, [%4];"
        : "=r"(r0), "=r"(r1), "=r"(r2), "=r"(r3) : "r"(addr));
}
__device__ __forceinline__ uint32_t pack_h2(float a, float b) {
    __half2 h = __floats2half2_rn(a, b);
    return *(uint32_t*)&h;
}

// ---------------------------------------------------------------------------
// RoPE cos/sin table: bit-identical math to the in-epilogue computation.
// ---------------------------------------------------------------------------
__global__ void rope_table(float2* __restrict__ T)
{
    int i = blockIdx.x * 256 + threadIdx.x;      // SEQ*64 threads
    int pos = i >> 6, d = i & 63;
    const float LG = 0.2076205059304640f;        // 2*log2(10000)/128
    float invf = exp2f(-LG * (float)d);
    float ang = (float)pos * invf;
    float sn, cs;
    sincosf(ang, &sn, &cs);
    T[i] = make_float2(cs, sn);
}

// ---------------------------------------------------------------------------
// One-shot fp32->half conversion of all 7 tensors. 2048 elems per block.
// ---------------------------------------------------------------------------
struct ConvDesc {
    const float* src[7];
    __half*      dst[7];
    int          nblk[7];
};

__global__ void conv_all(ConvDesc cd)
{
    int b = blockIdx.x;
    int seg = 0;
#pragma unroll
    for (int i = 0; i < 7; i++) {
        if (b >= cd.nblk[i]) { b -= cd.nblk[i]; seg = i + 1; }
        else break;
    }
    const float* src = cd.src[seg];
    __half* dst = cd.dst[seg];
    size_t i = (size_t)b * 2048 + (size_t)threadIdx.x * 4;
    float4 v0 = *(const float4*)(src + i);
    float4 v1 = *(const float4*)(src + i + 1024);
    *(__half2*)(dst + i)     = __floats2half2_rn(v0.x, v0.y);
    *(__half2*)(dst + i + 2) = __floats2half2_rn(v0.z, v0.w);
    *(__half2*)(dst + i + 1024)     = __floats2half2_rn(v1.x, v1.y);
    *(__half2*)(dst + i + 1024 + 2) = __floats2half2_rn(v1.z, v1.w);
}

// ---------------------------------------------------------------------------
// Grouped fp16 tensor-core GEMM. CTA 128x128, BK=64, 8 warps, 3-stage
// cp.async (de-bunched, hoisted offsets), frag double-buffer, 2 CTAs/SM.
// mode: 0 = fp32 out, 1 = half out, 2 = rope(+scale, table) half out.
// ---------------------------------------------------------------------------
#define HP  72
#define BPN 136
#define SPN 132
#define A_ST (128 * HP)
#define B_ST (64 * BPN)
#define STG_B ((A_ST + B_ST) * 2)
#define GN_SMEM (3 * STG_B)

struct GroupArgs {
    const __half* A[3];
    const __half* B[3];
    void*         C[3];
    int           N[3];
    int           mode[3];
    float         rsc[3];
    int           xend[3];
    int           nseg;
};

__global__ __launch_bounds__(256, 2) void gemm_grp(GroupArgs ga, int K)
{
    extern __shared__ __half smh[];
    const uint32_t sb = smem_u32(smh);

    int bx = blockIdx.x;
    int seg = 0;
#pragma unroll
    for (int i = 0; i < 2; i++)
        if (i + 1 < ga.nseg && bx >= ga.xend[i]) seg = i + 1;
    const int xbase = (seg == 0) ? 0 : ga.xend[seg - 1];
    const __half* A = ga.A[seg];
    const __half* B = ga.B[seg];
    void* Cv        = ga.C[seg];
    const int N     = ga.N[seg];
    const int mode  = ga.mode[seg];
    const float rsc = ga.rsc[seg];

    const int tid  = threadIdx.x;
    const int wid  = tid >> 5, lane = tid & 31;
    const int g    = lane >> 2, tig = lane & 3;
    const int wm   = (wid >> 2) * 64;
    const int wn   = (wid & 3) * 32;
    const int bm   = blockIdx.y * 128, bn = (bx - xbase) * 128;

    size_t   gA[4], gB[4];
    uint32_t sAo[4], sBo[4];
#pragma unroll
    for (int ks = 0; ks < 4; ks++) {
        int id = ks * 256 + tid;
        int ra = id >> 3, ca = (id & 7) * 8;
        int rb = id >> 4, cb = (id & 15) * 8;
        gA[ks]  = (size_t)ra * K + ca;
        gB[ks]  = (size_t)rb * N + cb;
        sAo[ks] = (uint32_t)(ra * HP + ca) * 2;
        sBo[ks] = (uint32_t)(rb * BPN + cb) * 2;
    }

    auto load_tile = [&](int c, int s) {
        const __half* Ab = A + (size_t)bm * K + c * 64;
        const __half* Bb = B + (size_t)(c * 64) * N + bn;
        uint32_t sa  = sb + (uint32_t)s * STG_B;
        uint32_t sbb = sa + A_ST * 2;
#pragma unroll
        for (int l = 0; l < 4; l++) {
            cpasync16(sa  + sAo[l], Ab + gA[l]);
            cpasync16(sbb + sBo[l], Bb + gB[l]);
        }
        CP_COMMIT();
    };

    const int l7  = lane & 7;
    const int lb3 = (lane >> 3) & 1;
    const int lb4 = lane >> 4;

    float acc[4][4][4];
#pragma unroll
    for (int mi = 0; mi < 4; mi++)
#pragma unroll
        for (int ni = 0; ni < 4; ni++)
#pragma unroll
            for (int r = 0; r < 4; r++) acc[mi][ni][r] = 0.0f;

    const int iters = K / 64;
    load_tile(0, 0);
    load_tile(1, 1);

    uint32_t sA = 0, sBb = 0;
    uint32_t af[2][4][4], bf[2][2][4];

    auto load_frag = [&](int ks, int pb) {
        const int kb = ks * 16;
#pragma unroll
        for (int mi = 0; mi < 4; mi++) {
            uint32_t addr = sA + (uint32_t)((wm + mi * 16 + l7 + lb3 * 8) * HP
                                            + kb + lb4 * 8) * 2;
            ldsm4(af[pb][mi][0], af[pb][mi][1], af[pb][mi][2], af[pb][mi][3], addr);
        }
#pragma unroll
        for (int nj = 0; nj < 2; nj++) {
            uint32_t addr = sBb + (uint32_t)((kb + l7 + lb3 * 8) * BPN
                                             + wn + nj * 16 + lb4 * 8) * 2;
            ldsm4t(bf[pb][nj][0], bf[pb][nj][1], bf[pb][nj][2], bf[pb][nj][3], addr);
        }
    };

    for (int c = 0; c < iters; c++) {
        const int s = c % 3;
        if (c + 1 < iters) { CP_WAIT(1); } else { CP_WAIT(0); }
        __syncthreads();

        sA  = sb + (uint32_t)s * STG_B;
        sBb = sA + A_ST * 2;

        const bool pf = (c + 2 < iters);
        const __half* Abn = nullptr;
        const __half* Bbn = nullptr;
        uint32_t san = 0, sbn = 0;
        if (pf) {
            const int cn = c + 2, sn = cn % 3;
            Abn = A + (size_t)bm * K + cn * 64;
            Bbn = B + (size_t)(cn * 64) * N + bn;
            san = sb + (uint32_t)sn * STG_B;
            sbn = san + A_ST * 2;
        }

        load_frag(0, 0);
#pragma unroll
        for (int ks = 0; ks < 4; ks++) {
            if (pf) {
                cpasync16(san + sAo[ks], Abn + gA[ks]);
                cpasync16(sbn + sBo[ks], Bbn + gB[ks]);
            }
            const int cur = ks & 1;
            if (ks < 3) load_frag(ks + 1, cur ^ 1);
#pragma unroll
            for (int mi = 0; mi < 4; mi++)
#pragma unroll
                for (int nj = 0; nj < 2; nj++) {
                    mma_f16(acc[mi][nj * 2],     af[cur][mi], bf[cur][nj][0], bf[cur][nj][1]);
                    mma_f16(acc[mi][nj * 2 + 1], af[cur][mi], bf[cur][nj][2], bf[cur][nj][3]);
                }
        }
        if (pf) CP_COMMIT();
    }

    if (mode == 2) {
        __syncthreads();
        float* S = (float*)smh;
#pragma unroll
        for (int mi = 0; mi < 4; mi++) {
            int r0 = wm + mi * 16 + g;
#pragma unroll
            for (int ni = 0; ni < 4; ni++) {
                int cc = wn + ni * 8 + tig * 2;
                *(float2*)(S + (size_t)r0 * SPN + cc)       = make_float2(acc[mi][ni][0], acc[mi][ni][1]);
                *(float2*)(S + (size_t)(r0 + 8) * SPN + cc) = make_float2(acc[mi][ni][2], acc[mi][ni][3]);
            }
        }
        __syncthreads();
        // vectorized rope epilogue: 2 d-pairs per step
        __half* C = (__half*)Cv;
#pragma unroll 4
        for (int l = 0; l < 16; l++) {
            int idx = l * 256 + tid;             // 4096 double-pairs
            int r  = idx >> 5;
            int d0 = (idx & 31) * 2;
            float2 x1 = *(float2*)(S + (size_t)r * SPN + d0);
            float2 x2 = *(float2*)(S + (size_t)r * SPN + d0 + 64);
            int grow = bm + r;
            float4 t = *(float4*)(&g_rope[(size_t)(grow & (SEQ - 1)) * 64 + d0]);
            // t = (cos0, sin0, cos1, sin1)
            float o0a = (x1.x * t.x - x2.x * t.y) * rsc;
            float o0b = (x1.y * t.z - x2.y * t.w) * rsc;
            float o1a = (x2.x * t.x + x1.x * t.y) * rsc;
            float o1b = (x2.y * t.z + x1.y * t.w) * rsc;
            size_t o = (size_t)grow * N + bn + d0;
            *(__half2*)(C + o)      = __floats2half2_rn(o0a, o0b);
            *(__half2*)(C + o + 64) = __floats2half2_rn(o1a, o1b);
        }
    } else if (mode == 1) {
        __half* C = (__half*)Cv;
#pragma unroll
        for (int mi = 0; mi < 4; mi++) {
            int row0 = bm + wm + mi * 16 + g;
#pragma unroll
            for (int ni = 0; ni < 4; ni++) {
                int col = bn + wn + ni * 8 + tig * 2;
                *(__half2*)(C + (size_t)row0 * N + col) =
                    __floats2half2_rn(acc[mi][ni][0], acc[mi][ni][1]);
                *(__half2*)(C + (size_t)(row0 + 8) * N + col) =
                    __floats2half2_rn(acc[mi][ni][2], acc[mi][ni][3]);
            }
        }
    } else {
        float* C = (float*)Cv;
#pragma unroll
        for (int mi = 0; mi < 4; mi++) {
            int row0 = bm + wm + mi * 16 + g;
#pragma unroll
            for (int ni = 0; ni < 4; ni++) {
                int col = bn + wn + ni * 8 + tig * 2;
                *(float2*)(C + (size_t)row0 * N + col)       = make_float2(acc[mi][ni][0], acc[mi][ni][1]);
                *(float2*)(C + (size_t)(row0 + 8) * N + col) = make_float2(acc[mi][ni][2], acc[mi][ni][3]);
            }
        }
    }
}

// ---------------------------------------------------------------------------
// Flash attention v10: hoisted Q fragments, register-resident P, deferred l,
// dead -INF guards removed (key 0 always valid => m finite from kb=0).
// 128 threads, Q tile 64, K tile 64, 2-stage de-bunched cp.async, 2 CTAs/SM.
// ---------------------------------------------------------------------------
#define QP 136
#define KVST (2 * 64 * QP)                      // halves per stage (K+V)
#define FL10_SMEM ((64*QP + 2*KVST) * 2)        // 87040 bytes

__global__ __launch_bounds__(128, 2) void flash10(const __half* __restrict__ Q,
                                                  const __half* __restrict__ K,
                                                  const __half* __restrict__ V,
                                                  __half* __restrict__ O)
{
    extern __shared__ __half hs[];
    __half* Qs  = hs;                        // [64][136]
    __half* KV0 = Qs + 64 * QP;              // 2 stages: K[64][136] then V[64][136]

    const uint32_t sbQ  = smem_u32(Qs);
    const uint32_t sbKV = smem_u32(KV0);

    const int qi  = (int)gridDim.x - 1 - (int)blockIdx.x;   // big tiles first
    const int h   = blockIdx.y;
    const int b   = blockIdx.z;
    const int kvh = h / GROUPS;
    const int tid = threadIdx.x;
    const int wid = tid >> 5, lane = tid & 31;
    const int g   = lane >> 2, tig = lane & 3;
    const int wq  = wid * 16;                 // 0..48
    const int l7  = lane & 7;
    const int lb3 = (lane >> 3) & 1;
    const int lb4 = lane >> 4;

    const __half* Qg = Q + (size_t)(b * SEQ + qi * 64) * QDIM + h * HD;
    const __half* Kg = K + (size_t)(b * SEQ) * KVDIM + kvh * HD;
    const __half* Vg = V + (size_t)(b * SEQ) * KVDIM + kvh * HD;

    size_t   gKV[8];
    uint32_t sKV[8];
#pragma unroll
    for (int l = 0; l < 8; l++) {
        int id = l * 128 + tid;
        int r = id >> 4, c8 = (id & 15) * 8;
        gKV[l] = (size_t)r * KVDIM + c8;
        sKV[l] = (uint32_t)(r * QP + c8) * 2;
    }

    auto load_kv_full = [&](int kb, int s) {
        const __half* Kt = Kg + (size_t)(kb * 64) * KVDIM;
        const __half* Vt = Vg + (size_t)(kb * 64) * KVDIM;
        uint32_t ks_ = sbKV + (uint32_t)s * (KVST * 2);
        uint32_t vs_ = ks_ + 64 * QP * 2;
#pragma unroll
        for (int l = 0; l < 8; l++) {
            cpasync16(ks_ + sKV[l], Kt + gKV[l]);
            cpasync16(vs_ + sKV[l], Vt + gKV[l]);
        }
        CP_COMMIT();
    };

    // load Q tile (64 x 128 halves)
#pragma unroll
    for (int l = 0; l < 8; l++) {
        int id = l * 128 + tid;
        int r = id >> 4, c8 = (id & 15) * 8;
        *(uint4*)(Qs + r * QP + c8) = *(const uint4*)(Qg + (size_t)r * QDIM + c8);
    }

    const int kmax = qi + 1;
    load_kv_full(0, 0);

    // Q fragments hoisted once (barrier: cross-thread STS -> LDSM)
    __syncthreads();
    uint32_t qf[8][4];
#pragma unroll
    for (int ks = 0; ks < 8; ks++) {
        uint32_t addr = sbQ + (uint32_t)((wq + l7 + lb3 * 8) * QP + ks * 16 + lb4 * 8) * 2;
        ldsm4(qf[ks][0], qf[ks][1], qf[ks][2], qf[ks][3], addr);
    }

    float m0 = -INFINITY, m1 = -INFINITY;
    float l0p = 0.f, l1p = 0.f;
    float oa[16][4];
#pragma unroll
    for (int ni = 0; ni < 16; ni++)
#pragma unroll
        for (int r = 0; r < 4; r++) oa[ni][r] = 0.f;

    for (int kb = 0; kb < kmax; kb++) {
        const int s = kb & 1;
        CP_WAIT(0);
        __syncthreads();

        const uint32_t sK = sbKV + (uint32_t)s * (KVST * 2);
        const uint32_t sV = sK + 64 * QP * 2;

        const bool pf = (kb + 1 < kmax);
        const __half* Ktn = Kg + (size_t)((kb + 1) * 64) * KVDIM;
        const __half* Vtn = Vg + (size_t)((kb + 1) * 64) * KVDIM;
        const uint32_t ksn = sbKV + (uint32_t)(s ^ 1) * (KVST * 2);
        const uint32_t vsn = ksn + 64 * QP * 2;

        // ---- S = Q K^T ----
        float sa[8][4];
#pragma unroll
        for (int ni = 0; ni < 8; ni++)
#pragma unroll
            for (int r = 0; r < 4; r++) sa[ni][r] = 0.f;

#pragma unroll
        for (int ks = 0; ks < 8; ks++) {
            if (pf) {
                cpasync16(ksn + sKV[ks], Ktn + gKV[ks]);
                cpasync16(vsn + sKV[ks], Vtn + gKV[ks]);
            }
            const int kc = ks * 16;
            uint32_t bfr[8][2];
#pragma unroll
            for (int nip = 0; nip < 4; nip++) {
                uint32_t addr = sK + (uint32_t)((nip * 16 + l7 + lb4 * 8) * QP + kc + lb3 * 8) * 2;
                ldsm4(bfr[nip*2][0], bfr[nip*2][1], bfr[nip*2+1][0], bfr[nip*2+1][1], addr);
            }
#pragma unroll
            for (int ni = 0; ni < 8; ni++)
                mma_f16(sa[ni], qf[ks], bfr[ni][0], bfr[ni][1]);
        }
        if (pf) CP_COMMIT();

        // ---- causal mask (diagonal tile only) ----
        if (kb == qi) {
            int r0 = qi * 64 + wq + g;
#pragma unroll
            for (int ni = 0; ni < 8; ni++) {
                int c0 = kb * 64 + ni * 8 + 2 * tig;
                if (c0 > r0)         sa[ni][0] = -INFINITY;
                if (c0 + 1 > r0)     sa[ni][1] = -INFINITY;
                if (c0 > r0 + 8)     sa[ni][2] = -INFINITY;
                if (c0 + 1 > r0 + 8) sa[ni][3] = -INFINITY;
            }
        }

        // ---- online softmax (m always finite after reduce: key 0 valid) ----
        float mx0 = -INFINITY, mx1 = -INFINITY;
#pragma unroll
        for (int ni = 0; ni < 8; ni++) {
            mx0 = fmaxf(mx0, fmaxf(sa[ni][0], sa[ni][1]));
            mx1 = fmaxf(mx1, fmaxf(sa[ni][2], sa[ni][3]));
        }
        mx0 = fmaxf(mx0, __shfl_xor_sync(0xffffffffu, mx0, 1));
        mx0 = fmaxf(mx0, __shfl_xor_sync(0xffffffffu, mx0, 2));
        mx1 = fmaxf(mx1, __shfl_xor_sync(0xffffffffu, mx1, 1));
        mx1 = fmaxf(mx1, __shfl_xor_sync(0xffffffffu, mx1, 2));

        float mm0 = fmaxf(m0, mx0), mm1 = fmaxf(m1, mx1);
        float al0 = exp2f(m0 - mm0);
        float al1 = exp2f(m1 - mm1);
        m0 = mm0; m1 = mm1;

        uint32_t ph[8][2];
        float ls0 = 0.f, ls1 = 0.f;
#pragma unroll
        for (int ni = 0; ni < 8; ni++) {
            float p0 = exp2f(sa[ni][0] - mm0);
            float p1 = exp2f(sa[ni][1] - mm0);
            float p2 = exp2f(sa[ni][2] - mm1);
            float p3 = exp2f(sa[ni][3] - mm1);
            ls0 += p0 + p1; ls1 += p2 + p3;
            ph[ni][0] = pack_h2(p0, p1);
            ph[ni][1] = pack_h2(p2, p3);
        }
        l0p = l0p * al0 + ls0;
        l1p = l1p * al1 + ls1;

#pragma unroll
        for (int ni = 0; ni < 16; ni++) {
            oa[ni][0] *= al0; oa[ni][1] *= al0;
            oa[ni][2] *= al1; oa[ni][3] *= al1;
        }

        // ---- O += P @ V ----
#pragma unroll
        for (int ks = 0; ks < 4; ks++) {
            const int kc = ks * 16;
            uint32_t a[4];
            a[0] = ph[2 * ks][0];
            a[1] = ph[2 * ks][1];
            a[2] = ph[2 * ks + 1][0];
            a[3] = ph[2 * ks + 1][1];
#pragma unroll
            for (int nip = 0; nip < 8; nip++) {
                uint32_t bf0, bf1, bf2, bf3;
                uint32_t addr = sV + (uint32_t)((kc + l7 + lb3 * 8) * QP + nip * 16 + lb4 * 8) * 2;
                ldsm4t(bf0, bf1, bf2, bf3, addr);
                mma_f16(oa[nip*2],     a, bf0, bf1);
                mma_f16(oa[nip*2 + 1], a, bf2, bf3);
            }
        }
    }

    // ---- final l reduction, epilogue ----
    float l0 = l0p, l1 = l1p;
    l0 += __shfl_xor_sync(0xffffffffu, l0, 1);
    l0 += __shfl_xor_sync(0xffffffffu, l0, 2);
    l1 += __shfl_xor_sync(0xffffffffu, l1, 1);
    l1 += __shfl_xor_sync(0xffffffffu, l1, 2);

    float inv0 = 1.0f / l0, inv1 = 1.0f / l1;
    __half* Og = O + (size_t)(b * SEQ + qi * 64 + wq) * QDIM + h * HD;
#pragma unroll
    for (int ni = 0; ni < 16; ni++) {
        int col = ni * 8 + 2 * tig;
        *(__half2*)(Og + (size_t)g * QDIM + col) =
            __floats2half2_rn(oa[ni][0] * inv0, oa[ni][1] * inv0);
        *(__half2*)(Og + (size_t)(g + 8) * QDIM + col) =
            __floats2half2_rn(oa[ni][2] * inv1, oa[ni][3] * inv1);
    }
}

// ---------------------------------------------------------------------------
// Launch: rope_table + conv_all -> grouped QKV gemm -> flash -> O gemm
// ---------------------------------------------------------------------------
extern "C" void kernel_launch(void* const* d_in, const int* in_sizes, int n_in,
                              void* d_out, int out_size)
{
    const float* query = (const float*)d_in[0];
    const float* key   = (const float*)d_in[1];
    const float* value = (const float*)d_in[2];
    const float* Wq = (const float*)d_in[5];
    const float* Wk = (const float*)d_in[6];
    const float* Wv = (const float*)d_in[7];
    const float* Wo = (const float*)d_in[8];
    float* out = (float*)d_out;

    __half *pQa, *pKa, *pVa, *pQh, *pKh, *pVh, *pAOh, *pWqh, *pWkh, *pWvh, *pWoh;
    float2* pRope;
    cudaGetSymbolAddress((void**)&pQa,   g_Qa);
    cudaGetSymbolAddress((void**)&pKa,   g_Ka);
    cudaGetSymbolAddress((void**)&pVa,   g_Va);
    cudaGetSymbolAddress((void**)&pQh,   g_Qh);
    cudaGetSymbolAddress((void**)&pKh,   g_Kh);
    cudaGetSymbolAddress((void**)&pVh,   g_Vh);
    cudaGetSymbolAddress((void**)&pAOh,  g_AOh);
    cudaGetSymbolAddress((void**)&pWqh,  g_Wqh);
    cudaGetSymbolAddress((void**)&pWkh,  g_Wkh);
    cudaGetSymbolAddress((void**)&pWvh,  g_Wvh);
    cudaGetSymbolAddress((void**)&pWoh,  g_Woh);
    cudaGetSymbolAddress((void**)&pRope, g_rope);

    cudaFuncSetAttribute(gemm_grp, cudaFuncAttributeMaxDynamicSharedMemorySize, GN_SMEM);
    cudaFuncSetAttribute(flash10,  cudaFuncAttributeMaxDynamicSharedMemorySize, FL10_SMEM);

    rope_table<<<(SEQ * 64) / 256, 256>>>(pRope);

    ConvDesc cd;
    cd.src[0] = query; cd.dst[0] = pQa;  cd.nblk[0] = (MROWS * EMB) / 2048;
    cd.src[1] = key;   cd.dst[1] = pKa;  cd.nblk[1] = (MROWS * EMB) / 2048;
    cd.src[2] = value; cd.dst[2] = pVa;  cd.nblk[2] = (MROWS * EMB) / 2048;
    cd.src[3] = Wq;    cd.dst[3] = pWqh; cd.nblk[3] = (EMB * QDIM) / 2048;
    cd.src[4] = Wk;    cd.dst[4] = pWkh; cd.nblk[4] = (EMB * KVDIM) / 2048;
    cd.src[5] = Wv;    cd.dst[5] = pWvh; cd.nblk[5] = (EMB * KVDIM) / 2048;
    cd.src[6] = Wo;    cd.dst[6] = pWoh; cd.nblk[6] = (QDIM * EMB) / 2048;
    int total_blk = cd.nblk[0] + cd.nblk[1] + cd.nblk[2] + cd.nblk[3]
                  + cd.nblk[4] + cd.nblk[5] + cd.nblk[6];
    conv_all<<<total_blk, 256>>>(cd);

    GroupArgs gq;
    gq.A[0] = pQa; gq.B[0] = pWqh; gq.C[0] = pQh; gq.N[0] = QDIM;  gq.mode[0] = 2; gq.rsc[0] = QSCALE; gq.xend[0] = 32;
    gq.A[1] = pKa; gq.B[1] = pWkh; gq.C[1] = pKh; gq.N[1] = KVDIM; gq.mode[1] = 2; gq.rsc[1] = 1.0f;   gq.xend[1] = 40;
    gq.A[2] = pVa; gq.B[2] = pWvh; gq.C[2] = pVh; gq.N[2] = KVDIM; gq.mode[2] = 1; gq.rsc[2] = 0.0f;   gq.xend[2] = 48;
    gq.nseg = 3;
    gemm_grp<<<dim3(48, MROWS / 128), 256, GN_SMEM>>>(gq, EMB);

    flash10<<<dim3(SEQ / 64, NH, BSZ), 128, FL10_SMEM>>>(pQh, pKh, pVh, pAOh);

    GroupArgs go;
    go.A[0] = pAOh; go.B[0] = pWoh; go.C[0] = out; go.N[0] = EMB; go.mode[0] = 0; go.rsc[0] = 0.0f; go.xend[0] = 32;
    go.nseg = 1;
    gemm_grp<<<dim3(32, MROWS / 128), 256, GN_SMEM>>>(go, QDIM);
}